// round 1
// baseline (speedup 1.0000x reference)
#include <cuda_runtime.h>

// ---------------------------------------------------------------------------
// FeedForwardNetwork (SO(3) equivariant FFN), sm_103a
//
// Math restructuring (exact up to fp reassociation):
//   y      = blockdiag_l(nf @ (w1[l] @ g1)) ; y[:,0,:] += b1 @ g1
//   grid1  = silu(T @ y)            per node   (T = to_grid [324 x 49])
//   grid2  = silu(grid1 @ g2)                  (the only irreducible big GEMM)
//   z      = F^T @ grid2            per node   (F = from_grid [324 x 49])
//   out[:,i>=1,:] = z[:,i,:] @ (g3 @ w2[l(i)])
//   out[:,0,:]    = silu(nf[:,0,:] @ ws + bs) @ w2[0] + b2
// ---------------------------------------------------------------------------

#define N_NODES 1024
#define NC      49          // (LMAX+1)^2
#define CIN     128
#define HID     256
#define RES     18
#define NP      (RES*RES)   // 324
#define NL      7

// -------- scratch (static device globals; no runtime allocation) -----------
__device__ float g_W1G1[NL * CIN * HID];            // 3.5 MB
__device__ float g_G3W2[NL * HID * CIN];            // 3.5 MB
__device__ float g_b1g1[HID];
__device__ float g_FT[NC * NP];                     // from_grid transposed
__device__ float g_y[(size_t)N_NODES * NC * HID];   // 51 MB
__device__ float g_grid1[(size_t)N_NODES * NP * HID]; // 340 MB
__device__ float g_grid2[(size_t)N_NODES * NP * HID]; // 340 MB
__device__ float g_z[(size_t)N_NODES * NC * HID];   // 51 MB
__device__ float g_gate[(size_t)N_NODES * HID];     // 1 MB

__device__ __forceinline__ float silu_f(float x) {
    return x / (1.0f + __expf(-x));
}

__device__ __forceinline__ int deg_of(int i) {
    int l = 0;
    while ((l + 1) * (l + 1) <= i) ++l;
    return l;
}

// ---------------------------------------------------------------------------
// Generic 64x64x16 tiled GEMM (row-major A[MxK], B[KxN] -> C[MxN]).
// 256 threads, 4x4 microtile per thread. Predicated loads (zero-fill) handle
// arbitrary M/N/K remainders. Optional bias (per output column) and SiLU.
// Tile indices come from blockIdx.x (N) / blockIdx.y (M).
// ---------------------------------------------------------------------------
template<bool DO_SILU, bool HAS_BIAS>
__device__ __forceinline__ void gemm_tile(
    const float* __restrict__ A, int lda,
    const float* __restrict__ B, int ldb,
    const float* __restrict__ bias,
    float* __restrict__ C, int ldc,
    int M, int N, int K)
{
    __shared__ float As[16][64];
    __shared__ float Bs[16][64];

    const int tid = threadIdx.x;
    const int tx  = tid & 15;   // N direction (16 threads * 4 cols)
    const int ty  = tid >> 4;   // M direction (16 threads * 4 rows)
    const int m0  = blockIdx.y * 64;
    const int n0  = blockIdx.x * 64;

    float acc[4][4];
#pragma unroll
    for (int i = 0; i < 4; i++)
#pragma unroll
        for (int j = 0; j < 4; j++) acc[i][j] = 0.0f;

    for (int k0 = 0; k0 < K; k0 += 16) {
        // Load A tile 64x16 (store transposed: As[k][m])
#pragma unroll
        for (int e = tid; e < 64 * 16; e += 256) {
            int m = e >> 4, k = e & 15;
            int gm = m0 + m, gk = k0 + k;
            As[k][m] = (gm < M && gk < K) ? A[(size_t)gm * lda + gk] : 0.0f;
        }
        // Load B tile 16x64
#pragma unroll
        for (int e = tid; e < 16 * 64; e += 256) {
            int k = e >> 6, n = e & 63;
            int gk = k0 + k, gn = n0 + n;
            Bs[k][n] = (gk < K && gn < N) ? B[(size_t)gk * ldb + gn] : 0.0f;
        }
        __syncthreads();

#pragma unroll
        for (int k = 0; k < 16; k++) {
            float4 av = *(const float4*)&As[k][ty * 4];
            float4 bv = *(const float4*)&Bs[k][tx * 4];
            float a4[4] = {av.x, av.y, av.z, av.w};
            float b4[4] = {bv.x, bv.y, bv.z, bv.w};
#pragma unroll
            for (int i = 0; i < 4; i++)
#pragma unroll
                for (int j = 0; j < 4; j++)
                    acc[i][j] += a4[i] * b4[j];
        }
        __syncthreads();
    }

#pragma unroll
    for (int i = 0; i < 4; i++) {
        int gm = m0 + ty * 4 + i;
        if (gm >= M) continue;
#pragma unroll
        for (int j = 0; j < 4; j++) {
            int gn = n0 + tx * 4 + j;
            if (gn >= N) continue;
            float v = acc[i][j];
            if (HAS_BIAS) v += bias[gn];
            if (DO_SILU)  v = silu_f(v);
            C[(size_t)gm * ldc + gn] = v;
        }
    }
}

// ---------------------------- stage kernels --------------------------------

// W1G1[l] = w1[l] (128x256) @ g1 (256x256)
__global__ void __launch_bounds__(256) k_w1g1(const float* __restrict__ w1,
                                              const float* __restrict__ g1) {
    int l = blockIdx.z;
    gemm_tile<false, false>(w1 + (size_t)l * CIN * HID, HID,
                            g1, HID, nullptr,
                            g_W1G1 + (size_t)l * CIN * HID, HID,
                            CIN, HID, HID);
}

// G3W2[l] = g3 (256x256) @ w2[l] (256x128)
__global__ void __launch_bounds__(256) k_g3w2(const float* __restrict__ g3,
                                              const float* __restrict__ w2) {
    int l = blockIdx.z;
    gemm_tile<false, false>(g3, HID,
                            w2 + (size_t)l * HID * CIN, CIN, nullptr,
                            g_G3W2 + (size_t)l * HID * CIN, CIN,
                            HID, CIN, HID);
}

// b1g1[k] = sum_h b1[h] * g1[h,k]
__global__ void k_b1g1(const float* __restrict__ b1, const float* __restrict__ g1) {
    int k = threadIdx.x;
    float s = 0.0f;
    for (int h = 0; h < HID; h++) s += b1[h] * g1[(size_t)h * HID + k];
    g_b1g1[k] = s;
}

// FT[i,p] = F[p,i]
__global__ void k_transposeF(const float* __restrict__ F) {
    int idx = blockIdx.x * blockDim.x + threadIdx.x;
    if (idx < NP * NC) {
        int p = idx / NC, i = idx % NC;
        g_FT[(size_t)i * NP + p] = F[idx];
    }
}

// gate = silu(nf[:,0,:] @ ws + bs)   [1024 x 256]
__global__ void __launch_bounds__(256) k_gate(const float* __restrict__ nf,
                                              const float* __restrict__ ws,
                                              const float* __restrict__ bs) {
    gemm_tile<true, true>(nf, NC * CIN,
                          ws, HID, bs,
                          g_gate, HID,
                          N_NODES, HID, CIN);
}

// y[:,i,:] = nf[:,i,:] @ W1G1[l(i)]  (+ b1g1 on i==0)
__global__ void __launch_bounds__(256) k_y(const float* __restrict__ nf) {
    int i = blockIdx.z;
    int l = deg_of(i);
    const float* A = nf + (size_t)i * CIN;
    const float* B = g_W1G1 + (size_t)l * CIN * HID;
    float* C = g_y + (size_t)i * HID;
    if (i == 0)
        gemm_tile<false, true>(A, NC * CIN, B, HID, g_b1g1, C, NC * HID,
                               N_NODES, HID, CIN);
    else
        gemm_tile<false, false>(A, NC * CIN, B, HID, nullptr, C, NC * HID,
                                N_NODES, HID, CIN);
}

// grid1[n] = silu(T @ y[n])   (324x49)@(49x256)
__global__ void __launch_bounds__(256) k_grid1(const float* __restrict__ T) {
    int n = blockIdx.z;
    gemm_tile<true, false>(T, NC,
                           g_y + (size_t)n * NC * HID, HID, nullptr,
                           g_grid1 + (size_t)n * NP * HID, HID,
                           NP, HID, NC);
}

// grid2 = silu(grid1 @ g2)    (331776x256)@(256x256)
__global__ void __launch_bounds__(256) k_grid2(const float* __restrict__ g2) {
    gemm_tile<true, false>(g_grid1, HID,
                           g2, HID, nullptr,
                           g_grid2, HID,
                           N_NODES * NP, HID, HID);
}

// z[n] = FT @ grid2[n]        (49x324)@(324x256)
__global__ void __launch_bounds__(256) k_z() {
    int n = blockIdx.z;
    gemm_tile<false, false>(g_FT, NP,
                            g_grid2 + (size_t)n * NP * HID, HID, nullptr,
                            g_z + (size_t)n * NC * HID, HID,
                            NC, HID, NP);
}

// out[:,i,:]:  i==0 -> gate @ w2[0] + b2 ;  i>=1 -> z[:,i,:] @ G3W2[l(i)]
__global__ void __launch_bounds__(256) k_out(const float* __restrict__ w2,
                                             const float* __restrict__ b2,
                                             float* __restrict__ out) {
    int i = blockIdx.z;
    if (i == 0) {
        gemm_tile<false, true>(g_gate, HID,
                               w2, CIN, b2,
                               out, NC * CIN,
                               N_NODES, CIN, HID);
    } else {
        int l = deg_of(i);
        gemm_tile<false, false>(g_z + (size_t)i * HID, NC * HID,
                                g_G3W2 + (size_t)l * HID * CIN, CIN, nullptr,
                                out + (size_t)i * CIN, NC * CIN,
                                N_NODES, CIN, HID);
    }
}

// ---------------------------------------------------------------------------

extern "C" void kernel_launch(void* const* d_in, const int* in_sizes, int n_in,
                              void* d_out, int out_size) {
    const float* nf = (const float*)d_in[0];   // [1024,49,128]
    const float* w1 = (const float*)d_in[1];   // [7,128,256]
    const float* b1 = (const float*)d_in[2];   // [256]
    const float* w2 = (const float*)d_in[3];   // [7,256,128]
    const float* b2 = (const float*)d_in[4];   // [128]
    const float* ws = (const float*)d_in[5];   // [128,256]
    const float* bs = (const float*)d_in[6];   // [256]
    const float* g1 = (const float*)d_in[7];   // [256,256]
    const float* g2 = (const float*)d_in[8];   // [256,256]
    const float* g3 = (const float*)d_in[9];   // [256,256]
    const float* Tg = (const float*)d_in[10];  // to_grid   [18,18,49]
    const float* Fg = (const float*)d_in[11];  // from_grid [18,18,49]
    float* out = (float*)d_out;                // [1024,49,128]

    // weight pre-folds (tiny)
    k_w1g1<<<dim3(HID / 64, CIN / 64, NL), 256>>>(w1, g1);
    k_g3w2<<<dim3(CIN / 64, HID / 64, NL), 256>>>(g3, w2);
    k_b1g1<<<1, HID>>>(b1, g1);
    k_transposeF<<<(NP * NC + 255) / 256, 256>>>(Fg);

    // scalar gating branch
    k_gate<<<dim3(HID / 64, N_NODES / 64), 256>>>(nf, ws, bs);

    // main pipeline
    k_y<<<dim3(HID / 64, N_NODES / 64, NC), 256>>>(nf);
    k_grid1<<<dim3(HID / 64, (NP + 63) / 64, N_NODES), 256>>>(Tg);
    k_grid2<<<dim3(HID / 64, (N_NODES * NP) / 64), 256>>>(g2);
    k_z<<<dim3(HID / 64, 1, N_NODES), 256>>>();
    k_out<<<dim3(CIN / 64, N_NODES / 64, NC), 256>>>(w2, b2, out);
}

// round 3
// speedup vs baseline: 1.5861x; 1.5861x over previous
#include <cuda_runtime.h>
#include <cuda_bf16.h>
#include <cstdint>

// ---------------------------------------------------------------------------
// FeedForwardNetwork (SO(3) equivariant FFN), sm_103a
//
//   y      = blockdiag_l(nf @ (w1[l] @ g1)) ; y[:,0,:] += b1 @ g1
//   grid1  = silu(T @ y)  -> bf16 split rows [M, 768] = [hi | lo | hi]
//   grid2  = silu(grid1 @ g2)  via mma.sync bf16, B^T rows [256,768]=[hi|hi|lo]
//            (hi*hi + lo*hi + hi*lo; dropped lo*lo ~ 2^-18)
//   z      = F^T @ grid2   per node
//   out[:,i>=1,:] = z[:,i,:] @ (g3 @ w2[l(i)])
//   out[:,0,:]    = silu(nf[:,0,:] @ ws + bs) @ w2[0] + b2
// ---------------------------------------------------------------------------

#define N_NODES 1024
#define NC      49
#define CIN     128
#define HID     256
#define RES     18
#define NP      (RES*RES)   // 324
#define NL      7
#define MROWS   ((size_t)N_NODES * NP)   // 331776
#define KS3     768          // 3*HID split-K
#define BM      128
#define BN      256
#define BK      32
#define NITER   (KS3 / BK)   // 24

// -------- scratch (static device globals; no runtime allocation) -----------
__device__ float g_W1G1[NL * CIN * HID];
__device__ float g_G3W2[NL * HID * CIN];
__device__ float g_b1g1[HID];
__device__ float g_FT[NC * NP];
__device__ float g_y[(size_t)N_NODES * NC * HID];
__device__ __nv_bfloat16 g_grid1b[MROWS * KS3];     // 510 MB
__device__ __nv_bfloat16 g_g2b[HID * KS3];          // B^T split
__device__ float g_grid2[MROWS * HID];              // 340 MB
__device__ float g_z[(size_t)N_NODES * NC * HID];
__device__ float g_gate[(size_t)N_NODES * HID];

__device__ __forceinline__ float silu_f(float x) {
    return x / (1.0f + __expf(-x));
}
__device__ __forceinline__ int deg_of(int i) {
    int l = 0;
    while ((l + 1) * (l + 1) <= i) ++l;
    return l;
}
__device__ __forceinline__ uint32_t smem_u32(const void* p) {
    uint32_t a;
    asm("{ .reg .u64 t; cvta.to.shared.u64 t, %1; cvt.u32.u64 %0, t; }"
        : "=r"(a) : "l"(p));
    return a;
}
__device__ __forceinline__ void cp_async16(uint32_t dst, const void* src) {
    asm volatile("cp.async.cg.shared.global [%0], [%1], 16;" :: "r"(dst), "l"(src));
}
__device__ __forceinline__ void ldsm_x4(uint32_t& r0, uint32_t& r1,
                                        uint32_t& r2, uint32_t& r3, uint32_t addr) {
    asm volatile("ldmatrix.sync.aligned.m8n8.x4.shared.b16 {%0,%1,%2,%3}, [%4];"
                 : "=r"(r0), "=r"(r1), "=r"(r2), "=r"(r3) : "r"(addr));
}
__device__ __forceinline__ void mma_bf16(float* d, const uint32_t* a, const uint32_t* b) {
    asm volatile(
        "mma.sync.aligned.m16n8k16.row.col.f32.bf16.bf16.f32 "
        "{%0,%1,%2,%3}, {%4,%5,%6,%7}, {%8,%9}, {%0,%1,%2,%3};"
        : "+f"(d[0]), "+f"(d[1]), "+f"(d[2]), "+f"(d[3])
        : "r"(a[0]), "r"(a[1]), "r"(a[2]), "r"(a[3]), "r"(b[0]), "r"(b[1]));
}

// ---------------------------------------------------------------------------
// Generic 64x64x16 SIMT tiled GEMM (small stages).
// ---------------------------------------------------------------------------
template<bool DO_SILU, bool HAS_BIAS>
__device__ __forceinline__ void gemm_tile(
    const float* __restrict__ A, int lda,
    const float* __restrict__ B, int ldb,
    const float* __restrict__ bias,
    float* __restrict__ C, int ldc,
    int M, int N, int K)
{
    __shared__ float As[16][64];
    __shared__ float Bs[16][64];

    const int tid = threadIdx.x;
    const int tx  = tid & 15;
    const int ty  = tid >> 4;
    const int m0  = blockIdx.y * 64;
    const int n0  = blockIdx.x * 64;

    float acc[4][4];
#pragma unroll
    for (int i = 0; i < 4; i++)
#pragma unroll
        for (int j = 0; j < 4; j++) acc[i][j] = 0.0f;

    for (int k0 = 0; k0 < K; k0 += 16) {
#pragma unroll
        for (int e = tid; e < 64 * 16; e += 256) {
            int m = e >> 4, k = e & 15;
            int gm = m0 + m, gk = k0 + k;
            As[k][m] = (gm < M && gk < K) ? A[(size_t)gm * lda + gk] : 0.0f;
        }
#pragma unroll
        for (int e = tid; e < 16 * 64; e += 256) {
            int k = e >> 6, n = e & 63;
            int gk = k0 + k, gn = n0 + n;
            Bs[k][n] = (gk < K && gn < N) ? B[(size_t)gk * ldb + gn] : 0.0f;
        }
        __syncthreads();

#pragma unroll
        for (int k = 0; k < 16; k++) {
            float4 av = *(const float4*)&As[k][ty * 4];
            float4 bv = *(const float4*)&Bs[k][tx * 4];
            float a4[4] = {av.x, av.y, av.z, av.w};
            float b4[4] = {bv.x, bv.y, bv.z, bv.w};
#pragma unroll
            for (int i = 0; i < 4; i++)
#pragma unroll
                for (int j = 0; j < 4; j++)
                    acc[i][j] += a4[i] * b4[j];
        }
        __syncthreads();
    }

#pragma unroll
    for (int i = 0; i < 4; i++) {
        int gm = m0 + ty * 4 + i;
        if (gm >= M) continue;
#pragma unroll
        for (int j = 0; j < 4; j++) {
            int gn = n0 + tx * 4 + j;
            if (gn >= N) continue;
            float v = acc[i][j];
            if (HAS_BIAS) v += bias[gn];
            if (DO_SILU)  v = silu_f(v);
            C[(size_t)gm * ldc + gn] = v;
        }
    }
}

// Variant: SiLU then bf16 split rows [hi | lo | hi] at stride KS3.
__device__ __forceinline__ void gemm_tile_silu_split(
    const float* __restrict__ A, int lda,
    const float* __restrict__ B, int ldb,
    __nv_bfloat16* __restrict__ C,
    int M, int N, int K)
{
    __shared__ float As[16][64];
    __shared__ float Bs[16][64];

    const int tid = threadIdx.x;
    const int tx  = tid & 15;
    const int ty  = tid >> 4;
    const int m0  = blockIdx.y * 64;
    const int n0  = blockIdx.x * 64;

    float acc[4][4];
#pragma unroll
    for (int i = 0; i < 4; i++)
#pragma unroll
        for (int j = 0; j < 4; j++) acc[i][j] = 0.0f;

    for (int k0 = 0; k0 < K; k0 += 16) {
#pragma unroll
        for (int e = tid; e < 64 * 16; e += 256) {
            int m = e >> 4, k = e & 15;
            int gm = m0 + m, gk = k0 + k;
            As[k][m] = (gm < M && gk < K) ? A[(size_t)gm * lda + gk] : 0.0f;
        }
#pragma unroll
        for (int e = tid; e < 16 * 64; e += 256) {
            int k = e >> 6, n = e & 63;
            int gk = k0 + k, gn = n0 + n;
            Bs[k][n] = (gk < K && gn < N) ? B[(size_t)gk * ldb + gn] : 0.0f;
        }
        __syncthreads();

#pragma unroll
        for (int k = 0; k < 16; k++) {
            float4 av = *(const float4*)&As[k][ty * 4];
            float4 bv = *(const float4*)&Bs[k][tx * 4];
            float a4[4] = {av.x, av.y, av.z, av.w};
            float b4[4] = {bv.x, bv.y, bv.z, bv.w};
#pragma unroll
            for (int i = 0; i < 4; i++)
#pragma unroll
                for (int j = 0; j < 4; j++)
                    acc[i][j] += a4[i] * b4[j];
        }
        __syncthreads();
    }

#pragma unroll
    for (int i = 0; i < 4; i++) {
        int gm = m0 + ty * 4 + i;
        if (gm >= M) continue;
#pragma unroll
        for (int j = 0; j < 4; j++) {
            int gn = n0 + tx * 4 + j;
            if (gn >= N) continue;
            float v = silu_f(acc[i][j]);
            __nv_bfloat16 h = __float2bfloat16(v);
            float r = v - __bfloat162float(h);
            __nv_bfloat16* row = C + (size_t)gm * KS3;
            row[gn]             = h;
            row[HID + gn]       = __float2bfloat16(r);
            row[2 * HID + gn]   = h;
        }
    }
}

// ---------------------------- stage kernels --------------------------------

__global__ void __launch_bounds__(256) k_w1g1(const float* __restrict__ w1,
                                              const float* __restrict__ g1) {
    int l = blockIdx.z;
    gemm_tile<false, false>(w1 + (size_t)l * CIN * HID, HID, g1, HID, nullptr,
                            g_W1G1 + (size_t)l * CIN * HID, HID, CIN, HID, HID);
}

__global__ void __launch_bounds__(256) k_g3w2(const float* __restrict__ g3,
                                              const float* __restrict__ w2) {
    int l = blockIdx.z;
    gemm_tile<false, false>(g3, HID, w2 + (size_t)l * HID * CIN, CIN, nullptr,
                            g_G3W2 + (size_t)l * HID * CIN, CIN, HID, CIN, HID);
}

__global__ void k_b1g1(const float* __restrict__ b1, const float* __restrict__ g1) {
    int k = threadIdx.x;
    float s = 0.0f;
    for (int h = 0; h < HID; h++) s += b1[h] * g1[(size_t)h * HID + k];
    g_b1g1[k] = s;
}

__global__ void k_transposeF(const float* __restrict__ F) {
    int idx = blockIdx.x * blockDim.x + threadIdx.x;
    if (idx < NP * NC) {
        int p = idx / NC, i = idx % NC;
        g_FT[(size_t)i * NP + p] = F[idx];
    }
}

// B^T split rows: g_g2b[n] = [hi(k) | hi(k) | lo(k)], k = 0..255
__global__ void k_prepg2(const float* __restrict__ g2) {
    int k = blockIdx.x;
    int n = threadIdx.x;
    float x = g2[(size_t)k * HID + n];
    __nv_bfloat16 h = __float2bfloat16(x);
    float r = x - __bfloat162float(h);
    __nv_bfloat16* row = g_g2b + (size_t)n * KS3;
    row[k]           = h;
    row[HID + k]     = h;
    row[2 * HID + k] = __float2bfloat16(r);
}

__global__ void __launch_bounds__(256) k_gate(const float* __restrict__ nf,
                                              const float* __restrict__ ws,
                                              const float* __restrict__ bs) {
    gemm_tile<true, true>(nf, NC * CIN, ws, HID, bs, g_gate, HID,
                          N_NODES, HID, CIN);
}

__global__ void __launch_bounds__(256) k_y(const float* __restrict__ nf) {
    int i = blockIdx.z;
    int l = deg_of(i);
    const float* A = nf + (size_t)i * CIN;
    const float* B = g_W1G1 + (size_t)l * CIN * HID;
    float* C = g_y + (size_t)i * HID;
    if (i == 0)
        gemm_tile<false, true>(A, NC * CIN, B, HID, g_b1g1, C, NC * HID,
                               N_NODES, HID, CIN);
    else
        gemm_tile<false, false>(A, NC * CIN, B, HID, nullptr, C, NC * HID,
                                N_NODES, HID, CIN);
}

__global__ void __launch_bounds__(256) k_grid1(const float* __restrict__ T) {
    int n = blockIdx.z;
    gemm_tile_silu_split(T, NC,
                         g_y + (size_t)n * NC * HID, HID,
                         g_grid1b + (size_t)n * NP * KS3,
                         NP, HID, NC);
}

// -------------------- bf16 MMA GEMM: grid2 = silu(grid1 @ g2) --------------
// A = g_grid1b [331776 x 768], B^T = g_g2b [256 x 768]. C fp32 [331776 x 256].
// BM=128, BN=256, BK=32, 8 warps (2x4), warp tile 64x64 (4x8 m16n8k16).
// Smem rows 64B, XOR swizzle on 16B chunks: c ^= (row>>1)&3 -> conflict-free
// for both cp.async stores and ldmatrix phases. Double-buffered (2x24KB).
__global__ void __launch_bounds__(256, 1) k_grid2_mma() {
    __shared__ __align__(128) char smem[2 * (BM * 64 + BN * 64)];  // 49152
    const uint32_t sbase = smem_u32(smem);
    const int tid = threadIdx.x;
    const int wid = tid >> 5;
    const int lid = tid & 31;
    const int wm  = wid & 1;        // M half (64 rows)
    const int wn  = wid >> 1;       // N quarter (64 cols)
    const size_t m0 = (size_t)blockIdx.x * BM;

    const uint32_t STAGE = BM * 64 + BN * 64;    // 24576
    const uint32_t BOFF  = BM * 64;              // 8192

    // Precompute ldmatrix addresses (stage 0); add cur*STAGE at use.
    uint32_t a_addr[4][2], b_addr[4][2];
#pragma unroll
    for (int mt = 0; mt < 4; mt++)
#pragma unroll
        for (int ks = 0; ks < 2; ks++) {
            int row = wm * 64 + mt * 16 + (lid & 7) + ((lid >> 3) & 1) * 8;
            int ch  = ks * 2 + (lid >> 4);
            a_addr[mt][ks] = sbase + row * 64 + 16 * (ch ^ ((row >> 1) & 3));
        }
#pragma unroll
    for (int np = 0; np < 4; np++)
#pragma unroll
        for (int ks = 0; ks < 2; ks++) {
            int row = wn * 64 + np * 16 + (lid & 7) + (lid >> 4) * 8;
            int ch  = ks * 2 + ((lid >> 3) & 1);
            b_addr[np][ks] = sbase + BOFF + row * 64 + 16 * (ch ^ ((row >> 1) & 3));
        }

    // Precompute cp.async smem destinations / gmem sources.
    uint32_t a_dst[2], b_dst[4];
    const __nv_bfloat16* a_src[2];
    const __nv_bfloat16* b_src[4];
#pragma unroll
    for (int i = 0; i < 2; i++) {
        int id = tid + i * 256, r = id >> 2, c = id & 3;
        a_dst[i] = sbase + r * 64 + 16 * (c ^ ((r >> 1) & 3));
        a_src[i] = g_grid1b + (m0 + r) * (size_t)KS3 + c * 8;
    }
#pragma unroll
    for (int i = 0; i < 4; i++) {
        int id = tid + i * 256, r = id >> 2, c = id & 3;
        b_dst[i] = sbase + BOFF + r * 64 + 16 * (c ^ ((r >> 1) & 3));
        b_src[i] = g_g2b + r * (size_t)KS3 + c * 8;
    }

    float acc[4][8][4];
#pragma unroll
    for (int mt = 0; mt < 4; mt++)
#pragma unroll
        for (int nt = 0; nt < 8; nt++)
#pragma unroll
            for (int v = 0; v < 4; v++) acc[mt][nt][v] = 0.0f;

    // Preload stage 0.
#pragma unroll
    for (int i = 0; i < 2; i++) cp_async16(a_dst[i], a_src[i]);
#pragma unroll
    for (int i = 0; i < 4; i++) cp_async16(b_dst[i], b_src[i]);
    asm volatile("cp.async.commit_group;");

#pragma unroll 1
    for (int kc = 0; kc < NITER; kc++) {
        const int cur = kc & 1;
        if (kc + 1 < NITER) {
            const uint32_t so = ((kc + 1) & 1) * STAGE;
            const int ko = (kc + 1) * BK;
#pragma unroll
            for (int i = 0; i < 2; i++) cp_async16(a_dst[i] + so, a_src[i] + ko);
#pragma unroll
            for (int i = 0; i < 4; i++) cp_async16(b_dst[i] + so, b_src[i] + ko);
            asm volatile("cp.async.commit_group;");
            asm volatile("cp.async.wait_group 1;");
        } else {
            asm volatile("cp.async.wait_group 0;");
        }
        __syncthreads();

        const uint32_t so = cur * STAGE;
#pragma unroll
        for (int ks = 0; ks < 2; ks++) {
            uint32_t af[4][4], bf[8][2];
#pragma unroll
            for (int mt = 0; mt < 4; mt++)
                ldsm_x4(af[mt][0], af[mt][1], af[mt][2], af[mt][3],
                        a_addr[mt][ks] + so);
#pragma unroll
            for (int np = 0; np < 4; np++)
                ldsm_x4(bf[2 * np][0], bf[2 * np][1], bf[2 * np + 1][0],
                        bf[2 * np + 1][1], b_addr[np][ks] + so);
#pragma unroll
            for (int mt = 0; mt < 4; mt++)
#pragma unroll
                for (int nt = 0; nt < 8; nt++)
                    mma_bf16(acc[mt][nt], af[mt], bf[nt]);
        }
        __syncthreads();
    }

    // Epilogue: SiLU + fp32 store.
    const int tq = lid >> 2;
    const int tr = lid & 3;
#pragma unroll
    for (int mt = 0; mt < 4; mt++) {
        size_t row0 = m0 + wm * 64 + mt * 16 + tq;
#pragma unroll
        for (int nt = 0; nt < 8; nt++) {
            int col = wn * 64 + nt * 8 + tr * 2;
            float2 v0, v1;
            v0.x = silu_f(acc[mt][nt][0]);
            v0.y = silu_f(acc[mt][nt][1]);
            v1.x = silu_f(acc[mt][nt][2]);
            v1.y = silu_f(acc[mt][nt][3]);
            *(float2*)(g_grid2 + row0 * HID + col)       = v0;
            *(float2*)(g_grid2 + (row0 + 8) * HID + col) = v1;
        }
    }
}

// z[n] = FT @ grid2[n]
__global__ void __launch_bounds__(256) k_z() {
    int n = blockIdx.z;
    gemm_tile<false, false>(g_FT, NP,
                            g_grid2 + (size_t)n * NP * HID, HID, nullptr,
                            g_z + (size_t)n * NC * HID, HID,
                            NC, HID, NP);
}

__global__ void __launch_bounds__(256) k_out(const float* __restrict__ w2,
                                             const float* __restrict__ b2,
                                             float* __restrict__ out) {
    int i = blockIdx.z;
    if (i == 0) {
        gemm_tile<false, true>(g_gate, HID, w2, CIN, b2,
                               out, NC * CIN, N_NODES, CIN, HID);
    } else {
        int l = deg_of(i);
        gemm_tile<false, false>(g_z + (size_t)i * HID, NC * HID,
                                g_G3W2 + (size_t)l * HID * CIN, CIN, nullptr,
                                out + (size_t)i * CIN, NC * CIN,
                                N_NODES, CIN, HID);
    }
}

// ---------------------------------------------------------------------------

extern "C" void kernel_launch(void* const* d_in, const int* in_sizes, int n_in,
                              void* d_out, int out_size) {
    const float* nf = (const float*)d_in[0];
    const float* w1 = (const float*)d_in[1];
    const float* b1 = (const float*)d_in[2];
    const float* w2 = (const float*)d_in[3];
    const float* b2 = (const float*)d_in[4];
    const float* ws = (const float*)d_in[5];
    const float* bs = (const float*)d_in[6];
    const float* g1 = (const float*)d_in[7];
    const float* g2 = (const float*)d_in[8];
    const float* g3 = (const float*)d_in[9];
    const float* Tg = (const float*)d_in[10];
    const float* Fg = (const float*)d_in[11];
    float* out = (float*)d_out;

    // weight pre-folds (tiny)
    k_w1g1<<<dim3(HID / 64, CIN / 64, NL), 256>>>(w1, g1);
    k_g3w2<<<dim3(CIN / 64, HID / 64, NL), 256>>>(g3, w2);
    k_b1g1<<<1, HID>>>(b1, g1);
    k_transposeF<<<(NP * NC + 255) / 256, 256>>>(Fg);
    k_prepg2<<<HID, HID>>>(g2);

    // scalar gating branch
    k_gate<<<dim3(HID / 64, N_NODES / 64), 256>>>(nf, ws, bs);

    // main pipeline
    k_y<<<dim3(HID / 64, N_NODES / 64, NC), 256>>>(nf);
    k_grid1<<<dim3(HID / 64, (NP + 63) / 64, N_NODES), 256>>>(Tg);
    k_grid2_mma<<<(int)(MROWS / BM), 256>>>();
    k_z<<<dim3(HID / 64, 1, N_NODES), 256>>>();
    k_out<<<dim3(CIN / 64, N_NODES / 64, NC), 256>>>(w2, b2, out);
}

// round 4
// speedup vs baseline: 2.3739x; 1.4967x over previous
#include <cuda_runtime.h>
#include <cuda_bf16.h>
#include <cstdint>

// ---------------------------------------------------------------------------
// FeedForwardNetwork (SO(3) equivariant FFN), sm_103a — HMMA mma.sync path
//
//   y      = blockdiag_l(nf @ (w1[l] @ g1)) ; y[:,0,:] += b1 @ g1
//            -> stored bf16 split planes [n][192][256] rows = [hi|hi|lo]
//   grid1  = silu(T @ y)  per node, bf16 MMA (A = split T [384x192]),
//            -> bf16 split rows [m][768] = [hi|lo|hi]
//   grid2  = silu(grid1 @ g2) bf16 MMA (B = split g2^T [256x768])
//            -> bf16 split per node [n][1056][256] rows = [hi(p)|hi(p)|lo(p)]
//   z      = F^T @ grid2  per node, bf16 MMA (A = split F^T [64x1056]) -> fp32
//   out[:,i>=1,:] = z[:,i,:] @ (g3 @ w2[l(i)])
//   out[:,0,:]    = silu(nf[:,0,:] @ ws + bs) @ w2[0] + b2
//
// Split-precision: x = hi + lo (bf16 each); A[hi|lo|hi] . B[hi|hi|lo]
// = hi*hi + lo*hi + hi*lo  (drops lo*lo ~ 2^-18 relative).
// ---------------------------------------------------------------------------

#define N_NODES 1024
#define NC      49
#define CIN     128
#define HID     256
#define RES     18
#define NP      (RES*RES)   // 324
#define NL      7
#define MROWS   ((size_t)N_NODES * NP)   // 331776
#define KS3     768          // grid2 split-K
#define YBK     192          // y split rows (3*64)
#define PBLK    352          // padded grid-point block for z contraction
#define ZK      (3*PBLK)     // 1056
#define BM      128
#define BN      256
#define BK      32
#define NITER2  (KS3 / BK)   // 24
#define NITER1  (YBK / BK)   // 6
#define NITERZ  (ZK / BK)    // 33

// -------- scratch (static device globals; no runtime allocation) -----------
__device__ float g_W1G1[NL * CIN * HID];
__device__ float g_G3W2[NL * HID * CIN];
__device__ float g_b1g1[HID];
__device__ __nv_bfloat16 g_Tb[384 * YBK];            // split to_grid
__device__ __nv_bfloat16 g_FTb[64 * ZK];             // split from_grid^T
__device__ __nv_bfloat16 g_g2b[HID * KS3];           // split g2^T
__device__ __nv_bfloat16 g_yb[(size_t)N_NODES * YBK * HID];   // 100 MB
__device__ __nv_bfloat16 g_grid1b[MROWS * KS3];               // 510 MB
__device__ __nv_bfloat16 g_grid2b[(size_t)N_NODES * ZK * HID];// 554 MB
__device__ float g_z[(size_t)N_NODES * NC * HID];             // 51 MB
__device__ float g_gate[(size_t)N_NODES * HID];

__device__ __forceinline__ float silu_f(float x) {
    return x / (1.0f + __expf(-x));
}
__device__ __forceinline__ int deg_of(int i) {
    int l = 0;
    while ((l + 1) * (l + 1) <= i) ++l;
    return l;
}
__device__ __forceinline__ uint32_t smem_u32(const void* p) {
    uint32_t a;
    asm("{ .reg .u64 t; cvta.to.shared.u64 t, %1; cvt.u32.u64 %0, t; }"
        : "=r"(a) : "l"(p));
    return a;
}
__device__ __forceinline__ void cp_async16(uint32_t dst, const void* src) {
    asm volatile("cp.async.cg.shared.global [%0], [%1], 16;" :: "r"(dst), "l"(src));
}
__device__ __forceinline__ void ldsm_x4(uint32_t& r0, uint32_t& r1,
                                        uint32_t& r2, uint32_t& r3, uint32_t addr) {
    asm volatile("ldmatrix.sync.aligned.m8n8.x4.shared.b16 {%0,%1,%2,%3}, [%4];"
                 : "=r"(r0), "=r"(r1), "=r"(r2), "=r"(r3) : "r"(addr));
}
__device__ __forceinline__ void ldsm_x4_t(uint32_t& r0, uint32_t& r1,
                                          uint32_t& r2, uint32_t& r3, uint32_t addr) {
    asm volatile("ldmatrix.sync.aligned.m8n8.x4.trans.shared.b16 {%0,%1,%2,%3}, [%4];"
                 : "=r"(r0), "=r"(r1), "=r"(r2), "=r"(r3) : "r"(addr));
}
__device__ __forceinline__ void mma_bf16(float* d, const uint32_t* a, const uint32_t* b) {
    asm volatile(
        "mma.sync.aligned.m16n8k16.row.col.f32.bf16.bf16.f32 "
        "{%0,%1,%2,%3}, {%4,%5,%6,%7}, {%8,%9}, {%0,%1,%2,%3};"
        : "+f"(d[0]), "+f"(d[1]), "+f"(d[2]), "+f"(d[3])
        : "r"(a[0]), "r"(a[1]), "r"(a[2]), "r"(a[3]), "r"(b[0]), "r"(b[1]));
}
__device__ __forceinline__ uint32_t pk2(float x, float y) {
    __nv_bfloat16 hx = __float2bfloat16(x), hy = __float2bfloat16(y);
    uint16_t bx = *(uint16_t*)&hx, by = *(uint16_t*)&hy;
    return (uint32_t)bx | ((uint32_t)by << 16);
}

// ---------------------------------------------------------------------------
// Generic 64x64x16 SIMT tiled GEMM (small stages).
// ---------------------------------------------------------------------------
template<bool DO_SILU, bool HAS_BIAS>
__device__ __forceinline__ void gemm_tile(
    const float* __restrict__ A, int lda,
    const float* __restrict__ B, int ldb,
    const float* __restrict__ bias,
    float* __restrict__ C, int ldc,
    int M, int N, int K)
{
    __shared__ float As[16][64];
    __shared__ float Bs[16][64];

    const int tid = threadIdx.x;
    const int tx  = tid & 15;
    const int ty  = tid >> 4;
    const int m0  = blockIdx.y * 64;
    const int n0  = blockIdx.x * 64;

    float acc[4][4];
#pragma unroll
    for (int i = 0; i < 4; i++)
#pragma unroll
        for (int j = 0; j < 4; j++) acc[i][j] = 0.0f;

    for (int k0 = 0; k0 < K; k0 += 16) {
#pragma unroll
        for (int e = tid; e < 64 * 16; e += 256) {
            int m = e >> 4, k = e & 15;
            int gm = m0 + m, gk = k0 + k;
            As[k][m] = (gm < M && gk < K) ? A[(size_t)gm * lda + gk] : 0.0f;
        }
#pragma unroll
        for (int e = tid; e < 16 * 64; e += 256) {
            int k = e >> 6, n = e & 63;
            int gk = k0 + k, gn = n0 + n;
            Bs[k][n] = (gk < K && gn < N) ? B[(size_t)gk * ldb + gn] : 0.0f;
        }
        __syncthreads();

#pragma unroll
        for (int k = 0; k < 16; k++) {
            float4 av = *(const float4*)&As[k][ty * 4];
            float4 bv = *(const float4*)&Bs[k][tx * 4];
            float a4[4] = {av.x, av.y, av.z, av.w};
            float b4[4] = {bv.x, bv.y, bv.z, bv.w};
#pragma unroll
            for (int i = 0; i < 4; i++)
#pragma unroll
                for (int j = 0; j < 4; j++)
                    acc[i][j] += a4[i] * b4[j];
        }
        __syncthreads();
    }

#pragma unroll
    for (int i = 0; i < 4; i++) {
        int gm = m0 + ty * 4 + i;
        if (gm >= M) continue;
#pragma unroll
        for (int j = 0; j < 4; j++) {
            int gn = n0 + tx * 4 + j;
            if (gn >= N) continue;
            float v = acc[i][j];
            if (HAS_BIAS) v += bias[gn];
            if (DO_SILU)  v = silu_f(v);
            C[(size_t)gm * ldc + gn] = v;
        }
    }
}

// k_y body: SIMT gemm, epilogue writes y split planes into g_yb.
template<bool HAS_BIAS>
__device__ __forceinline__ void gemm_tile_ysplit(
    const float* __restrict__ A, int lda,
    const float* __restrict__ B, int ldb,
    const float* __restrict__ bias,
    int ci,   // coefficient index (row within 64-row plane)
    int M, int N, int K)
{
    __shared__ float As[16][64];
    __shared__ float Bs[16][64];

    const int tid = threadIdx.x;
    const int tx  = tid & 15;
    const int ty  = tid >> 4;
    const int m0  = blockIdx.y * 64;
    const int n0  = blockIdx.x * 64;

    float acc[4][4];
#pragma unroll
    for (int i = 0; i < 4; i++)
#pragma unroll
        for (int j = 0; j < 4; j++) acc[i][j] = 0.0f;

    for (int k0 = 0; k0 < K; k0 += 16) {
#pragma unroll
        for (int e = tid; e < 64 * 16; e += 256) {
            int m = e >> 4, k = e & 15;
            As[k][m] = A[(size_t)(m0 + m) * lda + k0 + k];
        }
#pragma unroll
        for (int e = tid; e < 16 * 64; e += 256) {
            int k = e >> 6, n = e & 63;
            Bs[k][n] = B[(size_t)(k0 + k) * ldb + n0 + n];
        }
        __syncthreads();

#pragma unroll
        for (int k = 0; k < 16; k++) {
            float4 av = *(const float4*)&As[k][ty * 4];
            float4 bv = *(const float4*)&Bs[k][tx * 4];
            float a4[4] = {av.x, av.y, av.z, av.w};
            float b4[4] = {bv.x, bv.y, bv.z, bv.w};
#pragma unroll
            for (int i = 0; i < 4; i++)
#pragma unroll
                for (int j = 0; j < 4; j++)
                    acc[i][j] += a4[i] * b4[j];
        }
        __syncthreads();
    }

#pragma unroll
    for (int i = 0; i < 4; i++) {
        int gm = m0 + ty * 4 + i;   // node index
        __nv_bfloat16* yb = g_yb + (size_t)gm * (YBK * HID);
#pragma unroll
        for (int jp = 0; jp < 4; jp += 2) {
            int gn = n0 + tx * 4 + jp;
            float v0 = acc[i][jp], v1 = acc[i][jp + 1];
            if (HAS_BIAS) { v0 += bias[gn]; v1 += bias[gn + 1]; }
            __nv_bfloat16 h0 = __float2bfloat16(v0), h1 = __float2bfloat16(v1);
            uint16_t b0 = *(uint16_t*)&h0, b1 = *(uint16_t*)&h1;
            uint32_t hp = (uint32_t)b0 | ((uint32_t)b1 << 16);
            uint32_t lp = pk2(v0 - __bfloat162float(h0), v1 - __bfloat162float(h1));
            *(uint32_t*)&yb[(size_t)ci * HID + gn]        = hp;
            *(uint32_t*)&yb[(size_t)(64 + ci) * HID + gn] = hp;
            *(uint32_t*)&yb[(size_t)(128 + ci) * HID + gn] = lp;
        }
    }
}

// ---------------------------- prolog kernels --------------------------------

__global__ void __launch_bounds__(256) k_w1g1(const float* __restrict__ w1,
                                              const float* __restrict__ g1) {
    int l = blockIdx.z;
    gemm_tile<false, false>(w1 + (size_t)l * CIN * HID, HID, g1, HID, nullptr,
                            g_W1G1 + (size_t)l * CIN * HID, HID, CIN, HID, HID);
}

__global__ void __launch_bounds__(256) k_g3w2(const float* __restrict__ g3,
                                              const float* __restrict__ w2) {
    int l = blockIdx.z;
    gemm_tile<false, false>(g3, HID, w2 + (size_t)l * HID * CIN, CIN, nullptr,
                            g_G3W2 + (size_t)l * HID * CIN, CIN, HID, CIN, HID);
}

__global__ void k_b1g1(const float* __restrict__ b1, const float* __restrict__ g1) {
    int k = threadIdx.x;
    float s = 0.0f;
    for (int h = 0; h < HID; h++) s += b1[h] * g1[(size_t)h * HID + k];
    g_b1g1[k] = s;
}

// g_Tb [384 x 192]: cols [0,64)=hi(T[p][i]), [64,128)=lo, [128,192)=hi; pads 0.
__global__ void k_prepT(const float* __restrict__ T) {
    int p = blockIdx.x;          // 0..383
    int c = threadIdx.x;         // 0..191
    int reg = c >> 6, i = c & 63;
    float v = (p < NP && i < NC) ? T[p * NC + i] : 0.0f;
    __nv_bfloat16 h = __float2bfloat16(v);
    __nv_bfloat16 o = (reg == 1) ? __float2bfloat16(v - __bfloat162float(h)) : h;
    g_Tb[p * YBK + c] = o;
}

// g_FTb [64 x 1056]: col block b*352+p: b0=hi(F[p][i]), b1=lo, b2=hi; pads 0.
__global__ void k_prepFT(const float* __restrict__ F) {
    int i = blockIdx.x;          // 0..63
    int reg = blockIdx.y;        // 0..2
    int p = threadIdx.x;         // 0..351
    float v = (i < NC && p < NP) ? F[p * NC + i] : 0.0f;
    __nv_bfloat16 h = __float2bfloat16(v);
    __nv_bfloat16 o = (reg == 1) ? __float2bfloat16(v - __bfloat162float(h)) : h;
    g_FTb[i * ZK + reg * PBLK + p] = o;
}

// g_g2b [256 x 768] rows n: [hi(g2[k][n]) | hi | lo]
__global__ void k_prepg2(const float* __restrict__ g2) {
    int k = blockIdx.x;
    int n = threadIdx.x;
    float x = g2[(size_t)k * HID + n];
    __nv_bfloat16 h = __float2bfloat16(x);
    float r = x - __bfloat162float(h);
    __nv_bfloat16* row = g_g2b + (size_t)n * KS3;
    row[k]           = h;
    row[HID + k]     = h;
    row[2 * HID + k] = __float2bfloat16(r);
}

// zero y pad rows (i in [49,64) of each 64-row plane)
__global__ void k_pad_yb() {
    int q = blockIdx.x;                      // 0..44
    int node = blockIdx.y;
    int row = (q / 15) * 64 + NC + (q % 15);
    *(uint32_t*)&g_yb[(size_t)node * (YBK * HID) + (size_t)row * HID + threadIdx.x * 2] = 0;
}

// zero grid2b pad rows (p in [324,352) of each 352-row block)
__global__ void k_pad_g2b() {
    int q = blockIdx.x;                      // 0..83
    int node = blockIdx.y;
    int row = (q / 28) * PBLK + NP + (q % 28);
    *(uint32_t*)&g_grid2b[(size_t)node * (ZK * HID) + (size_t)row * HID + threadIdx.x * 2] = 0;
}

// ---------------------------- main stage kernels ----------------------------

__global__ void __launch_bounds__(256) k_gate(const float* __restrict__ nf,
                                              const float* __restrict__ ws,
                                              const float* __restrict__ bs) {
    gemm_tile<true, true>(nf, NC * CIN, ws, HID, bs, g_gate, HID,
                          N_NODES, HID, CIN);
}

__global__ void __launch_bounds__(256) k_y(const float* __restrict__ nf) {
    int i = blockIdx.z;
    int l = deg_of(i);
    const float* A = nf + (size_t)i * CIN;
    const float* B = g_W1G1 + (size_t)l * CIN * HID;
    if (i == 0)
        gemm_tile_ysplit<true>(A, NC * CIN, B, HID, g_b1g1, i, N_NODES, HID, CIN);
    else
        gemm_tile_ysplit<false>(A, NC * CIN, B, HID, nullptr, i, N_NODES, HID, CIN);
}

// ---------------- grid1 = silu(T @ y[n]) : bf16 MMA, trans-B ----------------
// A = g_Tb [384 x 192] (row 64B tiles), B = g_yb[n] [192 x 256] via ldsm.trans.
__global__ void __launch_bounds__(256, 1) k_grid1_mma() {
    __shared__ __align__(128) char smem[2 * (BM * 64 + BK * 512)];  // 49152
    const uint32_t sbase = smem_u32(smem);
    const int tid = threadIdx.x;
    const int wid = tid >> 5;
    const int lid = tid & 31;
    const int wm  = wid & 1;
    const int wn  = wid >> 1;
    const int node = blockIdx.y;
    const int m0 = blockIdx.x * BM;          // row in padded 384

    const uint32_t STAGE = BM * 64 + BK * 512;   // 24576
    const uint32_t BOFF  = BM * 64;              // 8192

    uint32_t a_addr[4][2], b_addr[4][2];
#pragma unroll
    for (int mt = 0; mt < 4; mt++)
#pragma unroll
        for (int ks = 0; ks < 2; ks++) {
            int row = wm * 64 + mt * 16 + (lid & 7) + ((lid >> 3) & 1) * 8;
            int ch  = ks * 2 + (lid >> 4);
            a_addr[mt][ks] = sbase + row * 64 + 16 * (ch ^ ((row >> 1) & 3));
        }
#pragma unroll
    for (int np = 0; np < 4; np++)
#pragma unroll
        for (int ks = 0; ks < 2; ks++) {
            int row = ks * 16 + (lid & 7) + 8 * ((lid >> 3) & 1);
            int cn  = wn * 8 + np * 2 + (lid >> 4);
            b_addr[np][ks] = sbase + BOFF + row * 512 + 16 * (cn ^ (row & 7));
        }

    uint32_t a_dst[2], b_dst[4];
    const __nv_bfloat16* a_src[2];
    const __nv_bfloat16* b_src[4];
    const __nv_bfloat16* ybn = g_yb + (size_t)node * (YBK * HID);
#pragma unroll
    for (int i = 0; i < 2; i++) {
        int id = tid + i * 256, r = id >> 2, c = id & 3;
        a_dst[i] = sbase + r * 64 + 16 * (c ^ ((r >> 1) & 3));
        a_src[i] = g_Tb + (m0 + r) * YBK + c * 8;
    }
#pragma unroll
    for (int i = 0; i < 4; i++) {
        int id = tid + i * 256, r = id >> 5, c = id & 31;
        b_dst[i] = sbase + BOFF + r * 512 + 16 * (c ^ (r & 7));
        b_src[i] = ybn + r * HID + c * 8;
    }

    float acc[4][8][4];
#pragma unroll
    for (int mt = 0; mt < 4; mt++)
#pragma unroll
        for (int nt = 0; nt < 8; nt++)
#pragma unroll
            for (int v = 0; v < 4; v++) acc[mt][nt][v] = 0.0f;

#pragma unroll
    for (int i = 0; i < 2; i++) cp_async16(a_dst[i], a_src[i]);
#pragma unroll
    for (int i = 0; i < 4; i++) cp_async16(b_dst[i], b_src[i]);
    asm volatile("cp.async.commit_group;");

#pragma unroll 1
    for (int kc = 0; kc < NITER1; kc++) {
        const int cur = kc & 1;
        if (kc + 1 < NITER1) {
            const uint32_t so = ((kc + 1) & 1) * STAGE;
            const int ko = (kc + 1) * BK;
#pragma unroll
            for (int i = 0; i < 2; i++) cp_async16(a_dst[i] + so, a_src[i] + ko);
#pragma unroll
            for (int i = 0; i < 4; i++) cp_async16(b_dst[i] + so, b_src[i] + ko * HID);
            asm volatile("cp.async.commit_group;");
            asm volatile("cp.async.wait_group 1;");
        } else {
            asm volatile("cp.async.wait_group 0;");
        }
        __syncthreads();

        const uint32_t so = cur * STAGE;
#pragma unroll
        for (int ks = 0; ks < 2; ks++) {
            uint32_t af[4][4], bf[8][2];
#pragma unroll
            for (int mt = 0; mt < 4; mt++)
                ldsm_x4(af[mt][0], af[mt][1], af[mt][2], af[mt][3],
                        a_addr[mt][ks] + so);
#pragma unroll
            for (int np = 0; np < 4; np++)
                ldsm_x4_t(bf[2 * np][0], bf[2 * np][1], bf[2 * np + 1][0],
                          bf[2 * np + 1][1], b_addr[np][ks] + so);
#pragma unroll
            for (int mt = 0; mt < 4; mt++)
#pragma unroll
                for (int nt = 0; nt < 8; nt++)
                    mma_bf16(acc[mt][nt], af[mt], bf[nt]);
        }
        __syncthreads();
    }

    // Epilogue: silu + split store into g_grid1b rows [hi | lo | hi].
    const int tq = lid >> 2;
    const int tr = lid & 3;
#pragma unroll
    for (int mt = 0; mt < 4; mt++) {
#pragma unroll
        for (int half = 0; half < 2; half++) {
            int p = m0 + wm * 64 + mt * 16 + tq + half * 8;
            if (p >= NP) continue;
            __nv_bfloat16* row = g_grid1b + ((size_t)node * NP + p) * KS3;
#pragma unroll
            for (int nt = 0; nt < 8; nt++) {
                int col = wn * 64 + nt * 8 + tr * 2;
                float v0 = silu_f(acc[mt][nt][half * 2 + 0]);
                float v1 = silu_f(acc[mt][nt][half * 2 + 1]);
                __nv_bfloat16 h0 = __float2bfloat16(v0), h1 = __float2bfloat16(v1);
                uint16_t x0 = *(uint16_t*)&h0, x1 = *(uint16_t*)&h1;
                uint32_t hp = (uint32_t)x0 | ((uint32_t)x1 << 16);
                uint32_t lp = pk2(v0 - __bfloat162float(h0), v1 - __bfloat162float(h1));
                *(uint32_t*)&row[col]       = hp;
                *(uint32_t*)&row[HID + col] = lp;
                *(uint32_t*)&row[2 * HID + col] = hp;
            }
        }
    }
}

// ------------- grid2 = silu(grid1 @ g2): bf16 MMA (round-3 core) ------------
// Epilogue now writes bf16 split rows into g_grid2b [n][1056][256].
__global__ void __launch_bounds__(256, 1) k_grid2_mma() {
    __shared__ __align__(128) char smem[2 * (BM * 64 + BN * 64)];  // 49152
    const uint32_t sbase = smem_u32(smem);
    const int tid = threadIdx.x;
    const int wid = tid >> 5;
    const int lid = tid & 31;
    const int wm  = wid & 1;
    const int wn  = wid >> 1;
    const size_t m0 = (size_t)blockIdx.x * BM;

    const uint32_t STAGE = BM * 64 + BN * 64;
    const uint32_t BOFF  = BM * 64;

    uint32_t a_addr[4][2], b_addr[4][2];
#pragma unroll
    for (int mt = 0; mt < 4; mt++)
#pragma unroll
        for (int ks = 0; ks < 2; ks++) {
            int row = wm * 64 + mt * 16 + (lid & 7) + ((lid >> 3) & 1) * 8;
            int ch  = ks * 2 + (lid >> 4);
            a_addr[mt][ks] = sbase + row * 64 + 16 * (ch ^ ((row >> 1) & 3));
        }
#pragma unroll
    for (int np = 0; np < 4; np++)
#pragma unroll
        for (int ks = 0; ks < 2; ks++) {
            int row = wn * 64 + np * 16 + (lid & 7) + (lid >> 4) * 8;
            int ch  = ks * 2 + ((lid >> 3) & 1);
            b_addr[np][ks] = sbase + BOFF + row * 64 + 16 * (ch ^ ((row >> 1) & 3));
        }

    uint32_t a_dst[2], b_dst[4];
    const __nv_bfloat16* a_src[2];
    const __nv_bfloat16* b_src[4];
#pragma unroll
    for (int i = 0; i < 2; i++) {
        int id = tid + i * 256, r = id >> 2, c = id & 3;
        a_dst[i] = sbase + r * 64 + 16 * (c ^ ((r >> 1) & 3));
        a_src[i] = g_grid1b + (m0 + r) * (size_t)KS3 + c * 8;
    }
#pragma unroll
    for (int i = 0; i < 4; i++) {
        int id = tid + i * 256, r = id >> 2, c = id & 3;
        b_dst[i] = sbase + BOFF + r * 64 + 16 * (c ^ ((r >> 1) & 3));
        b_src[i] = g_g2b + r * (size_t)KS3 + c * 8;
    }

    float acc[4][8][4];
#pragma unroll
    for (int mt = 0; mt < 4; mt++)
#pragma unroll
        for (int nt = 0; nt < 8; nt++)
#pragma unroll
            for (int v = 0; v < 4; v++) acc[mt][nt][v] = 0.0f;

#pragma unroll
    for (int i = 0; i < 2; i++) cp_async16(a_dst[i], a_src[i]);
#pragma unroll
    for (int i = 0; i < 4; i++) cp_async16(b_dst[i], b_src[i]);
    asm volatile("cp.async.commit_group;");

#pragma unroll 1
    for (int kc = 0; kc < NITER2; kc++) {
        const int cur = kc & 1;
        if (kc + 1 < NITER2) {
            const uint32_t so = ((kc + 1) & 1) * STAGE;
            const int ko = (kc + 1) * BK;
#pragma unroll
            for (int i = 0; i < 2; i++) cp_async16(a_dst[i] + so, a_src[i] + ko);
#pragma unroll
            for (int i = 0; i < 4; i++) cp_async16(b_dst[i] + so, b_src[i] + ko);
            asm volatile("cp.async.commit_group;");
            asm volatile("cp.async.wait_group 1;");
        } else {
            asm volatile("cp.async.wait_group 0;");
        }
        __syncthreads();

        const uint32_t so = cur * STAGE;
#pragma unroll
        for (int ks = 0; ks < 2; ks++) {
            uint32_t af[4][4], bf[8][2];
#pragma unroll
            for (int mt = 0; mt < 4; mt++)
                ldsm_x4(af[mt][0], af[mt][1], af[mt][2], af[mt][3],
                        a_addr[mt][ks] + so);
#pragma unroll
            for (int np = 0; np < 4; np++)
                ldsm_x4(bf[2 * np][0], bf[2 * np][1], bf[2 * np + 1][0],
                        bf[2 * np + 1][1], b_addr[np][ks] + so);
#pragma unroll
            for (int mt = 0; mt < 4; mt++)
#pragma unroll
                for (int nt = 0; nt < 8; nt++)
                    mma_bf16(acc[mt][nt], af[mt], bf[nt]);
        }
        __syncthreads();
    }

    // Epilogue: silu + split store into g_grid2b [n][p | 352+p | 704+p][h].
    const int tq = lid >> 2;
    const int tr = lid & 3;
#pragma unroll
    for (int mt = 0; mt < 4; mt++) {
#pragma unroll
        for (int half = 0; half < 2; half++) {
            size_t r = m0 + wm * 64 + mt * 16 + tq + half * 8;
            uint32_t n = (uint32_t)(r / NP);
            uint32_t p = (uint32_t)(r - (size_t)n * NP);
            __nv_bfloat16* row = g_grid2b + ((size_t)n * ZK + p) * HID;
#pragma unroll
            for (int nt = 0; nt < 8; nt++) {
                int col = wn * 64 + nt * 8 + tr * 2;
                float v0 = silu_f(acc[mt][nt][half * 2 + 0]);
                float v1 = silu_f(acc[mt][nt][half * 2 + 1]);
                __nv_bfloat16 h0 = __float2bfloat16(v0), h1 = __float2bfloat16(v1);
                uint16_t x0 = *(uint16_t*)&h0, x1 = *(uint16_t*)&h1;
                uint32_t hp = (uint32_t)x0 | ((uint32_t)x1 << 16);
                uint32_t lp = pk2(v0 - __bfloat162float(h0), v1 - __bfloat162float(h1));
                *(uint32_t*)&row[col]                   = hp;
                *(uint32_t*)&row[PBLK * HID + col]      = hp;
                *(uint32_t*)&row[2 * PBLK * HID + col]  = lp;
            }
        }
    }
}

// ---------------- z = F^T @ grid2[n] : bf16 MMA, trans-B --------------------
// A = g_FTb [64 x 1056], B = g_grid2b[n] [1056 x 256] via ldsm.trans. fp32 out.
__global__ void __launch_bounds__(256, 1) k_z_mma() {
    __shared__ __align__(128) char smem[2 * (64 * 64 + BK * 512)];  // 40960
    const uint32_t sbase = smem_u32(smem);
    const int tid = threadIdx.x;
    const int wid = tid >> 5;
    const int lid = tid & 31;
    const int node = blockIdx.x;

    const uint32_t STAGE = 64 * 64 + BK * 512;   // 20480
    const uint32_t BOFF  = 64 * 64;              // 4096

    uint32_t a_addr[4][2], b_addr[2][2];
#pragma unroll
    for (int mt = 0; mt < 4; mt++)
#pragma unroll
        for (int ks = 0; ks < 2; ks++) {
            int row = mt * 16 + (lid & 7) + ((lid >> 3) & 1) * 8;
            int ch  = ks * 2 + (lid >> 4);
            a_addr[mt][ks] = sbase + row * 64 + 16 * (ch ^ ((row >> 1) & 3));
        }
#pragma unroll
    for (int np = 0; np < 2; np++)
#pragma unroll
        for (int ks = 0; ks < 2; ks++) {
            int row = ks * 16 + (lid & 7) + 8 * ((lid >> 3) & 1);
            int cn  = wid * 4 + np * 2 + (lid >> 4);
            b_addr[np][ks] = sbase + BOFF + row * 512 + 16 * (cn ^ (row & 7));
        }

    uint32_t a_dst, b_dst[4];
    const __nv_bfloat16* a_srcp;
    const __nv_bfloat16* b_src[4];
    const __nv_bfloat16* g2bn = g_grid2b + (size_t)node * (ZK * HID);
    {
        int r = tid >> 2, c = tid & 3;
        a_dst = sbase + r * 64 + 16 * (c ^ ((r >> 1) & 3));
        a_srcp = g_FTb + r * ZK + c * 8;
    }
#pragma unroll
    for (int i = 0; i < 4; i++) {
        int id = tid + i * 256, r = id >> 5, c = id & 31;
        b_dst[i] = sbase + BOFF + r * 512 + 16 * (c ^ (r & 7));
        b_src[i] = g2bn + r * HID + c * 8;
    }

    float acc[4][4][4];
#pragma unroll
    for (int mt = 0; mt < 4; mt++)
#pragma unroll
        for (int nt = 0; nt < 4; nt++)
#pragma unroll
            for (int v = 0; v < 4; v++) acc[mt][nt][v] = 0.0f;

    cp_async16(a_dst, a_srcp);
#pragma unroll
    for (int i = 0; i < 4; i++) cp_async16(b_dst[i], b_src[i]);
    asm volatile("cp.async.commit_group;");

#pragma unroll 1
    for (int kc = 0; kc < NITERZ; kc++) {
        const int cur = kc & 1;
        if (kc + 1 < NITERZ) {
            const uint32_t so = ((kc + 1) & 1) * STAGE;
            const int ko = (kc + 1) * BK;
            cp_async16(a_dst + so, a_srcp + ko);
#pragma unroll
            for (int i = 0; i < 4; i++) cp_async16(b_dst[i] + so, b_src[i] + ko * HID);
            asm volatile("cp.async.commit_group;");
            asm volatile("cp.async.wait_group 1;");
        } else {
            asm volatile("cp.async.wait_group 0;");
        }
        __syncthreads();

        const uint32_t so = cur * STAGE;
#pragma unroll
        for (int ks = 0; ks < 2; ks++) {
            uint32_t af[4][4], bf[4][2];
#pragma unroll
            for (int mt = 0; mt < 4; mt++)
                ldsm_x4(af[mt][0], af[mt][1], af[mt][2], af[mt][3],
                        a_addr[mt][ks] + so);
#pragma unroll
            for (int np = 0; np < 2; np++)
                ldsm_x4_t(bf[2 * np][0], bf[2 * np][1], bf[2 * np + 1][0],
                          bf[2 * np + 1][1], b_addr[np][ks] + so);
#pragma unroll
            for (int mt = 0; mt < 4; mt++)
#pragma unroll
                for (int nt = 0; nt < 4; nt++)
                    mma_bf16(acc[mt][nt], af[mt], bf[nt]);
        }
        __syncthreads();
    }

    // Epilogue: fp32 store z[n][i][h], i < 49.
    const int tq = lid >> 2;
    const int tr = lid & 3;
#pragma unroll
    for (int mt = 0; mt < 4; mt++) {
#pragma unroll
        for (int half = 0; half < 2; half++) {
            int i = mt * 16 + tq + half * 8;
            if (i >= NC) continue;
            float* row = g_z + ((size_t)node * NC + i) * HID;
#pragma unroll
            for (int nt = 0; nt < 4; nt++) {
                int col = wid * 32 + nt * 8 + tr * 2;
                float2 v;
                v.x = acc[mt][nt][half * 2 + 0];
                v.y = acc[mt][nt][half * 2 + 1];
                *(float2*)&row[col] = v;
            }
        }
    }
}

__global__ void __launch_bounds__(256) k_out(const float* __restrict__ w2,
                                             const float* __restrict__ b2,
                                             float* __restrict__ out) {
    int i = blockIdx.z;
    if (i == 0) {
        gemm_tile<false, true>(g_gate, HID, w2, CIN, b2,
                               out, NC * CIN, N_NODES, CIN, HID);
    } else {
        int l = deg_of(i);
        gemm_tile<false, false>(g_z + (size_t)i * HID, NC * HID,
                                g_G3W2 + (size_t)l * HID * CIN, CIN, nullptr,
                                out + (size_t)i * CIN, NC * CIN,
                                N_NODES, CIN, HID);
    }
}

// ---------------------------------------------------------------------------

extern "C" void kernel_launch(void* const* d_in, const int* in_sizes, int n_in,
                              void* d_out, int out_size) {
    const float* nf = (const float*)d_in[0];
    const float* w1 = (const float*)d_in[1];
    const float* b1 = (const float*)d_in[2];
    const float* w2 = (const float*)d_in[3];
    const float* b2 = (const float*)d_in[4];
    const float* ws = (const float*)d_in[5];
    const float* bs = (const float*)d_in[6];
    const float* g1 = (const float*)d_in[7];
    const float* g2 = (const float*)d_in[8];
    const float* g3 = (const float*)d_in[9];
    const float* Tg = (const float*)d_in[10];
    const float* Fg = (const float*)d_in[11];
    float* out = (float*)d_out;

    // prologs
    k_w1g1<<<dim3(HID / 64, CIN / 64, NL), 256>>>(w1, g1);
    k_g3w2<<<dim3(CIN / 64, HID / 64, NL), 256>>>(g3, w2);
    k_b1g1<<<1, HID>>>(b1, g1);
    k_prepT<<<384, YBK>>>(Tg);
    k_prepFT<<<dim3(64, 3), PBLK>>>(Fg);
    k_prepg2<<<HID, HID>>>(g2);
    k_pad_yb<<<dim3(45, N_NODES), 128>>>();
    k_pad_g2b<<<dim3(84, N_NODES), 128>>>();

    // scalar gating branch
    k_gate<<<dim3(HID / 64, N_NODES / 64), 256>>>(nf, ws, bs);

    // main pipeline
    k_y<<<dim3(HID / 64, N_NODES / 64, NC), 256>>>(nf);
    k_grid1_mma<<<dim3(3, N_NODES), 256>>>();
    k_grid2_mma<<<(int)(MROWS / BM), 256>>>();
    k_z_mma<<<N_NODES, 256>>>();
    k_out<<<dim3(CIN / 64, N_NODES / 64, NC), 256>>>(w2, b2, out);
}

// round 5
// speedup vs baseline: 2.5235x; 1.0630x over previous
#include <cuda_runtime.h>
#include <cuda_bf16.h>
#include <cstdint>

// ---------------------------------------------------------------------------
// FeedForwardNetwork (SO(3) equivariant FFN), sm_103a — HMMA mma.sync path
//
//   y      = blockdiag_l(nf @ (w1[l] @ g1)) ; y[:,0,:] += b1 @ g1
//            -> bf16 planes [n][128][256]: rows [0,64)=hi, [64,128)=lo
//   grid1  = silu(T @ y)  per node  (A = split T [384x192] = [hi|lo|hi])
//            -> bf16 rows [m][512] = [hi(256) | lo(256)]
//   grid2  = silu(grid1 @ g2)  (B = g2^T [256x512] = [hi|lo], chunk-remapped)
//            -> bf16 per node [n][704][256]: rows [0,352)=hi(p), [352,704)=lo(p)
//   z      = F^T @ grid2  per node (A = split F^T [64x704] = [hi|lo]) -> fp32
//   out[:,i>=1,:] = z[:,i,:] @ (g3 @ w2[l(i)])
//   out[:,0,:]    = silu(nf[:,0,:] @ ws + bs) @ w2[0] + b2
//
// Split-precision per big GEMM: terms hi*hi + lo*hi + hi*lo (drop lo*lo).
// Duplicate-hi planes are NOT stored; the consumer remaps cp.async source
// offsets per K-chunk instead.
// ---------------------------------------------------------------------------

#define N_NODES 1024
#define NC      49
#define CIN     128
#define HID     256
#define RES     18
#define NP      (RES*RES)   // 324
#define NL      7
#define MROWS   ((size_t)N_NODES * NP)   // 331776
#define KST     512          // grid1b / g2b storage width (hi|lo)
#define YROWS   128          // yb rows (hi 64 | lo 64)
#define PBLK    352          // padded grid-point block
#define ZROWS   (2*PBLK)     // 704 grid2b rows per node (hi|lo)
#define BM      128
#define BN      256
#define BK      32
#define NITER2  24           // grid2 K chunks (3*256/32)
#define NITER1  6            // grid1 K chunks (3*64/32)
#define NITERZ  33           // z K chunks (3*352/32)

// -------- scratch (static device globals; no runtime allocation) -----------
__device__ float g_W1G1[NL * CIN * HID];
__device__ float g_G3W2[NL * HID * CIN];
__device__ float g_b1g1[HID];
__device__ __nv_bfloat16 g_Tb[384 * 192];            // split to_grid [hi|lo|hi]
__device__ __nv_bfloat16 g_FTb[64 * ZROWS];          // split from_grid^T [hi|lo]
__device__ __nv_bfloat16 g_g2b[HID * KST];           // split g2^T [hi|lo]
__device__ __nv_bfloat16 g_yb[(size_t)N_NODES * YROWS * HID];    // 67 MB
__device__ __nv_bfloat16 g_grid1b[MROWS * KST];                  // 340 MB
__device__ __nv_bfloat16 g_grid2b[(size_t)N_NODES * ZROWS * HID];// 369 MB
__device__ float g_z[(size_t)N_NODES * NC * HID];                // 51 MB
__device__ float g_gate[(size_t)N_NODES * HID];

__device__ __forceinline__ float silu_f(float x) {
    return x / (1.0f + __expf(-x));
}
__device__ __forceinline__ int deg_of(int i) {
    int l = 0;
    while ((l + 1) * (l + 1) <= i) ++l;
    return l;
}
__device__ __forceinline__ uint32_t smem_u32(const void* p) {
    uint32_t a;
    asm("{ .reg .u64 t; cvta.to.shared.u64 t, %1; cvt.u32.u64 %0, t; }"
        : "=r"(a) : "l"(p));
    return a;
}
__device__ __forceinline__ void cp_async16(uint32_t dst, const void* src) {
    asm volatile("cp.async.cg.shared.global [%0], [%1], 16;" :: "r"(dst), "l"(src));
}
__device__ __forceinline__ void ldsm_x4(uint32_t& r0, uint32_t& r1,
                                        uint32_t& r2, uint32_t& r3, uint32_t addr) {
    asm volatile("ldmatrix.sync.aligned.m8n8.x4.shared.b16 {%0,%1,%2,%3}, [%4];"
                 : "=r"(r0), "=r"(r1), "=r"(r2), "=r"(r3) : "r"(addr));
}
__device__ __forceinline__ void ldsm_x4_t(uint32_t& r0, uint32_t& r1,
                                          uint32_t& r2, uint32_t& r3, uint32_t addr) {
    asm volatile("ldmatrix.sync.aligned.m8n8.x4.trans.shared.b16 {%0,%1,%2,%3}, [%4];"
                 : "=r"(r0), "=r"(r1), "=r"(r2), "=r"(r3) : "r"(addr));
}
__device__ __forceinline__ void mma_bf16(float* d, const uint32_t* a, const uint32_t* b) {
    asm volatile(
        "mma.sync.aligned.m16n8k16.row.col.f32.bf16.bf16.f32 "
        "{%0,%1,%2,%3}, {%4,%5,%6,%7}, {%8,%9}, {%0,%1,%2,%3};"
        : "+f"(d[0]), "+f"(d[1]), "+f"(d[2]), "+f"(d[3])
        : "r"(a[0]), "r"(a[1]), "r"(a[2]), "r"(a[3]), "r"(b[0]), "r"(b[1]));
}
__device__ __forceinline__ uint32_t pk2(float x, float y) {
    __nv_bfloat16 hx = __float2bfloat16(x), hy = __float2bfloat16(y);
    uint16_t bx = *(uint16_t*)&hx, by = *(uint16_t*)&hy;
    return (uint32_t)bx | ((uint32_t)by << 16);
}

// K-chunk source-offset maps (duplicate-hi read twice from compact storage).
// grid2: A terms [hi|lo|hi] over grid1b [hi|lo]; B terms [hi|hi|lo] over g2b.
__device__ __forceinline__ int aoff2(int kc) {          // element offset
    return kc < 8 ? kc * 32 : kc < 16 ? 256 + (kc - 8) * 32 : (kc - 16) * 32;
}
__device__ __forceinline__ int boff2(int kc) {
    return kc < 8 ? kc * 32 : kc < 16 ? (kc - 8) * 32 : 256 + (kc - 16) * 32;
}
// grid1: A = Tb (full [hi|lo|hi], linear). B terms [hi|hi|lo] over yb row blocks.
__device__ __forceinline__ int brow1(int kc) {          // row offset into yb
    return kc < 2 ? kc * 32 : kc < 4 ? (kc - 2) * 32 : 64 + (kc - 4) * 32;
}
// z: A terms [hi|lo|hi] over FTb [hi|lo] cols; B terms [hi|hi|lo] over grid2b rows.
__device__ __forceinline__ int aoffz(int kc) {
    return kc < 11 ? kc * 32 : kc < 22 ? PBLK + (kc - 11) * 32 : (kc - 22) * 32;
}
__device__ __forceinline__ int browz(int kc) {
    return kc < 11 ? kc * 32 : kc < 22 ? (kc - 11) * 32 : PBLK + (kc - 22) * 32;
}

// ---------------------------------------------------------------------------
// Generic 64x64x16 SIMT tiled GEMM (small stages).
// ---------------------------------------------------------------------------
template<bool DO_SILU, bool HAS_BIAS>
__device__ __forceinline__ void gemm_tile(
    const float* __restrict__ A, int lda,
    const float* __restrict__ B, int ldb,
    const float* __restrict__ bias,
    float* __restrict__ C, int ldc,
    int M, int N, int K)
{
    __shared__ float As[16][64];
    __shared__ float Bs[16][64];

    const int tid = threadIdx.x;
    const int tx  = tid & 15;
    const int ty  = tid >> 4;
    const int m0  = blockIdx.y * 64;
    const int n0  = blockIdx.x * 64;

    float acc[4][4];
#pragma unroll
    for (int i = 0; i < 4; i++)
#pragma unroll
        for (int j = 0; j < 4; j++) acc[i][j] = 0.0f;

    for (int k0 = 0; k0 < K; k0 += 16) {
#pragma unroll
        for (int e = tid; e < 64 * 16; e += 256) {
            int m = e >> 4, k = e & 15;
            int gm = m0 + m, gk = k0 + k;
            As[k][m] = (gm < M && gk < K) ? A[(size_t)gm * lda + gk] : 0.0f;
        }
#pragma unroll
        for (int e = tid; e < 16 * 64; e += 256) {
            int k = e >> 6, n = e & 63;
            int gk = k0 + k, gn = n0 + n;
            Bs[k][n] = (gk < K && gn < N) ? B[(size_t)gk * ldb + gn] : 0.0f;
        }
        __syncthreads();

#pragma unroll
        for (int k = 0; k < 16; k++) {
            float4 av = *(const float4*)&As[k][ty * 4];
            float4 bv = *(const float4*)&Bs[k][tx * 4];
            float a4[4] = {av.x, av.y, av.z, av.w};
            float b4[4] = {bv.x, bv.y, bv.z, bv.w};
#pragma unroll
            for (int i = 0; i < 4; i++)
#pragma unroll
                for (int j = 0; j < 4; j++)
                    acc[i][j] += a4[i] * b4[j];
        }
        __syncthreads();
    }

#pragma unroll
    for (int i = 0; i < 4; i++) {
        int gm = m0 + ty * 4 + i;
        if (gm >= M) continue;
#pragma unroll
        for (int j = 0; j < 4; j++) {
            int gn = n0 + tx * 4 + j;
            if (gn >= N) continue;
            float v = acc[i][j];
            if (HAS_BIAS) v += bias[gn];
            if (DO_SILU)  v = silu_f(v);
            C[(size_t)gm * ldc + gn] = v;
        }
    }
}

// k_y body: SIMT gemm, epilogue writes y hi/lo planes into g_yb.
template<bool HAS_BIAS>
__device__ __forceinline__ void gemm_tile_ysplit(
    const float* __restrict__ A, int lda,
    const float* __restrict__ B, int ldb,
    const float* __restrict__ bias,
    int ci, int M, int N, int K)
{
    __shared__ float As[16][64];
    __shared__ float Bs[16][64];

    const int tid = threadIdx.x;
    const int tx  = tid & 15;
    const int ty  = tid >> 4;
    const int m0  = blockIdx.y * 64;
    const int n0  = blockIdx.x * 64;

    float acc[4][4];
#pragma unroll
    for (int i = 0; i < 4; i++)
#pragma unroll
        for (int j = 0; j < 4; j++) acc[i][j] = 0.0f;

    for (int k0 = 0; k0 < K; k0 += 16) {
#pragma unroll
        for (int e = tid; e < 64 * 16; e += 256) {
            int m = e >> 4, k = e & 15;
            As[k][m] = A[(size_t)(m0 + m) * lda + k0 + k];
        }
#pragma unroll
        for (int e = tid; e < 16 * 64; e += 256) {
            int k = e >> 6, n = e & 63;
            Bs[k][n] = B[(size_t)(k0 + k) * ldb + n0 + n];
        }
        __syncthreads();

#pragma unroll
        for (int k = 0; k < 16; k++) {
            float4 av = *(const float4*)&As[k][ty * 4];
            float4 bv = *(const float4*)&Bs[k][tx * 4];
            float a4[4] = {av.x, av.y, av.z, av.w};
            float b4[4] = {bv.x, bv.y, bv.z, bv.w};
#pragma unroll
            for (int i = 0; i < 4; i++)
#pragma unroll
                for (int j = 0; j < 4; j++)
                    acc[i][j] += a4[i] * b4[j];
        }
        __syncthreads();
    }

#pragma unroll
    for (int i = 0; i < 4; i++) {
        int gm = m0 + ty * 4 + i;   // node index
        __nv_bfloat16* yb = g_yb + (size_t)gm * (YROWS * HID);
#pragma unroll
        for (int jp = 0; jp < 4; jp += 2) {
            int gn = n0 + tx * 4 + jp;
            float v0 = acc[i][jp], v1 = acc[i][jp + 1];
            if (HAS_BIAS) { v0 += bias[gn]; v1 += bias[gn + 1]; }
            __nv_bfloat16 h0 = __float2bfloat16(v0), h1 = __float2bfloat16(v1);
            uint16_t b0 = *(uint16_t*)&h0, b1 = *(uint16_t*)&h1;
            uint32_t hp = (uint32_t)b0 | ((uint32_t)b1 << 16);
            uint32_t lp = pk2(v0 - __bfloat162float(h0), v1 - __bfloat162float(h1));
            *(uint32_t*)&yb[(size_t)ci * HID + gn]        = hp;
            *(uint32_t*)&yb[(size_t)(64 + ci) * HID + gn] = lp;
        }
    }
}

// ---------------------------- prolog kernels --------------------------------

__global__ void __launch_bounds__(256) k_w1g1(const float* __restrict__ w1,
                                              const float* __restrict__ g1) {
    int l = blockIdx.z;
    gemm_tile<false, false>(w1 + (size_t)l * CIN * HID, HID, g1, HID, nullptr,
                            g_W1G1 + (size_t)l * CIN * HID, HID, CIN, HID, HID);
}

__global__ void __launch_bounds__(256) k_g3w2(const float* __restrict__ g3,
                                              const float* __restrict__ w2) {
    int l = blockIdx.z;
    gemm_tile<false, false>(g3, HID, w2 + (size_t)l * HID * CIN, CIN, nullptr,
                            g_G3W2 + (size_t)l * HID * CIN, CIN, HID, CIN, HID);
}

__global__ void k_b1g1(const float* __restrict__ b1, const float* __restrict__ g1) {
    int k = threadIdx.x;
    float s = 0.0f;
    for (int h = 0; h < HID; h++) s += b1[h] * g1[(size_t)h * HID + k];
    g_b1g1[k] = s;
}

// g_Tb [384 x 192]: cols [0,64)=hi, [64,128)=lo, [128,192)=hi; pads 0.
__global__ void k_prepT(const float* __restrict__ T) {
    int p = blockIdx.x;
    int c = threadIdx.x;
    int reg = c >> 6, i = c & 63;
    float v = (p < NP && i < NC) ? T[p * NC + i] : 0.0f;
    __nv_bfloat16 h = __float2bfloat16(v);
    __nv_bfloat16 o = (reg == 1) ? __float2bfloat16(v - __bfloat162float(h)) : h;
    g_Tb[p * 192 + c] = o;
}

// g_FTb [64 x 704]: cols [0,352)=hi(F[p][i]), [352,704)=lo; pads 0.
__global__ void k_prepFT(const float* __restrict__ F) {
    int i = blockIdx.x;          // 0..63
    int reg = blockIdx.y;        // 0..1
    int p = threadIdx.x;         // 0..351
    float v = (i < NC && p < NP) ? F[p * NC + i] : 0.0f;
    __nv_bfloat16 h = __float2bfloat16(v);
    __nv_bfloat16 o = reg ? __float2bfloat16(v - __bfloat162float(h)) : h;
    g_FTb[i * ZROWS + reg * PBLK + p] = o;
}

// g_g2b [256 x 512] rows n: [hi(g2[k][n]) | lo]
__global__ void k_prepg2(const float* __restrict__ g2) {
    int k = blockIdx.x;
    int n = threadIdx.x;
    float x = g2[(size_t)k * HID + n];
    __nv_bfloat16 h = __float2bfloat16(x);
    __nv_bfloat16* row = g_g2b + (size_t)n * KST;
    row[k]       = h;
    row[HID + k] = __float2bfloat16(x - __bfloat162float(h));
}

// zero y pad rows (rows [49,64) of each 64-row plane)
__global__ void k_pad_yb() {
    int q = blockIdx.x;                      // 0..29
    int node = blockIdx.y;
    int row = (q / 15) * 64 + NC + (q % 15);
    *(uint32_t*)&g_yb[(size_t)node * (YROWS * HID) + (size_t)row * HID + threadIdx.x * 2] = 0;
}

// zero grid2b pad rows (rows [324,352) of each 352-row plane)
__global__ void k_pad_g2b() {
    int q = blockIdx.x;                      // 0..55
    int node = blockIdx.y;
    int row = (q / 28) * PBLK + NP + (q % 28);
    *(uint32_t*)&g_grid2b[(size_t)node * (ZROWS * HID) + (size_t)row * HID + threadIdx.x * 2] = 0;
}

// ---------------------------- main stage kernels ----------------------------

__global__ void __launch_bounds__(256) k_gate(const float* __restrict__ nf,
                                              const float* __restrict__ ws,
                                              const float* __restrict__ bs) {
    gemm_tile<true, true>(nf, NC * CIN, ws, HID, bs, g_gate, HID,
                          N_NODES, HID, CIN);
}

__global__ void __launch_bounds__(256) k_y(const float* __restrict__ nf) {
    int i = blockIdx.z;
    int l = deg_of(i);
    const float* A = nf + (size_t)i * CIN;
    const float* B = g_W1G1 + (size_t)l * CIN * HID;
    if (i == 0)
        gemm_tile_ysplit<true>(A, NC * CIN, B, HID, g_b1g1, i, N_NODES, HID, CIN);
    else
        gemm_tile_ysplit<false>(A, NC * CIN, B, HID, nullptr, i, N_NODES, HID, CIN);
}

// ---------------- grid1 = silu(T @ y[n]) : bf16 MMA, trans-B, 3-stage -------
__global__ void __launch_bounds__(256, 1) k_grid1_mma() {
    extern __shared__ __align__(128) char smem[];
    const uint32_t sbase = smem_u32(smem);
    const int tid = threadIdx.x;
    const int wid = tid >> 5;
    const int lid = tid & 31;
    const int wm  = wid & 1;
    const int wn  = wid >> 1;
    const int node = blockIdx.y;
    const int m0 = blockIdx.x * BM;

    const uint32_t STAGE = BM * 64 + BK * 512;   // 24576
    const uint32_t BOFF  = BM * 64;              // 8192

    uint32_t a_addr[4][2], b_addr[4][2];
#pragma unroll
    for (int mt = 0; mt < 4; mt++)
#pragma unroll
        for (int ks = 0; ks < 2; ks++) {
            int row = wm * 64 + mt * 16 + (lid & 7) + ((lid >> 3) & 1) * 8;
            int ch  = ks * 2 + (lid >> 4);
            a_addr[mt][ks] = sbase + row * 64 + 16 * (ch ^ ((row >> 1) & 3));
        }
#pragma unroll
    for (int np = 0; np < 4; np++)
#pragma unroll
        for (int ks = 0; ks < 2; ks++) {
            int row = ks * 16 + (lid & 7) + 8 * ((lid >> 3) & 1);
            int cn  = wn * 8 + np * 2 + (lid >> 4);
            b_addr[np][ks] = sbase + BOFF + row * 512 + 16 * (cn ^ (row & 7));
        }

    uint32_t a_rel[2], b_rel[4];
    const __nv_bfloat16* a_base[2];
    const __nv_bfloat16* b_base[4];
    const __nv_bfloat16* ybn = g_yb + (size_t)node * (YROWS * HID);
#pragma unroll
    for (int i = 0; i < 2; i++) {
        int id = tid + i * 256, r = id >> 2, c = id & 3;
        a_rel[i] = sbase + r * 64 + 16 * (c ^ ((r >> 1) & 3));
        a_base[i] = g_Tb + (m0 + r) * 192 + c * 8;
    }
#pragma unroll
    for (int i = 0; i < 4; i++) {
        int id = tid + i * 256, r = id >> 5, c = id & 31;
        b_rel[i] = sbase + BOFF + r * 512 + 16 * (c ^ (r & 7));
        b_base[i] = ybn + r * HID + c * 8;
    }

    float acc[4][8][4];
#pragma unroll
    for (int mt = 0; mt < 4; mt++)
#pragma unroll
        for (int nt = 0; nt < 8; nt++)
#pragma unroll
            for (int v = 0; v < 4; v++) acc[mt][nt][v] = 0.0f;

    // prefetch stages 0,1
#pragma unroll
    for (int s = 0; s < 2; s++) {
        uint32_t so = s * STAGE;
#pragma unroll
        for (int i = 0; i < 2; i++) cp_async16(a_rel[i] + so, a_base[i] + s * 32);
        int ro = brow1(s) * HID;
#pragma unroll
        for (int i = 0; i < 4; i++) cp_async16(b_rel[i] + so, b_base[i] + ro);
        asm volatile("cp.async.commit_group;");
    }

#pragma unroll 1
    for (int kc = 0; kc < NITER1; kc++) {
        asm volatile("cp.async.wait_group 1;");
        __syncthreads();
        int pf = kc + 2;
        if (pf < NITER1) {
            uint32_t so = (pf % 3) * STAGE;
#pragma unroll
            for (int i = 0; i < 2; i++) cp_async16(a_rel[i] + so, a_base[i] + pf * 32);
            int ro = brow1(pf) * HID;
#pragma unroll
            for (int i = 0; i < 4; i++) cp_async16(b_rel[i] + so, b_base[i] + ro);
        }
        asm volatile("cp.async.commit_group;");

        const uint32_t so = (kc % 3) * STAGE;
#pragma unroll
        for (int ks = 0; ks < 2; ks++) {
            uint32_t af[4][4], bf[8][2];
#pragma unroll
            for (int mt = 0; mt < 4; mt++)
                ldsm_x4(af[mt][0], af[mt][1], af[mt][2], af[mt][3],
                        a_addr[mt][ks] + so);
#pragma unroll
            for (int np = 0; np < 4; np++)
                ldsm_x4_t(bf[2 * np][0], bf[2 * np][1], bf[2 * np + 1][0],
                          bf[2 * np + 1][1], b_addr[np][ks] + so);
#pragma unroll
            for (int mt = 0; mt < 4; mt++)
#pragma unroll
                for (int nt = 0; nt < 8; nt++)
                    mma_bf16(acc[mt][nt], af[mt], bf[nt]);
        }
    }

    // Epilogue: silu + split store rows [hi(256) | lo(256)].
    const int tq = lid >> 2;
    const int tr = lid & 3;
#pragma unroll
    for (int mt = 0; mt < 4; mt++) {
#pragma unroll
        for (int half = 0; half < 2; half++) {
            int p = m0 + wm * 64 + mt * 16 + tq + half * 8;
            if (p >= NP) continue;
            __nv_bfloat16* row = g_grid1b + ((size_t)node * NP + p) * KST;
#pragma unroll
            for (int nt = 0; nt < 8; nt++) {
                int col = wn * 64 + nt * 8 + tr * 2;
                float v0 = silu_f(acc[mt][nt][half * 2 + 0]);
                float v1 = silu_f(acc[mt][nt][half * 2 + 1]);
                __nv_bfloat16 h0 = __float2bfloat16(v0), h1 = __float2bfloat16(v1);
                uint16_t x0 = *(uint16_t*)&h0, x1 = *(uint16_t*)&h1;
                uint32_t hp = (uint32_t)x0 | ((uint32_t)x1 << 16);
                uint32_t lp = pk2(v0 - __bfloat162float(h0), v1 - __bfloat162float(h1));
                *(uint32_t*)&row[col]       = hp;
                *(uint32_t*)&row[HID + col] = lp;
            }
        }
    }
}

// ------------- grid2 = silu(grid1 @ g2): bf16 MMA, 4-stage ------------------
__global__ void __launch_bounds__(256, 1) k_grid2_mma() {
    extern __shared__ __align__(128) char smem[];
    const uint32_t sbase = smem_u32(smem);
    const int tid = threadIdx.x;
    const int wid = tid >> 5;
    const int lid = tid & 31;
    const int wm  = wid & 1;
    const int wn  = wid >> 1;
    const size_t m0 = (size_t)blockIdx.x * BM;

    const uint32_t STAGE = BM * 64 + BN * 64;    // 24576
    const uint32_t BOFF  = BM * 64;              // 8192

    uint32_t a_addr[4][2], b_addr[4][2];
#pragma unroll
    for (int mt = 0; mt < 4; mt++)
#pragma unroll
        for (int ks = 0; ks < 2; ks++) {
            int row = wm * 64 + mt * 16 + (lid & 7) + ((lid >> 3) & 1) * 8;
            int ch  = ks * 2 + (lid >> 4);
            a_addr[mt][ks] = sbase + row * 64 + 16 * (ch ^ ((row >> 1) & 3));
        }
#pragma unroll
    for (int np = 0; np < 4; np++)
#pragma unroll
        for (int ks = 0; ks < 2; ks++) {
            int row = wn * 64 + np * 16 + (lid & 7) + (lid >> 4) * 8;
            int ch  = ks * 2 + ((lid >> 3) & 1);
            b_addr[np][ks] = sbase + BOFF + row * 64 + 16 * (ch ^ ((row >> 1) & 3));
        }

    uint32_t a_rel[2], b_rel[4];
    const __nv_bfloat16* a_base[2];
    const __nv_bfloat16* b_base[4];
#pragma unroll
    for (int i = 0; i < 2; i++) {
        int id = tid + i * 256, r = id >> 2, c = id & 3;
        a_rel[i] = sbase + r * 64 + 16 * (c ^ ((r >> 1) & 3));
        a_base[i] = g_grid1b + (m0 + r) * (size_t)KST + c * 8;
    }
#pragma unroll
    for (int i = 0; i < 4; i++) {
        int id = tid + i * 256, r = id >> 2, c = id & 3;
        b_rel[i] = sbase + BOFF + r * 64 + 16 * (c ^ ((r >> 1) & 3));
        b_base[i] = g_g2b + r * (size_t)KST + c * 8;
    }

    float acc[4][8][4];
#pragma unroll
    for (int mt = 0; mt < 4; mt++)
#pragma unroll
        for (int nt = 0; nt < 8; nt++)
#pragma unroll
            for (int v = 0; v < 4; v++) acc[mt][nt][v] = 0.0f;

    // prefetch stages 0..2
#pragma unroll
    for (int s = 0; s < 3; s++) {
        uint32_t so = s * STAGE;
        int ao = aoff2(s), bo = boff2(s);
#pragma unroll
        for (int i = 0; i < 2; i++) cp_async16(a_rel[i] + so, a_base[i] + ao);
#pragma unroll
        for (int i = 0; i < 4; i++) cp_async16(b_rel[i] + so, b_base[i] + bo);
        asm volatile("cp.async.commit_group;");
    }

#pragma unroll 1
    for (int kc = 0; kc < NITER2; kc++) {
        asm volatile("cp.async.wait_group 2;");
        __syncthreads();
        int pf = kc + 3;
        if (pf < NITER2) {
            uint32_t so = (pf & 3) * STAGE;
            int ao = aoff2(pf), bo = boff2(pf);
#pragma unroll
            for (int i = 0; i < 2; i++) cp_async16(a_rel[i] + so, a_base[i] + ao);
#pragma unroll
            for (int i = 0; i < 4; i++) cp_async16(b_rel[i] + so, b_base[i] + bo);
        }
        asm volatile("cp.async.commit_group;");

        const uint32_t so = (kc & 3) * STAGE;
#pragma unroll
        for (int ks = 0; ks < 2; ks++) {
            uint32_t af[4][4], bf[8][2];
#pragma unroll
            for (int mt = 0; mt < 4; mt++)
                ldsm_x4(af[mt][0], af[mt][1], af[mt][2], af[mt][3],
                        a_addr[mt][ks] + so);
#pragma unroll
            for (int np = 0; np < 4; np++)
                ldsm_x4(bf[2 * np][0], bf[2 * np][1], bf[2 * np + 1][0],
                        bf[2 * np + 1][1], b_addr[np][ks] + so);
#pragma unroll
            for (int mt = 0; mt < 4; mt++)
#pragma unroll
                for (int nt = 0; nt < 8; nt++)
                    mma_bf16(acc[mt][nt], af[mt], bf[nt]);
        }
    }

    // Epilogue: silu + split store into g_grid2b planes [hi(p) | lo(352+p)].
    const int tq = lid >> 2;
    const int tr = lid & 3;
#pragma unroll
    for (int mt = 0; mt < 4; mt++) {
#pragma unroll
        for (int half = 0; half < 2; half++) {
            size_t r = m0 + wm * 64 + mt * 16 + tq + half * 8;
            uint32_t n = (uint32_t)(r / NP);
            uint32_t p = (uint32_t)(r - (size_t)n * NP);
            __nv_bfloat16* row = g_grid2b + ((size_t)n * ZROWS + p) * HID;
#pragma unroll
            for (int nt = 0; nt < 8; nt++) {
                int col = wn * 64 + nt * 8 + tr * 2;
                float v0 = silu_f(acc[mt][nt][half * 2 + 0]);
                float v1 = silu_f(acc[mt][nt][half * 2 + 1]);
                __nv_bfloat16 h0 = __float2bfloat16(v0), h1 = __float2bfloat16(v1);
                uint16_t x0 = *(uint16_t*)&h0, x1 = *(uint16_t*)&h1;
                uint32_t hp = (uint32_t)x0 | ((uint32_t)x1 << 16);
                uint32_t lp = pk2(v0 - __bfloat162float(h0), v1 - __bfloat162float(h1));
                *(uint32_t*)&row[col]              = hp;
                *(uint32_t*)&row[PBLK * HID + col] = lp;
            }
        }
    }
}

// ---------------- z = F^T @ grid2[n] : bf16 MMA, trans-B, 4-stage -----------
__global__ void __launch_bounds__(256, 1) k_z_mma() {
    extern __shared__ __align__(128) char smem[];
    const uint32_t sbase = smem_u32(smem);
    const int tid = threadIdx.x;
    const int wid = tid >> 5;
    const int lid = tid & 31;
    const int node = blockIdx.x;

    const uint32_t STAGE = 64 * 64 + BK * 512;   // 20480
    const uint32_t BOFF  = 64 * 64;              // 4096

    uint32_t a_addr[4][2], b_addr[2][2];
#pragma unroll
    for (int mt = 0; mt < 4; mt++)
#pragma unroll
        for (int ks = 0; ks < 2; ks++) {
            int row = mt * 16 + (lid & 7) + ((lid >> 3) & 1) * 8;
            int ch  = ks * 2 + (lid >> 4);
            a_addr[mt][ks] = sbase + row * 64 + 16 * (ch ^ ((row >> 1) & 3));
        }
#pragma unroll
    for (int np = 0; np < 2; np++)
#pragma unroll
        for (int ks = 0; ks < 2; ks++) {
            int row = ks * 16 + (lid & 7) + 8 * ((lid >> 3) & 1);
            int cn  = wid * 4 + np * 2 + (lid >> 4);
            b_addr[np][ks] = sbase + BOFF + row * 512 + 16 * (cn ^ (row & 7));
        }

    uint32_t a_rel, b_rel[4];
    const __nv_bfloat16* a_basep;
    const __nv_bfloat16* b_base[4];
    const __nv_bfloat16* g2bn = g_grid2b + (size_t)node * (ZROWS * HID);
    {
        int r = tid >> 2, c = tid & 3;
        a_rel = sbase + r * 64 + 16 * (c ^ ((r >> 1) & 3));
        a_basep = g_FTb + r * ZROWS + c * 8;
    }
#pragma unroll
    for (int i = 0; i < 4; i++) {
        int id = tid + i * 256, r = id >> 5, c = id & 31;
        b_rel[i] = sbase + BOFF + r * 512 + 16 * (c ^ (r & 7));
        b_base[i] = g2bn + r * HID + c * 8;
    }

    float acc[4][4][4];
#pragma unroll
    for (int mt = 0; mt < 4; mt++)
#pragma unroll
        for (int nt = 0; nt < 4; nt++)
#pragma unroll
            for (int v = 0; v < 4; v++) acc[mt][nt][v] = 0.0f;

#pragma unroll
    for (int s = 0; s < 3; s++) {
        uint32_t so = s * STAGE;
        cp_async16(a_rel + so, a_basep + aoffz(s));
        int ro = browz(s) * HID;
#pragma unroll
        for (int i = 0; i < 4; i++) cp_async16(b_rel[i] + so, b_base[i] + ro);
        asm volatile("cp.async.commit_group;");
    }

#pragma unroll 1
    for (int kc = 0; kc < NITERZ; kc++) {
        asm volatile("cp.async.wait_group 2;");
        __syncthreads();
        int pf = kc + 3;
        if (pf < NITERZ) {
            uint32_t so = (pf & 3) * STAGE;
            cp_async16(a_rel + so, a_basep + aoffz(pf));
            int ro = browz(pf) * HID;
#pragma unroll
            for (int i = 0; i < 4; i++) cp_async16(b_rel[i] + so, b_base[i] + ro);
        }
        asm volatile("cp.async.commit_group;");

        const uint32_t so = (kc & 3) * STAGE;
#pragma unroll
        for (int ks = 0; ks < 2; ks++) {
            uint32_t af[4][4], bf[4][2];
#pragma unroll
            for (int mt = 0; mt < 4; mt++)
                ldsm_x4(af[mt][0], af[mt][1], af[mt][2], af[mt][3],
                        a_addr[mt][ks] + so);
#pragma unroll
            for (int np = 0; np < 2; np++)
                ldsm_x4_t(bf[2 * np][0], bf[2 * np][1], bf[2 * np + 1][0],
                          bf[2 * np + 1][1], b_addr[np][ks] + so);
#pragma unroll
            for (int mt = 0; mt < 4; mt++)
#pragma unroll
                for (int nt = 0; nt < 4; nt++)
                    mma_bf16(acc[mt][nt], af[mt], bf[nt]);
        }
    }

    // Epilogue: fp32 store z[n][i][h], i < 49.
    const int tq = lid >> 2;
    const int tr = lid & 3;
#pragma unroll
    for (int mt = 0; mt < 4; mt++) {
#pragma unroll
        for (int half = 0; half < 2; half++) {
            int i = mt * 16 + tq + half * 8;
            if (i >= NC) continue;
            float* row = g_z + ((size_t)node * NC + i) * HID;
#pragma unroll
            for (int nt = 0; nt < 4; nt++) {
                int col = wid * 32 + nt * 8 + tr * 2;
                float2 v;
                v.x = acc[mt][nt][half * 2 + 0];
                v.y = acc[mt][nt][half * 2 + 1];
                *(float2*)&row[col] = v;
            }
        }
    }
}

__global__ void __launch_bounds__(256) k_out(const float* __restrict__ w2,
                                             const float* __restrict__ b2,
                                             float* __restrict__ out) {
    int i = blockIdx.z;
    if (i == 0) {
        gemm_tile<false, true>(g_gate, HID, w2, CIN, b2,
                               out, NC * CIN, N_NODES, CIN, HID);
    } else {
        int l = deg_of(i);
        gemm_tile<false, false>(g_z + (size_t)i * HID, NC * HID,
                                g_G3W2 + (size_t)l * HID * CIN, CIN, nullptr,
                                out + (size_t)i * CIN, NC * CIN,
                                N_NODES, CIN, HID);
    }
}

// ---------------------------------------------------------------------------

extern "C" void kernel_launch(void* const* d_in, const int* in_sizes, int n_in,
                              void* d_out, int out_size) {
    const float* nf = (const float*)d_in[0];
    const float* w1 = (const float*)d_in[1];
    const float* b1 = (const float*)d_in[2];
    const float* w2 = (const float*)d_in[3];
    const float* b2 = (const float*)d_in[4];
    const float* ws = (const float*)d_in[5];
    const float* bs = (const float*)d_in[6];
    const float* g1 = (const float*)d_in[7];
    const float* g2 = (const float*)d_in[8];
    const float* g3 = (const float*)d_in[9];
    const float* Tg = (const float*)d_in[10];
    const float* Fg = (const float*)d_in[11];
    float* out = (float*)d_out;

    const int SMEM1 = 3 * (BM * 64 + BK * 512);   // 73728
    const int SMEM2 = 4 * (BM * 64 + BN * 64);    // 98304
    const int SMEMZ = 4 * (64 * 64 + BK * 512);   // 81920
    cudaFuncSetAttribute(k_grid1_mma, cudaFuncAttributeMaxDynamicSharedMemorySize, SMEM1);
    cudaFuncSetAttribute(k_grid2_mma, cudaFuncAttributeMaxDynamicSharedMemorySize, SMEM2);
    cudaFuncSetAttribute(k_z_mma,     cudaFuncAttributeMaxDynamicSharedMemorySize, SMEMZ);

    // prologs
    k_w1g1<<<dim3(HID / 64, CIN / 64, NL), 256>>>(w1, g1);
    k_g3w2<<<dim3(CIN / 64, HID / 64, NL), 256>>>(g3, w2);
    k_b1g1<<<1, HID>>>(b1, g1);
    k_prepT<<<384, 192>>>(Tg);
    k_prepFT<<<dim3(64, 2), PBLK>>>(Fg);
    k_prepg2<<<HID, HID>>>(g2);
    k_pad_yb<<<dim3(30, N_NODES), 128>>>();
    k_pad_g2b<<<dim3(56, N_NODES), 128>>>();

    // scalar gating branch
    k_gate<<<dim3(HID / 64, N_NODES / 64), 256>>>(nf, ws, bs);

    // main pipeline
    k_y<<<dim3(HID / 64, N_NODES / 64, NC), 256>>>(nf);
    k_grid1_mma<<<dim3(3, N_NODES), 256, SMEM1>>>();
    k_grid2_mma<<<(int)(MROWS / BM), 256, SMEM2>>>();
    k_z_mma<<<N_NODES, 256, SMEMZ>>>();
    k_out<<<dim3(CIN / 64, N_NODES / 64, NC), 256>>>(w2, b2, out);
}

// round 6
// speedup vs baseline: 3.0607x; 1.2129x over previous
#include <cuda_runtime.h>
#include <cuda_fp16.h>
#include <cstdint>

// ---------------------------------------------------------------------------
// FeedForwardNetwork (SO(3) equivariant FFN), sm_103a — HMMA mma.sync fp16
//
//   y      = blockdiag_l(nf @ (w1[l] @ g1)) ; y[:,0,:] += b1 @ g1
//            -> fp16 hi plane [n][64][256] (rows 49..63 zero)
//   grid1  = silu(T @ y)  per node  (A = split T [384x128] = [hi|lo],
//            B = y hi re-read twice)  -> fp16 hi rows [m][256]
//   grid2  = silu(grid1 @ g2)  (A = grid1 hi re-read twice,
//            B = g2^T [256x512] = [hi|lo])  -> fp16 hi [n][352][256] (pads 0)
//   z      = F^T @ grid2  per node (A = split F^T [64x704] = [hi|lo],
//            B = grid2 hi re-read twice) -> fp32
//   out[:,i>=1,:] = z[:,i,:] @ (g3 @ w2[l(i)])
//   out[:,0,:]    = silu(nf[:,0,:] @ ws + bs) @ w2[0] + b2
//
// fp16 2-term split: static matrix = hi+lo (eps 2^-11 each); activation kept
// as fp16 hi only. Each GEMM = sum a_hi*(b_hi+b_lo); dropped activation
// residual ~1e-4 relative per GEMM (sqrt-K cancellation), ~3e-4 chained.
// ---------------------------------------------------------------------------

#define N_NODES 1024
#define NC      49
#define CIN     128
#define HID     256
#define RES     18
#define NP      (RES*RES)   // 324
#define NL      7
#define MROWS   ((size_t)N_NODES * NP)   // 331776
#define PBLK    352          // padded grid-point block
#define BM      128
#define BN      256
#define BK      32
#define NITER1  4            // grid1 K chunks (2*64/32)
#define NITER2  16           // grid2 K chunks (2*256/32)
#define NITERZ  22           // z K chunks (2*352/32)

// -------- scratch (static device globals; no runtime allocation) -----------
__device__ float g_W1G1[NL * CIN * HID];
__device__ float g_G3W2[NL * HID * CIN];
__device__ float g_b1g1[HID];
__device__ __half g_Tb[384 * 128];                  // to_grid [hi|lo]
__device__ __half g_FTb[64 * 704];                  // from_grid^T [hi|lo]
__device__ __half g_g2b[HID * 512];                 // g2^T [hi|lo]
__device__ __half g_yb[(size_t)N_NODES * 64 * HID];        // 34 MB (hi)
__device__ __half g_grid1b[MROWS * HID];                   // 170 MB (hi)
__device__ __half g_grid2b[(size_t)N_NODES * PBLK * HID];  // 185 MB (hi)
__device__ float g_z[(size_t)N_NODES * NC * HID];          // 51 MB
__device__ float g_gate[(size_t)N_NODES * HID];

__device__ __forceinline__ float silu_f(float x) {
    return x / (1.0f + __expf(-x));
}
__device__ __forceinline__ int deg_of(int i) {
    int l = 0;
    while ((l + 1) * (l + 1) <= i) ++l;
    return l;
}
__device__ __forceinline__ uint32_t smem_u32(const void* p) {
    uint32_t a;
    asm("{ .reg .u64 t; cvta.to.shared.u64 t, %1; cvt.u32.u64 %0, t; }"
        : "=r"(a) : "l"(p));
    return a;
}
__device__ __forceinline__ void cp_async16(uint32_t dst, const void* src) {
    asm volatile("cp.async.cg.shared.global [%0], [%1], 16;" :: "r"(dst), "l"(src));
}
__device__ __forceinline__ void ldsm_x4(uint32_t& r0, uint32_t& r1,
                                        uint32_t& r2, uint32_t& r3, uint32_t addr) {
    asm volatile("ldmatrix.sync.aligned.m8n8.x4.shared.b16 {%0,%1,%2,%3}, [%4];"
                 : "=r"(r0), "=r"(r1), "=r"(r2), "=r"(r3) : "r"(addr));
}
__device__ __forceinline__ void ldsm_x4_t(uint32_t& r0, uint32_t& r1,
                                          uint32_t& r2, uint32_t& r3, uint32_t addr) {
    asm volatile("ldmatrix.sync.aligned.m8n8.x4.trans.shared.b16 {%0,%1,%2,%3}, [%4];"
                 : "=r"(r0), "=r"(r1), "=r"(r2), "=r"(r3) : "r"(addr));
}
__device__ __forceinline__ void mma_f16(float* d, const uint32_t* a, const uint32_t* b) {
    asm volatile(
        "mma.sync.aligned.m16n8k16.row.col.f32.f16.f16.f32 "
        "{%0,%1,%2,%3}, {%4,%5,%6,%7}, {%8,%9}, {%0,%1,%2,%3};"
        : "+f"(d[0]), "+f"(d[1]), "+f"(d[2]), "+f"(d[3])
        : "r"(a[0]), "r"(a[1]), "r"(a[2]), "r"(a[3]), "r"(b[0]), "r"(b[1]));
}
__device__ __forceinline__ uint32_t pkh2(float x, float y) {
    __half hx = __float2half_rn(x), hy = __float2half_rn(y);
    uint16_t bx = *(uint16_t*)&hx, by = *(uint16_t*)&hy;
    return (uint32_t)bx | ((uint32_t)by << 16);
}

// K-chunk source maps (activation hi planes are re-read for the lo term).
__device__ __forceinline__ int brow1(int kc) { return (kc & 1) * 32; }        // y rows
__device__ __forceinline__ int aoff2(int kc) { return (kc & 7) * 32; }        // grid1b cols
__device__ __forceinline__ int browz(int kc) { return (kc < 11 ? kc : kc - 11) * 32; } // grid2b rows

// ---------------------------------------------------------------------------
// Generic 64x64x16 SIMT tiled GEMM (small stages).
// ---------------------------------------------------------------------------
template<bool DO_SILU, bool HAS_BIAS>
__device__ __forceinline__ void gemm_tile(
    const float* __restrict__ A, int lda,
    const float* __restrict__ B, int ldb,
    const float* __restrict__ bias,
    float* __restrict__ C, int ldc,
    int M, int N, int K)
{
    __shared__ float As[16][64];
    __shared__ float Bs[16][64];

    const int tid = threadIdx.x;
    const int tx  = tid & 15;
    const int ty  = tid >> 4;
    const int m0  = blockIdx.y * 64;
    const int n0  = blockIdx.x * 64;

    float acc[4][4];
#pragma unroll
    for (int i = 0; i < 4; i++)
#pragma unroll
        for (int j = 0; j < 4; j++) acc[i][j] = 0.0f;

    for (int k0 = 0; k0 < K; k0 += 16) {
#pragma unroll
        for (int e = tid; e < 64 * 16; e += 256) {
            int m = e >> 4, k = e & 15;
            int gm = m0 + m, gk = k0 + k;
            As[k][m] = (gm < M && gk < K) ? A[(size_t)gm * lda + gk] : 0.0f;
        }
#pragma unroll
        for (int e = tid; e < 16 * 64; e += 256) {
            int k = e >> 6, n = e & 63;
            int gk = k0 + k, gn = n0 + n;
            Bs[k][n] = (gk < K && gn < N) ? B[(size_t)gk * ldb + gn] : 0.0f;
        }
        __syncthreads();

#pragma unroll
        for (int k = 0; k < 16; k++) {
            float4 av = *(const float4*)&As[k][ty * 4];
            float4 bv = *(const float4*)&Bs[k][tx * 4];
            float a4[4] = {av.x, av.y, av.z, av.w};
            float b4[4] = {bv.x, bv.y, bv.z, bv.w};
#pragma unroll
            for (int i = 0; i < 4; i++)
#pragma unroll
                for (int j = 0; j < 4; j++)
                    acc[i][j] += a4[i] * b4[j];
        }
        __syncthreads();
    }

#pragma unroll
    for (int i = 0; i < 4; i++) {
        int gm = m0 + ty * 4 + i;
        if (gm >= M) continue;
#pragma unroll
        for (int j = 0; j < 4; j++) {
            int gn = n0 + tx * 4 + j;
            if (gn >= N) continue;
            float v = acc[i][j];
            if (HAS_BIAS) v += bias[gn];
            if (DO_SILU)  v = silu_f(v);
            C[(size_t)gm * ldc + gn] = v;
        }
    }
}

// k_y body: SIMT gemm, epilogue writes fp16 hi plane into g_yb.
template<bool HAS_BIAS>
__device__ __forceinline__ void gemm_tile_yh(
    const float* __restrict__ A, int lda,
    const float* __restrict__ B, int ldb,
    const float* __restrict__ bias,
    int ci, int M, int N, int K)
{
    __shared__ float As[16][64];
    __shared__ float Bs[16][64];

    const int tid = threadIdx.x;
    const int tx  = tid & 15;
    const int ty  = tid >> 4;
    const int m0  = blockIdx.y * 64;
    const int n0  = blockIdx.x * 64;

    float acc[4][4];
#pragma unroll
    for (int i = 0; i < 4; i++)
#pragma unroll
        for (int j = 0; j < 4; j++) acc[i][j] = 0.0f;

    for (int k0 = 0; k0 < K; k0 += 16) {
#pragma unroll
        for (int e = tid; e < 64 * 16; e += 256) {
            int m = e >> 4, k = e & 15;
            As[k][m] = A[(size_t)(m0 + m) * lda + k0 + k];
        }
#pragma unroll
        for (int e = tid; e < 16 * 64; e += 256) {
            int k = e >> 6, n = e & 63;
            Bs[k][n] = B[(size_t)(k0 + k) * ldb + n0 + n];
        }
        __syncthreads();

#pragma unroll
        for (int k = 0; k < 16; k++) {
            float4 av = *(const float4*)&As[k][ty * 4];
            float4 bv = *(const float4*)&Bs[k][tx * 4];
            float a4[4] = {av.x, av.y, av.z, av.w};
            float b4[4] = {bv.x, bv.y, bv.z, bv.w};
#pragma unroll
            for (int i = 0; i < 4; i++)
#pragma unroll
                for (int j = 0; j < 4; j++)
                    acc[i][j] += a4[i] * b4[j];
        }
        __syncthreads();
    }

#pragma unroll
    for (int i = 0; i < 4; i++) {
        int gm = m0 + ty * 4 + i;   // node index
        __half* yb = g_yb + (size_t)gm * (64 * HID);
#pragma unroll
        for (int jp = 0; jp < 4; jp += 2) {
            int gn = n0 + tx * 4 + jp;
            float v0 = acc[i][jp], v1 = acc[i][jp + 1];
            if (HAS_BIAS) { v0 += bias[gn]; v1 += bias[gn + 1]; }
            *(uint32_t*)&yb[(size_t)ci * HID + gn] = pkh2(v0, v1);
        }
    }
}

// ---------------------------- prolog kernels --------------------------------

__global__ void __launch_bounds__(256) k_w1g1(const float* __restrict__ w1,
                                              const float* __restrict__ g1) {
    int l = blockIdx.z;
    gemm_tile<false, false>(w1 + (size_t)l * CIN * HID, HID, g1, HID, nullptr,
                            g_W1G1 + (size_t)l * CIN * HID, HID, CIN, HID, HID);
}

__global__ void __launch_bounds__(256) k_g3w2(const float* __restrict__ g3,
                                              const float* __restrict__ w2) {
    int l = blockIdx.z;
    gemm_tile<false, false>(g3, HID, w2 + (size_t)l * HID * CIN, CIN, nullptr,
                            g_G3W2 + (size_t)l * HID * CIN, CIN, HID, CIN, HID);
}

__global__ void k_b1g1(const float* __restrict__ b1, const float* __restrict__ g1) {
    int k = threadIdx.x;
    float s = 0.0f;
    for (int h = 0; h < HID; h++) s += b1[h] * g1[(size_t)h * HID + k];
    g_b1g1[k] = s;
}

// g_Tb [384 x 128]: cols [0,64)=hi(T[p][i]), [64,128)=lo; pads 0.
__global__ void k_prepT(const float* __restrict__ T) {
    int p = blockIdx.x;          // 0..383
    int c = threadIdx.x;         // 0..127
    int reg = c >> 6, i = c & 63;
    float v = (p < NP && i < NC) ? T[p * NC + i] : 0.0f;
    __half h = __float2half_rn(v);
    __half o = reg ? __float2half_rn(v - __half2float(h)) : h;
    g_Tb[p * 128 + c] = o;
}

// g_FTb [64 x 704]: cols [0,352)=hi(F[p][i]), [352,704)=lo; pads 0.
__global__ void k_prepFT(const float* __restrict__ F) {
    int i = blockIdx.x;          // 0..63
    int reg = blockIdx.y;        // 0..1
    int p = threadIdx.x;         // 0..351
    float v = (i < NC && p < NP) ? F[p * NC + i] : 0.0f;
    __half h = __float2half_rn(v);
    __half o = reg ? __float2half_rn(v - __half2float(h)) : h;
    g_FTb[i * 704 + reg * PBLK + p] = o;
}

// g_g2b [256 x 512] rows n: [hi(g2[k][n]) | lo]
__global__ void k_prepg2(const float* __restrict__ g2) {
    int k = blockIdx.x;
    int n = threadIdx.x;
    float x = g2[(size_t)k * HID + n];
    __half h = __float2half_rn(x);
    __half* row = g_g2b + (size_t)n * 512;
    row[k]       = h;
    row[HID + k] = __float2half_rn(x - __half2float(h));
}

// zero y pad rows (rows [49,64))
__global__ void k_pad_yb() {
    int q = blockIdx.x;                      // 0..14
    int node = blockIdx.y;
    int row = NC + q;
    *(uint32_t*)&g_yb[(size_t)node * (64 * HID) + (size_t)row * HID + threadIdx.x * 2] = 0;
}

// zero grid2b pad rows (rows [324,352))
__global__ void k_pad_g2b() {
    int q = blockIdx.x;                      // 0..27
    int node = blockIdx.y;
    int row = NP + q;
    *(uint32_t*)&g_grid2b[(size_t)node * (PBLK * HID) + (size_t)row * HID + threadIdx.x * 2] = 0;
}

// ---------------------------- main stage kernels ----------------------------

__global__ void __launch_bounds__(256) k_gate(const float* __restrict__ nf,
                                              const float* __restrict__ ws,
                                              const float* __restrict__ bs) {
    gemm_tile<true, true>(nf, NC * CIN, ws, HID, bs, g_gate, HID,
                          N_NODES, HID, CIN);
}

__global__ void __launch_bounds__(256) k_y(const float* __restrict__ nf) {
    int i = blockIdx.z;
    int l = deg_of(i);
    const float* A = nf + (size_t)i * CIN;
    const float* B = g_W1G1 + (size_t)l * CIN * HID;
    if (i == 0)
        gemm_tile_yh<true>(A, NC * CIN, B, HID, g_b1g1, i, N_NODES, HID, CIN);
    else
        gemm_tile_yh<false>(A, NC * CIN, B, HID, nullptr, i, N_NODES, HID, CIN);
}

// ---------------- grid1 = silu(T @ y[n]) : fp16 MMA, trans-B, 3-stage -------
__global__ void __launch_bounds__(256, 1) k_grid1_mma() {
    extern __shared__ __align__(128) char smem[];
    const uint32_t sbase = smem_u32(smem);
    const int tid = threadIdx.x;
    const int wid = tid >> 5;
    const int lid = tid & 31;
    const int wm  = wid & 1;
    const int wn  = wid >> 1;
    const int node = blockIdx.y;
    const int m0 = blockIdx.x * BM;

    const uint32_t STAGE = BM * 64 + BK * 512;   // 24576
    const uint32_t BOFF  = BM * 64;              // 8192

    uint32_t a_addr[4][2], b_addr[4][2];
#pragma unroll
    for (int mt = 0; mt < 4; mt++)
#pragma unroll
        for (int ks = 0; ks < 2; ks++) {
            int row = wm * 64 + mt * 16 + (lid & 7) + ((lid >> 3) & 1) * 8;
            int ch  = ks * 2 + (lid >> 4);
            a_addr[mt][ks] = sbase + row * 64 + 16 * (ch ^ ((row >> 1) & 3));
        }
#pragma unroll
    for (int np = 0; np < 4; np++)
#pragma unroll
        for (int ks = 0; ks < 2; ks++) {
            int row = ks * 16 + (lid & 7) + 8 * ((lid >> 3) & 1);
            int cn  = wn * 8 + np * 2 + (lid >> 4);
            b_addr[np][ks] = sbase + BOFF + row * 512 + 16 * (cn ^ (row & 7));
        }

    uint32_t a_rel[2], b_rel[4];
    const __half* a_base[2];
    const __half* b_base[4];
    const __half* ybn = g_yb + (size_t)node * (64 * HID);
#pragma unroll
    for (int i = 0; i < 2; i++) {
        int id = tid + i * 256, r = id >> 2, c = id & 3;
        a_rel[i] = sbase + r * 64 + 16 * (c ^ ((r >> 1) & 3));
        a_base[i] = g_Tb + (m0 + r) * 128 + c * 8;
    }
#pragma unroll
    for (int i = 0; i < 4; i++) {
        int id = tid + i * 256, r = id >> 5, c = id & 31;
        b_rel[i] = sbase + BOFF + r * 512 + 16 * (c ^ (r & 7));
        b_base[i] = ybn + r * HID + c * 8;
    }

    float acc[4][8][4];
#pragma unroll
    for (int mt = 0; mt < 4; mt++)
#pragma unroll
        for (int nt = 0; nt < 8; nt++)
#pragma unroll
            for (int v = 0; v < 4; v++) acc[mt][nt][v] = 0.0f;

#pragma unroll
    for (int s = 0; s < 2; s++) {
        uint32_t so = s * STAGE;
#pragma unroll
        for (int i = 0; i < 2; i++) cp_async16(a_rel[i] + so, a_base[i] + s * 32);
        int ro = brow1(s) * HID;
#pragma unroll
        for (int i = 0; i < 4; i++) cp_async16(b_rel[i] + so, b_base[i] + ro);
        asm volatile("cp.async.commit_group;");
    }

#pragma unroll 1
    for (int kc = 0; kc < NITER1; kc++) {
        asm volatile("cp.async.wait_group 1;");
        __syncthreads();
        int pf = kc + 2;
        if (pf < NITER1) {
            uint32_t so = (pf % 3) * STAGE;
#pragma unroll
            for (int i = 0; i < 2; i++) cp_async16(a_rel[i] + so, a_base[i] + pf * 32);
            int ro = brow1(pf) * HID;
#pragma unroll
            for (int i = 0; i < 4; i++) cp_async16(b_rel[i] + so, b_base[i] + ro);
        }
        asm volatile("cp.async.commit_group;");

        const uint32_t so = (kc % 3) * STAGE;
#pragma unroll
        for (int ks = 0; ks < 2; ks++) {
            uint32_t af[4][4], bf[8][2];
#pragma unroll
            for (int mt = 0; mt < 4; mt++)
                ldsm_x4(af[mt][0], af[mt][1], af[mt][2], af[mt][3],
                        a_addr[mt][ks] + so);
#pragma unroll
            for (int np = 0; np < 4; np++)
                ldsm_x4_t(bf[2 * np][0], bf[2 * np][1], bf[2 * np + 1][0],
                          bf[2 * np + 1][1], b_addr[np][ks] + so);
#pragma unroll
            for (int mt = 0; mt < 4; mt++)
#pragma unroll
                for (int nt = 0; nt < 8; nt++)
                    mma_f16(acc[mt][nt], af[mt], bf[nt]);
        }
    }

    // Epilogue: silu -> fp16 hi store.
    const int tq = lid >> 2;
    const int tr = lid & 3;
#pragma unroll
    for (int mt = 0; mt < 4; mt++) {
#pragma unroll
        for (int half = 0; half < 2; half++) {
            int p = m0 + wm * 64 + mt * 16 + tq + half * 8;
            if (p >= NP) continue;
            __half* row = g_grid1b + ((size_t)node * NP + p) * HID;
#pragma unroll
            for (int nt = 0; nt < 8; nt++) {
                int col = wn * 64 + nt * 8 + tr * 2;
                *(uint32_t*)&row[col] = pkh2(silu_f(acc[mt][nt][half * 2 + 0]),
                                             silu_f(acc[mt][nt][half * 2 + 1]));
            }
        }
    }
}

// ------------- grid2 = silu(grid1 @ g2): fp16 MMA, 4-stage ------------------
__global__ void __launch_bounds__(256, 1) k_grid2_mma() {
    extern __shared__ __align__(128) char smem[];
    const uint32_t sbase = smem_u32(smem);
    const int tid = threadIdx.x;
    const int wid = tid >> 5;
    const int lid = tid & 31;
    const int wm  = wid & 1;
    const int wn  = wid >> 1;
    const size_t m0 = (size_t)blockIdx.x * BM;

    const uint32_t STAGE = BM * 64 + BN * 64;    // 24576
    const uint32_t BOFF  = BM * 64;              // 8192

    uint32_t a_addr[4][2], b_addr[4][2];
#pragma unroll
    for (int mt = 0; mt < 4; mt++)
#pragma unroll
        for (int ks = 0; ks < 2; ks++) {
            int row = wm * 64 + mt * 16 + (lid & 7) + ((lid >> 3) & 1) * 8;
            int ch  = ks * 2 + (lid >> 4);
            a_addr[mt][ks] = sbase + row * 64 + 16 * (ch ^ ((row >> 1) & 3));
        }
#pragma unroll
    for (int np = 0; np < 4; np++)
#pragma unroll
        for (int ks = 0; ks < 2; ks++) {
            int row = wn * 64 + np * 16 + (lid & 7) + (lid >> 4) * 8;
            int ch  = ks * 2 + ((lid >> 3) & 1);
            b_addr[np][ks] = sbase + BOFF + row * 64 + 16 * (ch ^ ((row >> 1) & 3));
        }

    uint32_t a_rel[2], b_rel[4];
    const __half* a_base[2];
    const __half* b_base[4];
#pragma unroll
    for (int i = 0; i < 2; i++) {
        int id = tid + i * 256, r = id >> 2, c = id & 3;
        a_rel[i] = sbase + r * 64 + 16 * (c ^ ((r >> 1) & 3));
        a_base[i] = g_grid1b + (m0 + r) * (size_t)HID + c * 8;
    }
#pragma unroll
    for (int i = 0; i < 4; i++) {
        int id = tid + i * 256, r = id >> 2, c = id & 3;
        b_rel[i] = sbase + BOFF + r * 64 + 16 * (c ^ ((r >> 1) & 3));
        b_base[i] = g_g2b + r * (size_t)512 + c * 8;
    }

    float acc[4][8][4];
#pragma unroll
    for (int mt = 0; mt < 4; mt++)
#pragma unroll
        for (int nt = 0; nt < 8; nt++)
#pragma unroll
            for (int v = 0; v < 4; v++) acc[mt][nt][v] = 0.0f;

#pragma unroll
    for (int s = 0; s < 3; s++) {
        uint32_t so = s * STAGE;
        int ao = aoff2(s), bo = s * 32;
#pragma unroll
        for (int i = 0; i < 2; i++) cp_async16(a_rel[i] + so, a_base[i] + ao);
#pragma unroll
        for (int i = 0; i < 4; i++) cp_async16(b_rel[i] + so, b_base[i] + bo);
        asm volatile("cp.async.commit_group;");
    }

#pragma unroll 1
    for (int kc = 0; kc < NITER2; kc++) {
        asm volatile("cp.async.wait_group 2;");
        __syncthreads();
        int pf = kc + 3;
        if (pf < NITER2) {
            uint32_t so = (pf & 3) * STAGE;
            int ao = aoff2(pf), bo = pf * 32;
#pragma unroll
            for (int i = 0; i < 2; i++) cp_async16(a_rel[i] + so, a_base[i] + ao);
#pragma unroll
            for (int i = 0; i < 4; i++) cp_async16(b_rel[i] + so, b_base[i] + bo);
        }
        asm volatile("cp.async.commit_group;");

        const uint32_t so = (kc & 3) * STAGE;
#pragma unroll
        for (int ks = 0; ks < 2; ks++) {
            uint32_t af[4][4], bf[8][2];
#pragma unroll
            for (int mt = 0; mt < 4; mt++)
                ldsm_x4(af[mt][0], af[mt][1], af[mt][2], af[mt][3],
                        a_addr[mt][ks] + so);
#pragma unroll
            for (int np = 0; np < 4; np++)
                ldsm_x4(bf[2 * np][0], bf[2 * np][1], bf[2 * np + 1][0],
                        bf[2 * np + 1][1], b_addr[np][ks] + so);
#pragma unroll
            for (int mt = 0; mt < 4; mt++)
#pragma unroll
                for (int nt = 0; nt < 8; nt++)
                    mma_f16(acc[mt][nt], af[mt], bf[nt]);
        }
    }

    // Epilogue: silu -> fp16 hi store into g_grid2b [n][p][h].
    const int tq = lid >> 2;
    const int tr = lid & 3;
#pragma unroll
    for (int mt = 0; mt < 4; mt++) {
#pragma unroll
        for (int half = 0; half < 2; half++) {
            size_t r = m0 + wm * 64 + mt * 16 + tq + half * 8;
            uint32_t n = (uint32_t)(r / NP);
            uint32_t p = (uint32_t)(r - (size_t)n * NP);
            __half* row = g_grid2b + ((size_t)n * PBLK + p) * HID;
#pragma unroll
            for (int nt = 0; nt < 8; nt++) {
                int col = wn * 64 + nt * 8 + tr * 2;
                *(uint32_t*)&row[col] = pkh2(silu_f(acc[mt][nt][half * 2 + 0]),
                                             silu_f(acc[mt][nt][half * 2 + 1]));
            }
        }
    }
}

// ---------------- z = F^T @ grid2[n] : fp16 MMA, trans-B, 4-stage -----------
__global__ void __launch_bounds__(256, 1) k_z_mma() {
    extern __shared__ __align__(128) char smem[];
    const uint32_t sbase = smem_u32(smem);
    const int tid = threadIdx.x;
    const int wid = tid >> 5;
    const int lid = tid & 31;
    const int node = blockIdx.x;

    const uint32_t STAGE = 64 * 64 + BK * 512;   // 20480
    const uint32_t BOFF  = 64 * 64;              // 4096

    uint32_t a_addr[4][2], b_addr[2][2];
#pragma unroll
    for (int mt = 0; mt < 4; mt++)
#pragma unroll
        for (int ks = 0; ks < 2; ks++) {
            int row = mt * 16 + (lid & 7) + ((lid >> 3) & 1) * 8;
            int ch  = ks * 2 + (lid >> 4);
            a_addr[mt][ks] = sbase + row * 64 + 16 * (ch ^ ((row >> 1) & 3));
        }
#pragma unroll
    for (int np = 0; np < 2; np++)
#pragma unroll
        for (int ks = 0; ks < 2; ks++) {
            int row = ks * 16 + (lid & 7) + 8 * ((lid >> 3) & 1);
            int cn  = wid * 4 + np * 2 + (lid >> 4);
            b_addr[np][ks] = sbase + BOFF + row * 512 + 16 * (cn ^ (row & 7));
        }

    uint32_t a_rel, b_rel[4];
    const __half* a_basep;
    const __half* b_base[4];
    const __half* g2bn = g_grid2b + (size_t)node * (PBLK * HID);
    {
        int r = tid >> 2, c = tid & 3;
        a_rel = sbase + r * 64 + 16 * (c ^ ((r >> 1) & 3));
        a_basep = g_FTb + r * 704 + c * 8;
    }
#pragma unroll
    for (int i = 0; i < 4; i++) {
        int id = tid + i * 256, r = id >> 5, c = id & 31;
        b_rel[i] = sbase + BOFF + r * 512 + 16 * (c ^ (r & 7));
        b_base[i] = g2bn + r * HID + c * 8;
    }

    float acc[4][4][4];
#pragma unroll
    for (int mt = 0; mt < 4; mt++)
#pragma unroll
        for (int nt = 0; nt < 4; nt++)
#pragma unroll
            for (int v = 0; v < 4; v++) acc[mt][nt][v] = 0.0f;

#pragma unroll
    for (int s = 0; s < 3; s++) {
        uint32_t so = s * STAGE;
        cp_async16(a_rel + so, a_basep + s * 32);
        int ro = browz(s) * HID;
#pragma unroll
        for (int i = 0; i < 4; i++) cp_async16(b_rel[i] + so, b_base[i] + ro);
        asm volatile("cp.async.commit_group;");
    }

#pragma unroll 1
    for (int kc = 0; kc < NITERZ; kc++) {
        asm volatile("cp.async.wait_group 2;");
        __syncthreads();
        int pf = kc + 3;
        if (pf < NITERZ) {
            uint32_t so = (pf & 3) * STAGE;
            cp_async16(a_rel + so, a_basep + pf * 32);
            int ro = browz(pf) * HID;
#pragma unroll
            for (int i = 0; i < 4; i++) cp_async16(b_rel[i] + so, b_base[i] + ro);
        }
        asm volatile("cp.async.commit_group;");

        const uint32_t so = (kc & 3) * STAGE;
#pragma unroll
        for (int ks = 0; ks < 2; ks++) {
            uint32_t af[4][4], bf[4][2];
#pragma unroll
            for (int mt = 0; mt < 4; mt++)
                ldsm_x4(af[mt][0], af[mt][1], af[mt][2], af[mt][3],
                        a_addr[mt][ks] + so);
#pragma unroll
            for (int np = 0; np < 2; np++)
                ldsm_x4_t(bf[2 * np][0], bf[2 * np][1], bf[2 * np + 1][0],
                          bf[2 * np + 1][1], b_addr[np][ks] + so);
#pragma unroll
            for (int mt = 0; mt < 4; mt++)
#pragma unroll
                for (int nt = 0; nt < 4; nt++)
                    mma_f16(acc[mt][nt], af[mt], bf[nt]);
        }
    }

    // Epilogue: fp32 store z[n][i][h], i < 49.
    const int tq = lid >> 2;
    const int tr = lid & 3;
#pragma unroll
    for (int mt = 0; mt < 4; mt++) {
#pragma unroll
        for (int half = 0; half < 2; half++) {
            int i = mt * 16 + tq + half * 8;
            if (i >= NC) continue;
            float* row = g_z + ((size_t)node * NC + i) * HID;
#pragma unroll
            for (int nt = 0; nt < 4; nt++) {
                int col = wid * 32 + nt * 8 + tr * 2;
                float2 v;
                v.x = acc[mt][nt][half * 2 + 0];
                v.y = acc[mt][nt][half * 2 + 1];
                *(float2*)&row[col] = v;
            }
        }
    }
}

__global__ void __launch_bounds__(256) k_out(const float* __restrict__ w2,
                                             const float* __restrict__ b2,
                                             float* __restrict__ out) {
    int i = blockIdx.z;
    if (i == 0) {
        gemm_tile<false, true>(g_gate, HID, w2, CIN, b2,
                               out, NC * CIN, N_NODES, CIN, HID);
    } else {
        int l = deg_of(i);
        gemm_tile<false, false>(g_z + (size_t)i * HID, NC * HID,
                                g_G3W2 + (size_t)l * HID * CIN, CIN, nullptr,
                                out + (size_t)i * CIN, NC * CIN,
                                N_NODES, CIN, HID);
    }
}

// ---------------------------------------------------------------------------

extern "C" void kernel_launch(void* const* d_in, const int* in_sizes, int n_in,
                              void* d_out, int out_size) {
    const float* nf = (const float*)d_in[0];
    const float* w1 = (const float*)d_in[1];
    const float* b1 = (const float*)d_in[2];
    const float* w2 = (const float*)d_in[3];
    const float* b2 = (const float*)d_in[4];
    const float* ws = (const float*)d_in[5];
    const float* bs = (const float*)d_in[6];
    const float* g1 = (const float*)d_in[7];
    const float* g2 = (const float*)d_in[8];
    const float* g3 = (const float*)d_in[9];
    const float* Tg = (const float*)d_in[10];
    const float* Fg = (const float*)d_in[11];
    float* out = (float*)d_out;

    const int SMEM1 = 3 * (BM * 64 + BK * 512);   // 73728
    const int SMEM2 = 4 * (BM * 64 + BN * 64);    // 98304
    const int SMEMZ = 4 * (64 * 64 + BK * 512);   // 81920
    cudaFuncSetAttribute(k_grid1_mma, cudaFuncAttributeMaxDynamicSharedMemorySize, SMEM1);
    cudaFuncSetAttribute(k_grid2_mma, cudaFuncAttributeMaxDynamicSharedMemorySize, SMEM2);
    cudaFuncSetAttribute(k_z_mma,     cudaFuncAttributeMaxDynamicSharedMemorySize, SMEMZ);

    // prologs
    k_w1g1<<<dim3(HID / 64, CIN / 64, NL), 256>>>(w1, g1);
    k_g3w2<<<dim3(CIN / 64, HID / 64, NL), 256>>>(g3, w2);
    k_b1g1<<<1, HID>>>(b1, g1);
    k_prepT<<<384, 128>>>(Tg);
    k_prepFT<<<dim3(64, 2), PBLK>>>(Fg);
    k_prepg2<<<HID, HID>>>(g2);
    k_pad_yb<<<dim3(15, N_NODES), 128>>>();
    k_pad_g2b<<<dim3(28, N_NODES), 128>>>();

    // scalar gating branch
    k_gate<<<dim3(HID / 64, N_NODES / 64), 256>>>(nf, ws, bs);

    // main pipeline
    k_y<<<dim3(HID / 64, N_NODES / 64, NC), 256>>>(nf);
    k_grid1_mma<<<dim3(3, N_NODES), 256, SMEM1>>>();
    k_grid2_mma<<<(int)(MROWS / BM), 256, SMEM2>>>();
    k_z_mma<<<N_NODES, 256, SMEMZ>>>();
    k_out<<<dim3(CIN / 64, N_NODES / 64, NC), 256>>>(w2, b2, out);
}

// round 7
// speedup vs baseline: 3.6134x; 1.1806x over previous
#include <cuda_runtime.h>
#include <cuda_fp16.h>
#include <cstdint>

// ---------------------------------------------------------------------------
// FeedForwardNetwork (SO(3) equivariant FFN), sm_103a — all-MMA fp16 path
//
//   nfh    = fp16(node_feats)
//   y      = nfh @ split(W1G1[l])           (MMA, per-coeff i) -> fp16 planes
//   grid1  = silu(split(T) @ y)   per node  (MMA)              -> fp16
//   grid2  = silu(grid1 @ split(g2))        (MMA)              -> fp16
//   z      = split(F^T) @ grid2   per node  (MMA)              -> fp16
//   out[:,i>=1,:] = z[:,i,:] @ split(g3 @ w2[l(i)])  (MMA)     -> fp32
//   out[:,0,:]    = silu(nf[:,0,:] @ ws + bs) @ w2[0] + b2     (SIMT, tiny)
//
// fp16 2-term split on static matrices ([hi|lo], eps 2^-11 each); activations
// fp16 hi only, re-read for the lo term via K-chunk source remapping.
// ---------------------------------------------------------------------------

#define N_NODES 1024
#define NC      49
#define CIN     128
#define HID     256
#define RES     18
#define NP      (RES*RES)   // 324
#define NL      7
#define MROWS   ((size_t)N_NODES * NP)   // 331776
#define PBLK    352
#define BM      128
#define BN      256
#define BK      32
#define NITER1  4            // grid1 K chunks (2*64/32)
#define NITER2  16           // grid2 K chunks (2*256/32)
#define NITERZ  22           // z K chunks (2*352/32)
#define NITERY  8            // y K chunks (2*128/32)
#define NITERO  16           // out K chunks (2*256/32)

// -------- scratch (static device globals; no runtime allocation) -----------
__device__ float g_W1G1[NL * CIN * HID];
__device__ float g_G3W2[NL * HID * CIN];
__device__ float g_b1g1[HID];
__device__ __half g_Tb[384 * 128];                   // to_grid [hi|lo]
__device__ __half g_FTb[64 * 704];                   // from_grid^T [hi|lo]
__device__ __half g_g2b[HID * 512];                  // g2^T [hi|lo]
__device__ __half g_w1g1h[NL * HID * 256];           // W1G1^T rows [hi|lo]
__device__ __half g_g3w2h[NL * CIN * 512];           // (g3 w2)^T rows [hi|lo]
__device__ __half g_nfh[(size_t)N_NODES * NC * CIN];       // 12.8 MB
__device__ __half g_yb[(size_t)N_NODES * 64 * HID];        // 34 MB (hi)
__device__ __half g_grid1b[MROWS * HID];                   // 170 MB (hi)
__device__ __half g_grid2b[(size_t)N_NODES * PBLK * HID];  // 185 MB (hi)
__device__ __half g_zh[(size_t)N_NODES * NC * HID];        // 25.7 MB (hi)
__device__ float g_gate[(size_t)N_NODES * HID];

__device__ __forceinline__ float silu_f(float x) {
    return x / (1.0f + __expf(-x));
}
__device__ __forceinline__ int deg_of(int i) {
    int l = 0;
    while ((l + 1) * (l + 1) <= i) ++l;
    return l;
}
__device__ __forceinline__ uint32_t smem_u32(const void* p) {
    uint32_t a;
    asm("{ .reg .u64 t; cvta.to.shared.u64 t, %1; cvt.u32.u64 %0, t; }"
        : "=r"(a) : "l"(p));
    return a;
}
__device__ __forceinline__ void cp_async16(uint32_t dst, const void* src) {
    asm volatile("cp.async.cg.shared.global [%0], [%1], 16;" :: "r"(dst), "l"(src));
}
__device__ __forceinline__ void ldsm_x4(uint32_t& r0, uint32_t& r1,
                                        uint32_t& r2, uint32_t& r3, uint32_t addr) {
    asm volatile("ldmatrix.sync.aligned.m8n8.x4.shared.b16 {%0,%1,%2,%3}, [%4];"
                 : "=r"(r0), "=r"(r1), "=r"(r2), "=r"(r3) : "r"(addr));
}
__device__ __forceinline__ void ldsm_x4_t(uint32_t& r0, uint32_t& r1,
                                          uint32_t& r2, uint32_t& r3, uint32_t addr) {
    asm volatile("ldmatrix.sync.aligned.m8n8.x4.trans.shared.b16 {%0,%1,%2,%3}, [%4];"
                 : "=r"(r0), "=r"(r1), "=r"(r2), "=r"(r3) : "r"(addr));
}
__device__ __forceinline__ void mma_f16(float* d, const uint32_t* a, const uint32_t* b) {
    asm volatile(
        "mma.sync.aligned.m16n8k16.row.col.f32.f16.f16.f32 "
        "{%0,%1,%2,%3}, {%4,%5,%6,%7}, {%8,%9}, {%0,%1,%2,%3};"
        : "+f"(d[0]), "+f"(d[1]), "+f"(d[2]), "+f"(d[3])
        : "r"(a[0]), "r"(a[1]), "r"(a[2]), "r"(a[3]), "r"(b[0]), "r"(b[1]));
}
__device__ __forceinline__ uint32_t pkh2(float x, float y) {
    __half hx = __float2half_rn(x), hy = __float2half_rn(y);
    uint16_t bx = *(uint16_t*)&hx, by = *(uint16_t*)&hy;
    return (uint32_t)bx | ((uint32_t)by << 16);
}

// K-chunk source maps (activation hi planes re-read for the lo term).
__device__ __forceinline__ int brow1(int kc) { return (kc & 1) * 32; }
__device__ __forceinline__ int aoff2(int kc) { return (kc & 7) * 32; }
__device__ __forceinline__ int browz(int kc) { return (kc < 11 ? kc : kc - 11) * 32; }
__device__ __forceinline__ int aoffy(int kc) { return (kc & 3) * 32; }
__device__ __forceinline__ int aoffo(int kc) { return (kc & 7) * 32; }

// ---------------------------------------------------------------------------
// Generic 64x64x16 SIMT tiled GEMM (small stages only).
// ---------------------------------------------------------------------------
template<bool DO_SILU, bool HAS_BIAS>
__device__ __forceinline__ void gemm_tile(
    const float* __restrict__ A, int lda,
    const float* __restrict__ B, int ldb,
    const float* __restrict__ bias,
    float* __restrict__ C, int ldc,
    int M, int N, int K)
{
    __shared__ float As[16][64];
    __shared__ float Bs[16][64];

    const int tid = threadIdx.x;
    const int tx  = tid & 15;
    const int ty  = tid >> 4;
    const int m0  = blockIdx.y * 64;
    const int n0  = blockIdx.x * 64;

    float acc[4][4];
#pragma unroll
    for (int i = 0; i < 4; i++)
#pragma unroll
        for (int j = 0; j < 4; j++) acc[i][j] = 0.0f;

    for (int k0 = 0; k0 < K; k0 += 16) {
#pragma unroll
        for (int e = tid; e < 64 * 16; e += 256) {
            int m = e >> 4, k = e & 15;
            int gm = m0 + m, gk = k0 + k;
            As[k][m] = (gm < M && gk < K) ? A[(size_t)gm * lda + gk] : 0.0f;
        }
#pragma unroll
        for (int e = tid; e < 16 * 64; e += 256) {
            int k = e >> 6, n = e & 63;
            int gk = k0 + k, gn = n0 + n;
            Bs[k][n] = (gk < K && gn < N) ? B[(size_t)gk * ldb + gn] : 0.0f;
        }
        __syncthreads();

#pragma unroll
        for (int k = 0; k < 16; k++) {
            float4 av = *(const float4*)&As[k][ty * 4];
            float4 bv = *(const float4*)&Bs[k][tx * 4];
            float a4[4] = {av.x, av.y, av.z, av.w};
            float b4[4] = {bv.x, bv.y, bv.z, bv.w};
#pragma unroll
            for (int i = 0; i < 4; i++)
#pragma unroll
                for (int j = 0; j < 4; j++)
                    acc[i][j] += a4[i] * b4[j];
        }
        __syncthreads();
    }

#pragma unroll
    for (int i = 0; i < 4; i++) {
        int gm = m0 + ty * 4 + i;
        if (gm >= M) continue;
#pragma unroll
        for (int j = 0; j < 4; j++) {
            int gn = n0 + tx * 4 + j;
            if (gn >= N) continue;
            float v = acc[i][j];
            if (HAS_BIAS) v += bias[gn];
            if (DO_SILU)  v = silu_f(v);
            C[(size_t)gm * ldc + gn] = v;
        }
    }
}

// ---------------------------- prolog kernels --------------------------------

__global__ void __launch_bounds__(256) k_w1g1(const float* __restrict__ w1,
                                              const float* __restrict__ g1) {
    int l = blockIdx.z;
    gemm_tile<false, false>(w1 + (size_t)l * CIN * HID, HID, g1, HID, nullptr,
                            g_W1G1 + (size_t)l * CIN * HID, HID, CIN, HID, HID);
}

__global__ void __launch_bounds__(256) k_g3w2(const float* __restrict__ g3,
                                              const float* __restrict__ w2) {
    int l = blockIdx.z;
    gemm_tile<false, false>(g3, HID, w2 + (size_t)l * HID * CIN, CIN, nullptr,
                            g_G3W2 + (size_t)l * HID * CIN, CIN, HID, CIN, HID);
}

__global__ void k_b1g1(const float* __restrict__ b1, const float* __restrict__ g1) {
    int k = threadIdx.x;
    float s = 0.0f;
    for (int h = 0; h < HID; h++) s += b1[h] * g1[(size_t)h * HID + k];
    g_b1g1[k] = s;
}

// g_Tb [384 x 128]: cols [0,64)=hi(T[p][i]), [64,128)=lo; pads 0.
__global__ void k_prepT(const float* __restrict__ T) {
    int p = blockIdx.x;
    int c = threadIdx.x;
    int reg = c >> 6, i = c & 63;
    float v = (p < NP && i < NC) ? T[p * NC + i] : 0.0f;
    __half h = __float2half_rn(v);
    __half o = reg ? __float2half_rn(v - __half2float(h)) : h;
    g_Tb[p * 128 + c] = o;
}

// g_FTb [64 x 704]: cols [0,352)=hi(F[p][i]), [352,704)=lo; pads 0.
__global__ void k_prepFT(const float* __restrict__ F) {
    int i = blockIdx.x;
    int reg = blockIdx.y;
    int p = threadIdx.x;
    float v = (i < NC && p < NP) ? F[p * NC + i] : 0.0f;
    __half h = __float2half_rn(v);
    __half o = reg ? __float2half_rn(v - __half2float(h)) : h;
    g_FTb[i * 704 + reg * PBLK + p] = o;
}

// g_g2b [256 x 512] rows n: [hi(g2[k][n]) | lo]
__global__ void k_prepg2(const float* __restrict__ g2) {
    int k = blockIdx.x;
    int n = threadIdx.x;
    float x = g2[(size_t)k * HID + n];
    __half h = __float2half_rn(x);
    __half* row = g_g2b + (size_t)n * 512;
    row[k]       = h;
    row[HID + k] = __float2half_rn(x - __half2float(h));
}

// g_w1g1h [l][n(256)][256]: row n = [hi(W1G1[l][k][n]) k<128 | lo]
__global__ void k_prep_w1g1h() {
    int l = blockIdx.x, n = blockIdx.y, k = threadIdx.x;
    float x = g_W1G1[((size_t)l * CIN + k) * HID + n];
    __half h = __float2half_rn(x);
    __half* row = g_w1g1h + ((size_t)l * HID + n) * 256;
    row[k]       = h;
    row[CIN + k] = __float2half_rn(x - __half2float(h));
}

// g_g3w2h [l][n(128)][512]: row n = [hi(G3W2[l][k][n]) k<256 | lo]
__global__ void k_prep_g3w2h() {
    int l = blockIdx.x, n = blockIdx.y, k = threadIdx.x;
    float x = g_G3W2[((size_t)l * HID + k) * CIN + n];
    __half h = __float2half_rn(x);
    __half* row = g_g3w2h + ((size_t)l * CIN + n) * 512;
    row[k]       = h;
    row[HID + k] = __float2half_rn(x - __half2float(h));
}

// nf -> fp16
__global__ void k_prep_nfh(const float* __restrict__ nf) {
    size_t idx = ((size_t)blockIdx.x * blockDim.x + threadIdx.x) * 2;
    float2 v = *(const float2*)(nf + idx);
    *(uint32_t*)&g_nfh[idx] = pkh2(v.x, v.y);
}

// zero y pad rows (rows [49,64))
__global__ void k_pad_yb() {
    int q = blockIdx.x;
    int node = blockIdx.y;
    int row = NC + q;
    *(uint32_t*)&g_yb[(size_t)node * (64 * HID) + (size_t)row * HID + threadIdx.x * 2] = 0;
}

// zero grid2b pad rows (rows [324,352))
__global__ void k_pad_g2b() {
    int q = blockIdx.x;
    int node = blockIdx.y;
    int row = NP + q;
    *(uint32_t*)&g_grid2b[(size_t)node * (PBLK * HID) + (size_t)row * HID + threadIdx.x * 2] = 0;
}

// ---------------------------- main stage kernels ----------------------------

__global__ void __launch_bounds__(256) k_gate(const float* __restrict__ nf,
                                              const float* __restrict__ ws,
                                              const float* __restrict__ bs) {
    gemm_tile<true, true>(nf, NC * CIN, ws, HID, bs, g_gate, HID,
                          N_NODES, HID, CIN);
}

// ---------------- y = nfh @ W1G1[l] : fp16 MMA, 4-stage ---------------------
// Grid (8 M-tiles, 49 i). A = g_nfh rows (m*49+i)*128, B = g_w1g1h[l].
__global__ void __launch_bounds__(256, 1) k_y_mma() {
    extern __shared__ __align__(128) char smem[];
    const uint32_t sbase = smem_u32(smem);
    const int tid = threadIdx.x;
    const int wid = tid >> 5;
    const int lid = tid & 31;
    const int wm  = wid & 1;
    const int wn  = wid >> 1;
    const int i   = blockIdx.y;
    const int l   = deg_of(i);
    const int m0  = blockIdx.x * BM;

    const uint32_t STAGE = BM * 64 + BN * 64;    // 24576
    const uint32_t BOFF  = BM * 64;

    uint32_t a_addr[4][2], b_addr[4][2];
#pragma unroll
    for (int mt = 0; mt < 4; mt++)
#pragma unroll
        for (int ks = 0; ks < 2; ks++) {
            int row = wm * 64 + mt * 16 + (lid & 7) + ((lid >> 3) & 1) * 8;
            int ch  = ks * 2 + (lid >> 4);
            a_addr[mt][ks] = sbase + row * 64 + 16 * (ch ^ ((row >> 1) & 3));
        }
#pragma unroll
    for (int np = 0; np < 4; np++)
#pragma unroll
        for (int ks = 0; ks < 2; ks++) {
            int row = wn * 64 + np * 16 + (lid & 7) + (lid >> 4) * 8;
            int ch  = ks * 2 + ((lid >> 3) & 1);
            b_addr[np][ks] = sbase + BOFF + row * 64 + 16 * (ch ^ ((row >> 1) & 3));
        }

    uint32_t a_rel[2], b_rel[4];
    const __half* a_base[2];
    const __half* b_base[4];
#pragma unroll
    for (int j = 0; j < 2; j++) {
        int id = tid + j * 256, r = id >> 2, c = id & 3;
        a_rel[j] = sbase + r * 64 + 16 * (c ^ ((r >> 1) & 3));
        a_base[j] = g_nfh + ((size_t)(m0 + r) * NC + i) * CIN + c * 8;
    }
#pragma unroll
    for (int j = 0; j < 4; j++) {
        int id = tid + j * 256, r = id >> 2, c = id & 3;
        b_rel[j] = sbase + BOFF + r * 64 + 16 * (c ^ ((r >> 1) & 3));
        b_base[j] = g_w1g1h + ((size_t)l * HID + r) * 256 + c * 8;
    }

    float acc[4][8][4];
#pragma unroll
    for (int mt = 0; mt < 4; mt++)
#pragma unroll
        for (int nt = 0; nt < 8; nt++)
#pragma unroll
            for (int v = 0; v < 4; v++) acc[mt][nt][v] = 0.0f;

#pragma unroll
    for (int s = 0; s < 3; s++) {
        uint32_t so = s * STAGE;
#pragma unroll
        for (int j = 0; j < 2; j++) cp_async16(a_rel[j] + so, a_base[j] + aoffy(s));
#pragma unroll
        for (int j = 0; j < 4; j++) cp_async16(b_rel[j] + so, b_base[j] + s * 32);
        asm volatile("cp.async.commit_group;");
    }

#pragma unroll 1
    for (int kc = 0; kc < NITERY; kc++) {
        asm volatile("cp.async.wait_group 2;");
        __syncthreads();
        int pf = kc + 3;
        if (pf < NITERY) {
            uint32_t so = (pf & 3) * STAGE;
#pragma unroll
            for (int j = 0; j < 2; j++) cp_async16(a_rel[j] + so, a_base[j] + aoffy(pf));
#pragma unroll
            for (int j = 0; j < 4; j++) cp_async16(b_rel[j] + so, b_base[j] + pf * 32);
        }
        asm volatile("cp.async.commit_group;");

        const uint32_t so = (kc & 3) * STAGE;
#pragma unroll
        for (int ks = 0; ks < 2; ks++) {
            uint32_t af[4][4], bf[8][2];
#pragma unroll
            for (int mt = 0; mt < 4; mt++)
                ldsm_x4(af[mt][0], af[mt][1], af[mt][2], af[mt][3],
                        a_addr[mt][ks] + so);
#pragma unroll
            for (int np = 0; np < 4; np++)
                ldsm_x4(bf[2 * np][0], bf[2 * np][1], bf[2 * np + 1][0],
                        bf[2 * np + 1][1], b_addr[np][ks] + so);
#pragma unroll
            for (int mt = 0; mt < 4; mt++)
#pragma unroll
                for (int nt = 0; nt < 8; nt++)
                    mma_f16(acc[mt][nt], af[mt], bf[nt]);
        }
    }

    // Epilogue: fp16 store into g_yb[node][i][:], +b1g1 bias when i==0.
    const int tq = lid >> 2;
    const int tr = lid & 3;
#pragma unroll
    for (int mt = 0; mt < 4; mt++) {
#pragma unroll
        for (int half = 0; half < 2; half++) {
            int node = m0 + wm * 64 + mt * 16 + tq + half * 8;
            __half* row = g_yb + ((size_t)node * 64 + i) * HID;
#pragma unroll
            for (int nt = 0; nt < 8; nt++) {
                int col = wn * 64 + nt * 8 + tr * 2;
                float v0 = acc[mt][nt][half * 2 + 0];
                float v1 = acc[mt][nt][half * 2 + 1];
                if (i == 0) { v0 += g_b1g1[col]; v1 += g_b1g1[col + 1]; }
                *(uint32_t*)&row[col] = pkh2(v0, v1);
            }
        }
    }
}

// ---------------- grid1 = silu(T @ y[n]) : fp16 MMA, trans-B, 3-stage -------
__global__ void __launch_bounds__(256, 1) k_grid1_mma() {
    extern __shared__ __align__(128) char smem[];
    const uint32_t sbase = smem_u32(smem);
    const int tid = threadIdx.x;
    const int wid = tid >> 5;
    const int lid = tid & 31;
    const int wm  = wid & 1;
    const int wn  = wid >> 1;
    const int node = blockIdx.y;
    const int m0 = blockIdx.x * BM;

    const uint32_t STAGE = BM * 64 + BK * 512;   // 24576
    const uint32_t BOFF  = BM * 64;

    uint32_t a_addr[4][2], b_addr[4][2];
#pragma unroll
    for (int mt = 0; mt < 4; mt++)
#pragma unroll
        for (int ks = 0; ks < 2; ks++) {
            int row = wm * 64 + mt * 16 + (lid & 7) + ((lid >> 3) & 1) * 8;
            int ch  = ks * 2 + (lid >> 4);
            a_addr[mt][ks] = sbase + row * 64 + 16 * (ch ^ ((row >> 1) & 3));
        }
#pragma unroll
    for (int np = 0; np < 4; np++)
#pragma unroll
        for (int ks = 0; ks < 2; ks++) {
            int row = ks * 16 + (lid & 7) + 8 * ((lid >> 3) & 1);
            int cn  = wn * 8 + np * 2 + (lid >> 4);
            b_addr[np][ks] = sbase + BOFF + row * 512 + 16 * (cn ^ (row & 7));
        }

    uint32_t a_rel[2], b_rel[4];
    const __half* a_base[2];
    const __half* b_base[4];
    const __half* ybn = g_yb + (size_t)node * (64 * HID);
#pragma unroll
    for (int i = 0; i < 2; i++) {
        int id = tid + i * 256, r = id >> 2, c = id & 3;
        a_rel[i] = sbase + r * 64 + 16 * (c ^ ((r >> 1) & 3));
        a_base[i] = g_Tb + (m0 + r) * 128 + c * 8;
    }
#pragma unroll
    for (int i = 0; i < 4; i++) {
        int id = tid + i * 256, r = id >> 5, c = id & 31;
        b_rel[i] = sbase + BOFF + r * 512 + 16 * (c ^ (r & 7));
        b_base[i] = ybn + r * HID + c * 8;
    }

    float acc[4][8][4];
#pragma unroll
    for (int mt = 0; mt < 4; mt++)
#pragma unroll
        for (int nt = 0; nt < 8; nt++)
#pragma unroll
            for (int v = 0; v < 4; v++) acc[mt][nt][v] = 0.0f;

#pragma unroll
    for (int s = 0; s < 2; s++) {
        uint32_t so = s * STAGE;
#pragma unroll
        for (int i = 0; i < 2; i++) cp_async16(a_rel[i] + so, a_base[i] + s * 32);
        int ro = brow1(s) * HID;
#pragma unroll
        for (int i = 0; i < 4; i++) cp_async16(b_rel[i] + so, b_base[i] + ro);
        asm volatile("cp.async.commit_group;");
    }

#pragma unroll 1
    for (int kc = 0; kc < NITER1; kc++) {
        asm volatile("cp.async.wait_group 1;");
        __syncthreads();
        int pf = kc + 2;
        if (pf < NITER1) {
            uint32_t so = (pf % 3) * STAGE;
#pragma unroll
            for (int i = 0; i < 2; i++) cp_async16(a_rel[i] + so, a_base[i] + pf * 32);
            int ro = brow1(pf) * HID;
#pragma unroll
            for (int i = 0; i < 4; i++) cp_async16(b_rel[i] + so, b_base[i] + ro);
        }
        asm volatile("cp.async.commit_group;");

        const uint32_t so = (kc % 3) * STAGE;
#pragma unroll
        for (int ks = 0; ks < 2; ks++) {
            uint32_t af[4][4], bf[8][2];
#pragma unroll
            for (int mt = 0; mt < 4; mt++)
                ldsm_x4(af[mt][0], af[mt][1], af[mt][2], af[mt][3],
                        a_addr[mt][ks] + so);
#pragma unroll
            for (int np = 0; np < 4; np++)
                ldsm_x4_t(bf[2 * np][0], bf[2 * np][1], bf[2 * np + 1][0],
                          bf[2 * np + 1][1], b_addr[np][ks] + so);
#pragma unroll
            for (int mt = 0; mt < 4; mt++)
#pragma unroll
                for (int nt = 0; nt < 8; nt++)
                    mma_f16(acc[mt][nt], af[mt], bf[nt]);
        }
    }

    const int tq = lid >> 2;
    const int tr = lid & 3;
#pragma unroll
    for (int mt = 0; mt < 4; mt++) {
#pragma unroll
        for (int half = 0; half < 2; half++) {
            int p = m0 + wm * 64 + mt * 16 + tq + half * 8;
            if (p >= NP) continue;
            __half* row = g_grid1b + ((size_t)node * NP + p) * HID;
#pragma unroll
            for (int nt = 0; nt < 8; nt++) {
                int col = wn * 64 + nt * 8 + tr * 2;
                *(uint32_t*)&row[col] = pkh2(silu_f(acc[mt][nt][half * 2 + 0]),
                                             silu_f(acc[mt][nt][half * 2 + 1]));
            }
        }
    }
}

// ------------- grid2 = silu(grid1 @ g2): fp16 MMA, 4-stage ------------------
__global__ void __launch_bounds__(256, 1) k_grid2_mma() {
    extern __shared__ __align__(128) char smem[];
    const uint32_t sbase = smem_u32(smem);
    const int tid = threadIdx.x;
    const int wid = tid >> 5;
    const int lid = tid & 31;
    const int wm  = wid & 1;
    const int wn  = wid >> 1;
    const size_t m0 = (size_t)blockIdx.x * BM;

    const uint32_t STAGE = BM * 64 + BN * 64;    // 24576
    const uint32_t BOFF  = BM * 64;

    uint32_t a_addr[4][2], b_addr[4][2];
#pragma unroll
    for (int mt = 0; mt < 4; mt++)
#pragma unroll
        for (int ks = 0; ks < 2; ks++) {
            int row = wm * 64 + mt * 16 + (lid & 7) + ((lid >> 3) & 1) * 8;
            int ch  = ks * 2 + (lid >> 4);
            a_addr[mt][ks] = sbase + row * 64 + 16 * (ch ^ ((row >> 1) & 3));
        }
#pragma unroll
    for (int np = 0; np < 4; np++)
#pragma unroll
        for (int ks = 0; ks < 2; ks++) {
            int row = wn * 64 + np * 16 + (lid & 7) + (lid >> 4) * 8;
            int ch  = ks * 2 + ((lid >> 3) & 1);
            b_addr[np][ks] = sbase + BOFF + row * 64 + 16 * (ch ^ ((row >> 1) & 3));
        }

    uint32_t a_rel[2], b_rel[4];
    const __half* a_base[2];
    const __half* b_base[4];
#pragma unroll
    for (int i = 0; i < 2; i++) {
        int id = tid + i * 256, r = id >> 2, c = id & 3;
        a_rel[i] = sbase + r * 64 + 16 * (c ^ ((r >> 1) & 3));
        a_base[i] = g_grid1b + (m0 + r) * (size_t)HID + c * 8;
    }
#pragma unroll
    for (int i = 0; i < 4; i++) {
        int id = tid + i * 256, r = id >> 2, c = id & 3;
        b_rel[i] = sbase + BOFF + r * 64 + 16 * (c ^ ((r >> 1) & 3));
        b_base[i] = g_g2b + r * (size_t)512 + c * 8;
    }

    float acc[4][8][4];
#pragma unroll
    for (int mt = 0; mt < 4; mt++)
#pragma unroll
        for (int nt = 0; nt < 8; nt++)
#pragma unroll
            for (int v = 0; v < 4; v++) acc[mt][nt][v] = 0.0f;

#pragma unroll
    for (int s = 0; s < 3; s++) {
        uint32_t so = s * STAGE;
        int ao = aoff2(s), bo = s * 32;
#pragma unroll
        for (int i = 0; i < 2; i++) cp_async16(a_rel[i] + so, a_base[i] + ao);
#pragma unroll
        for (int i = 0; i < 4; i++) cp_async16(b_rel[i] + so, b_base[i] + bo);
        asm volatile("cp.async.commit_group;");
    }

#pragma unroll 1
    for (int kc = 0; kc < NITER2; kc++) {
        asm volatile("cp.async.wait_group 2;");
        __syncthreads();
        int pf = kc + 3;
        if (pf < NITER2) {
            uint32_t so = (pf & 3) * STAGE;
            int ao = aoff2(pf), bo = pf * 32;
#pragma unroll
            for (int i = 0; i < 2; i++) cp_async16(a_rel[i] + so, a_base[i] + ao);
#pragma unroll
            for (int i = 0; i < 4; i++) cp_async16(b_rel[i] + so, b_base[i] + bo);
        }
        asm volatile("cp.async.commit_group;");

        const uint32_t so = (kc & 3) * STAGE;
#pragma unroll
        for (int ks = 0; ks < 2; ks++) {
            uint32_t af[4][4], bf[8][2];
#pragma unroll
            for (int mt = 0; mt < 4; mt++)
                ldsm_x4(af[mt][0], af[mt][1], af[mt][2], af[mt][3],
                        a_addr[mt][ks] + so);
#pragma unroll
            for (int np = 0; np < 4; np++)
                ldsm_x4(bf[2 * np][0], bf[2 * np][1], bf[2 * np + 1][0],
                        bf[2 * np + 1][1], b_addr[np][ks] + so);
#pragma unroll
            for (int mt = 0; mt < 4; mt++)
#pragma unroll
                for (int nt = 0; nt < 8; nt++)
                    mma_f16(acc[mt][nt], af[mt], bf[nt]);
        }
    }

    const int tq = lid >> 2;
    const int tr = lid & 3;
#pragma unroll
    for (int mt = 0; mt < 4; mt++) {
#pragma unroll
        for (int half = 0; half < 2; half++) {
            size_t r = m0 + wm * 64 + mt * 16 + tq + half * 8;
            uint32_t n = (uint32_t)(r / NP);
            uint32_t p = (uint32_t)(r - (size_t)n * NP);
            __half* row = g_grid2b + ((size_t)n * PBLK + p) * HID;
#pragma unroll
            for (int nt = 0; nt < 8; nt++) {
                int col = wn * 64 + nt * 8 + tr * 2;
                *(uint32_t*)&row[col] = pkh2(silu_f(acc[mt][nt][half * 2 + 0]),
                                             silu_f(acc[mt][nt][half * 2 + 1]));
            }
        }
    }
}

// ---------------- z = F^T @ grid2[n] : fp16 MMA, trans-B, 4-stage -----------
__global__ void __launch_bounds__(256, 1) k_z_mma() {
    extern __shared__ __align__(128) char smem[];
    const uint32_t sbase = smem_u32(smem);
    const int tid = threadIdx.x;
    const int wid = tid >> 5;
    const int lid = tid & 31;
    const int node = blockIdx.x;

    const uint32_t STAGE = 64 * 64 + BK * 512;   // 20480
    const uint32_t BOFF  = 64 * 64;

    uint32_t a_addr[4][2], b_addr[2][2];
#pragma unroll
    for (int mt = 0; mt < 4; mt++)
#pragma unroll
        for (int ks = 0; ks < 2; ks++) {
            int row = mt * 16 + (lid & 7) + ((lid >> 3) & 1) * 8;
            int ch  = ks * 2 + (lid >> 4);
            a_addr[mt][ks] = sbase + row * 64 + 16 * (ch ^ ((row >> 1) & 3));
        }
#pragma unroll
    for (int np = 0; np < 2; np++)
#pragma unroll
        for (int ks = 0; ks < 2; ks++) {
            int row = ks * 16 + (lid & 7) + 8 * ((lid >> 3) & 1);
            int cn  = wid * 4 + np * 2 + (lid >> 4);
            b_addr[np][ks] = sbase + BOFF + row * 512 + 16 * (cn ^ (row & 7));
        }

    uint32_t a_rel, b_rel[4];
    const __half* a_basep;
    const __half* b_base[4];
    const __half* g2bn = g_grid2b + (size_t)node * (PBLK * HID);
    {
        int r = tid >> 2, c = tid & 3;
        a_rel = sbase + r * 64 + 16 * (c ^ ((r >> 1) & 3));
        a_basep = g_FTb + r * 704 + c * 8;
    }
#pragma unroll
    for (int i = 0; i < 4; i++) {
        int id = tid + i * 256, r = id >> 5, c = id & 31;
        b_rel[i] = sbase + BOFF + r * 512 + 16 * (c ^ (r & 7));
        b_base[i] = g2bn + r * HID + c * 8;
    }

    float acc[4][4][4];
#pragma unroll
    for (int mt = 0; mt < 4; mt++)
#pragma unroll
        for (int nt = 0; nt < 4; nt++)
#pragma unroll
            for (int v = 0; v < 4; v++) acc[mt][nt][v] = 0.0f;

#pragma unroll
    for (int s = 0; s < 3; s++) {
        uint32_t so = s * STAGE;
        cp_async16(a_rel + so, a_basep + s * 32);
        int ro = browz(s) * HID;
#pragma unroll
        for (int i = 0; i < 4; i++) cp_async16(b_rel[i] + so, b_base[i] + ro);
        asm volatile("cp.async.commit_group;");
    }

#pragma unroll 1
    for (int kc = 0; kc < NITERZ; kc++) {
        asm volatile("cp.async.wait_group 2;");
        __syncthreads();
        int pf = kc + 3;
        if (pf < NITERZ) {
            uint32_t so = (pf & 3) * STAGE;
            cp_async16(a_rel + so, a_basep + pf * 32);
            int ro = browz(pf) * HID;
#pragma unroll
            for (int i = 0; i < 4; i++) cp_async16(b_rel[i] + so, b_base[i] + ro);
        }
        asm volatile("cp.async.commit_group;");

        const uint32_t so = (kc & 3) * STAGE;
#pragma unroll
        for (int ks = 0; ks < 2; ks++) {
            uint32_t af[4][4], bf[4][2];
#pragma unroll
            for (int mt = 0; mt < 4; mt++)
                ldsm_x4(af[mt][0], af[mt][1], af[mt][2], af[mt][3],
                        a_addr[mt][ks] + so);
#pragma unroll
            for (int np = 0; np < 2; np++)
                ldsm_x4_t(bf[2 * np][0], bf[2 * np][1], bf[2 * np + 1][0],
                          bf[2 * np + 1][1], b_addr[np][ks] + so);
#pragma unroll
            for (int mt = 0; mt < 4; mt++)
#pragma unroll
                for (int nt = 0; nt < 4; nt++)
                    mma_f16(acc[mt][nt], af[mt], bf[nt]);
        }
    }

    // Epilogue: fp16 store z[n][i][h], i < 49.
    const int tq = lid >> 2;
    const int tr = lid & 3;
#pragma unroll
    for (int mt = 0; mt < 4; mt++) {
#pragma unroll
        for (int half = 0; half < 2; half++) {
            int i = mt * 16 + tq + half * 8;
            if (i >= NC) continue;
            __half* row = g_zh + ((size_t)node * NC + i) * HID;
#pragma unroll
            for (int nt = 0; nt < 4; nt++) {
                int col = wid * 32 + nt * 8 + tr * 2;
                *(uint32_t*)&row[col] = pkh2(acc[mt][nt][half * 2 + 0],
                                             acc[mt][nt][half * 2 + 1]);
            }
        }
    }
}

// ---------------- out[:,i,:] = z[:,i,:] @ G3W2[l]: fp16 MMA (i>=1) ----------
// Grid (8 M-tiles, 48). BN=128, warp tile 64x32.
__global__ void __launch_bounds__(256, 1) k_out_mma(float* __restrict__ out) {
    extern __shared__ __align__(128) char smem[];
    const uint32_t sbase = smem_u32(smem);
    const int tid = threadIdx.x;
    const int wid = tid >> 5;
    const int lid = tid & 31;
    const int wm  = wid & 1;
    const int wn  = wid >> 1;   // 0..3, 32 cols each
    const int i   = blockIdx.y + 1;
    const int l   = deg_of(i);
    const int m0  = blockIdx.x * BM;

    const uint32_t STAGE = BM * 64 + CIN * 64;   // 16384
    const uint32_t BOFF  = BM * 64;

    uint32_t a_addr[4][2], b_addr[2][2];
#pragma unroll
    for (int mt = 0; mt < 4; mt++)
#pragma unroll
        for (int ks = 0; ks < 2; ks++) {
            int row = wm * 64 + mt * 16 + (lid & 7) + ((lid >> 3) & 1) * 8;
            int ch  = ks * 2 + (lid >> 4);
            a_addr[mt][ks] = sbase + row * 64 + 16 * (ch ^ ((row >> 1) & 3));
        }
#pragma unroll
    for (int np = 0; np < 2; np++)
#pragma unroll
        for (int ks = 0; ks < 2; ks++) {
            int row = wn * 32 + np * 16 + (lid & 7) + (lid >> 4) * 8;
            int ch  = ks * 2 + ((lid >> 3) & 1);
            b_addr[np][ks] = sbase + BOFF + row * 64 + 16 * (ch ^ ((row >> 1) & 3));
        }

    uint32_t a_rel[2], b_rel[2];
    const __half* a_base[2];
    const __half* b_base[2];
#pragma unroll
    for (int j = 0; j < 2; j++) {
        int id = tid + j * 256, r = id >> 2, c = id & 3;
        a_rel[j] = sbase + r * 64 + 16 * (c ^ ((r >> 1) & 3));
        a_base[j] = g_zh + ((size_t)(m0 + r) * NC + i) * HID + c * 8;
        b_rel[j] = sbase + BOFF + r * 64 + 16 * (c ^ ((r >> 1) & 3));
        b_base[j] = g_g3w2h + ((size_t)l * CIN + r) * 512 + c * 8;
    }

    float acc[4][4][4];
#pragma unroll
    for (int mt = 0; mt < 4; mt++)
#pragma unroll
        for (int nt = 0; nt < 4; nt++)
#pragma unroll
            for (int v = 0; v < 4; v++) acc[mt][nt][v] = 0.0f;

#pragma unroll
    for (int s = 0; s < 3; s++) {
        uint32_t so = s * STAGE;
#pragma unroll
        for (int j = 0; j < 2; j++) {
            cp_async16(a_rel[j] + so, a_base[j] + aoffo(s));
            cp_async16(b_rel[j] + so, b_base[j] + s * 32);
        }
        asm volatile("cp.async.commit_group;");
    }

#pragma unroll 1
    for (int kc = 0; kc < NITERO; kc++) {
        asm volatile("cp.async.wait_group 2;");
        __syncthreads();
        int pf = kc + 3;
        if (pf < NITERO) {
            uint32_t so = (pf & 3) * STAGE;
#pragma unroll
            for (int j = 0; j < 2; j++) {
                cp_async16(a_rel[j] + so, a_base[j] + aoffo(pf));
                cp_async16(b_rel[j] + so, b_base[j] + pf * 32);
            }
        }
        asm volatile("cp.async.commit_group;");

        const uint32_t so = (kc & 3) * STAGE;
#pragma unroll
        for (int ks = 0; ks < 2; ks++) {
            uint32_t af[4][4], bf[4][2];
#pragma unroll
            for (int mt = 0; mt < 4; mt++)
                ldsm_x4(af[mt][0], af[mt][1], af[mt][2], af[mt][3],
                        a_addr[mt][ks] + so);
#pragma unroll
            for (int np = 0; np < 2; np++)
                ldsm_x4(bf[2 * np][0], bf[2 * np][1], bf[2 * np + 1][0],
                        bf[2 * np + 1][1], b_addr[np][ks] + so);
#pragma unroll
            for (int mt = 0; mt < 4; mt++)
#pragma unroll
                for (int nt = 0; nt < 4; nt++)
                    mma_f16(acc[mt][nt], af[mt], bf[nt]);
        }
    }

    // Epilogue: fp32 store out[node][i][col].
    const int tq = lid >> 2;
    const int tr = lid & 3;
#pragma unroll
    for (int mt = 0; mt < 4; mt++) {
#pragma unroll
        for (int half = 0; half < 2; half++) {
            int node = m0 + wm * 64 + mt * 16 + tq + half * 8;
            float* row = out + ((size_t)node * NC + i) * CIN;
#pragma unroll
            for (int nt = 0; nt < 4; nt++) {
                int col = wn * 32 + nt * 8 + tr * 2;
                float2 v;
                v.x = acc[mt][nt][half * 2 + 0];
                v.y = acc[mt][nt][half * 2 + 1];
                *(float2*)&row[col] = v;
            }
        }
    }
}

// out[:,0,:] = gate @ w2[0] + b2  (SIMT, tiny)
__global__ void __launch_bounds__(256) k_out0(const float* __restrict__ w2,
                                              const float* __restrict__ b2,
                                              float* __restrict__ out) {
    gemm_tile<false, true>(g_gate, HID, w2, CIN, b2,
                           out, NC * CIN, N_NODES, CIN, HID);
}

// ---------------------------------------------------------------------------

extern "C" void kernel_launch(void* const* d_in, const int* in_sizes, int n_in,
                              void* d_out, int out_size) {
    const float* nf = (const float*)d_in[0];
    const float* w1 = (const float*)d_in[1];
    const float* b1 = (const float*)d_in[2];
    const float* w2 = (const float*)d_in[3];
    const float* b2 = (const float*)d_in[4];
    const float* ws = (const float*)d_in[5];
    const float* bs = (const float*)d_in[6];
    const float* g1 = (const float*)d_in[7];
    const float* g2 = (const float*)d_in[8];
    const float* g3 = (const float*)d_in[9];
    const float* Tg = (const float*)d_in[10];
    const float* Fg = (const float*)d_in[11];
    float* out = (float*)d_out;

    const int SMEM1 = 3 * (BM * 64 + BK * 512);   // 73728
    const int SMEM2 = 4 * (BM * 64 + BN * 64);    // 98304
    const int SMEMZ = 4 * (64 * 64 + BK * 512);   // 81920
    const int SMEMY = 4 * (BM * 64 + BN * 64);    // 98304
    const int SMEMO = 4 * (BM * 64 + CIN * 64);   // 65536
    cudaFuncSetAttribute(k_grid1_mma, cudaFuncAttributeMaxDynamicSharedMemorySize, SMEM1);
    cudaFuncSetAttribute(k_grid2_mma, cudaFuncAttributeMaxDynamicSharedMemorySize, SMEM2);
    cudaFuncSetAttribute(k_z_mma,     cudaFuncAttributeMaxDynamicSharedMemorySize, SMEMZ);
    cudaFuncSetAttribute(k_y_mma,     cudaFuncAttributeMaxDynamicSharedMemorySize, SMEMY);
    cudaFuncSetAttribute(k_out_mma,   cudaFuncAttributeMaxDynamicSharedMemorySize, SMEMO);

    // prologs
    k_w1g1<<<dim3(HID / 64, CIN / 64, NL), 256>>>(w1, g1);
    k_g3w2<<<dim3(CIN / 64, HID / 64, NL), 256>>>(g3, w2);
    k_b1g1<<<1, HID>>>(b1, g1);
    k_prepT<<<384, 128>>>(Tg);
    k_prepFT<<<dim3(64, 2), PBLK>>>(Fg);
    k_prepg2<<<HID, HID>>>(g2);
    k_prep_w1g1h<<<dim3(NL, HID), CIN>>>();
    k_prep_g3w2h<<<dim3(NL, CIN), HID>>>();
    k_prep_nfh<<<(int)((size_t)N_NODES * NC * CIN / 512), 256>>>(nf);
    k_pad_yb<<<dim3(15, N_NODES), 128>>>();
    k_pad_g2b<<<dim3(28, N_NODES), 128>>>();

    // scalar gating branch
    k_gate<<<dim3(HID / 64, N_NODES / 64), 256>>>(nf, ws, bs);

    // main pipeline (all MMA)
    k_y_mma<<<dim3(N_NODES / BM, NC), 256, SMEMY>>>();
    k_grid1_mma<<<dim3(3, N_NODES), 256, SMEM1>>>();
    k_grid2_mma<<<(int)(MROWS / BM), 256, SMEM2>>>();
    k_z_mma<<<N_NODES, 256, SMEMZ>>>();
    k_out_mma<<<dim3(N_NODES / BM, NC - 1), 256, SMEMO>>>(out);
    k_out0<<<dim3(CIN / 64, N_NODES / 64), 256>>>(w2, b2, out);
}

// round 8
// speedup vs baseline: 3.9159x; 1.0837x over previous
#include <cuda_runtime.h>
#include <cuda_fp16.h>
#include <cstdint>

// ---------------------------------------------------------------------------
// FeedForwardNetwork (SO(3) equivariant FFN), sm_103a — all-MMA fp16 path
// Round 8: grid1/grid2/z converted to 512-thread (16-warp, 64x32 warp tile)
// for better issue overlap (4 warps/SMSP).
// ---------------------------------------------------------------------------

#define N_NODES 1024
#define NC      49
#define CIN     128
#define HID     256
#define RES     18
#define NP      (RES*RES)   // 324
#define NL      7
#define MROWS   ((size_t)N_NODES * NP)   // 331776
#define PBLK    352
#define BM      128
#define BN      256
#define BK      32
#define NITER1  4            // grid1 K chunks (2*64/32)
#define NITER2  16           // grid2 K chunks (2*256/32)
#define NITERZ  22           // z K chunks (2*352/32)
#define NITERY  8            // y K chunks (2*128/32)
#define NITERO  16           // out K chunks (2*256/32)

// -------- scratch (static device globals; no runtime allocation) -----------
__device__ float g_W1G1[NL * CIN * HID];
__device__ float g_G3W2[NL * HID * CIN];
__device__ float g_b1g1[HID];
__device__ __half g_Tb[384 * 128];                   // to_grid [hi|lo]
__device__ __half g_FTb[64 * 704];                   // from_grid^T [hi|lo]
__device__ __half g_g2b[HID * 512];                  // g2^T [hi|lo]
__device__ __half g_w1g1h[NL * HID * 256];           // W1G1^T rows [hi|lo]
__device__ __half g_g3w2h[NL * CIN * 512];           // (g3 w2)^T rows [hi|lo]
__device__ __half g_nfh[(size_t)N_NODES * NC * CIN];       // 12.8 MB
__device__ __half g_yb[(size_t)N_NODES * 64 * HID];        // 34 MB (hi)
__device__ __half g_grid1b[MROWS * HID];                   // 170 MB (hi)
__device__ __half g_grid2b[(size_t)N_NODES * PBLK * HID];  // 185 MB (hi)
__device__ __half g_zh[(size_t)N_NODES * NC * HID];        // 25.7 MB (hi)
__device__ float g_gate[(size_t)N_NODES * HID];

__device__ __forceinline__ float silu_f(float x) {
    return x / (1.0f + __expf(-x));
}
__device__ __forceinline__ int deg_of(int i) {
    int l = 0;
    while ((l + 1) * (l + 1) <= i) ++l;
    return l;
}
__device__ __forceinline__ uint32_t smem_u32(const void* p) {
    uint32_t a;
    asm("{ .reg .u64 t; cvta.to.shared.u64 t, %1; cvt.u32.u64 %0, t; }"
        : "=r"(a) : "l"(p));
    return a;
}
__device__ __forceinline__ void cp_async16(uint32_t dst, const void* src) {
    asm volatile("cp.async.cg.shared.global [%0], [%1], 16;" :: "r"(dst), "l"(src));
}
__device__ __forceinline__ void ldsm_x4(uint32_t& r0, uint32_t& r1,
                                        uint32_t& r2, uint32_t& r3, uint32_t addr) {
    asm volatile("ldmatrix.sync.aligned.m8n8.x4.shared.b16 {%0,%1,%2,%3}, [%4];"
                 : "=r"(r0), "=r"(r1), "=r"(r2), "=r"(r3) : "r"(addr));
}
__device__ __forceinline__ void ldsm_x4_t(uint32_t& r0, uint32_t& r1,
                                          uint32_t& r2, uint32_t& r3, uint32_t addr) {
    asm volatile("ldmatrix.sync.aligned.m8n8.x4.trans.shared.b16 {%0,%1,%2,%3}, [%4];"
                 : "=r"(r0), "=r"(r1), "=r"(r2), "=r"(r3) : "r"(addr));
}
__device__ __forceinline__ void mma_f16(float* d, const uint32_t* a, const uint32_t* b) {
    asm volatile(
        "mma.sync.aligned.m16n8k16.row.col.f32.f16.f16.f32 "
        "{%0,%1,%2,%3}, {%4,%5,%6,%7}, {%8,%9}, {%0,%1,%2,%3};"
        : "+f"(d[0]), "+f"(d[1]), "+f"(d[2]), "+f"(d[3])
        : "r"(a[0]), "r"(a[1]), "r"(a[2]), "r"(a[3]), "r"(b[0]), "r"(b[1]));
}
__device__ __forceinline__ uint32_t pkh2(float x, float y) {
    __half hx = __float2half_rn(x), hy = __float2half_rn(y);
    uint16_t bx = *(uint16_t*)&hx, by = *(uint16_t*)&hy;
    return (uint32_t)bx | ((uint32_t)by << 16);
}

// K-chunk source maps (activation hi planes re-read for the lo term).
__device__ __forceinline__ int brow1(int kc) { return (kc & 1) * 32; }
__device__ __forceinline__ int aoff2(int kc) { return (kc & 7) * 32; }
__device__ __forceinline__ int browz(int kc) { return (kc < 11 ? kc : kc - 11) * 32; }
__device__ __forceinline__ int aoffy(int kc) { return (kc & 3) * 32; }
__device__ __forceinline__ int aoffo(int kc) { return (kc & 7) * 32; }

// ---------------------------------------------------------------------------
// Generic 64x64x16 SIMT tiled GEMM (small stages only).
// ---------------------------------------------------------------------------
template<bool DO_SILU, bool HAS_BIAS>
__device__ __forceinline__ void gemm_tile(
    const float* __restrict__ A, int lda,
    const float* __restrict__ B, int ldb,
    const float* __restrict__ bias,
    float* __restrict__ C, int ldc,
    int M, int N, int K)
{
    __shared__ float As[16][64];
    __shared__ float Bs[16][64];

    const int tid = threadIdx.x;
    const int tx  = tid & 15;
    const int ty  = tid >> 4;
    const int m0  = blockIdx.y * 64;
    const int n0  = blockIdx.x * 64;

    float acc[4][4];
#pragma unroll
    for (int i = 0; i < 4; i++)
#pragma unroll
        for (int j = 0; j < 4; j++) acc[i][j] = 0.0f;

    for (int k0 = 0; k0 < K; k0 += 16) {
#pragma unroll
        for (int e = tid; e < 64 * 16; e += 256) {
            int m = e >> 4, k = e & 15;
            int gm = m0 + m, gk = k0 + k;
            As[k][m] = (gm < M && gk < K) ? A[(size_t)gm * lda + gk] : 0.0f;
        }
#pragma unroll
        for (int e = tid; e < 16 * 64; e += 256) {
            int k = e >> 6, n = e & 63;
            int gk = k0 + k, gn = n0 + n;
            Bs[k][n] = (gk < K && gn < N) ? B[(size_t)gk * ldb + gn] : 0.0f;
        }
        __syncthreads();

#pragma unroll
        for (int k = 0; k < 16; k++) {
            float4 av = *(const float4*)&As[k][ty * 4];
            float4 bv = *(const float4*)&Bs[k][tx * 4];
            float a4[4] = {av.x, av.y, av.z, av.w};
            float b4[4] = {bv.x, bv.y, bv.z, bv.w};
#pragma unroll
            for (int i = 0; i < 4; i++)
#pragma unroll
                for (int j = 0; j < 4; j++)
                    acc[i][j] += a4[i] * b4[j];
        }
        __syncthreads();
    }

#pragma unroll
    for (int i = 0; i < 4; i++) {
        int gm = m0 + ty * 4 + i;
        if (gm >= M) continue;
#pragma unroll
        for (int j = 0; j < 4; j++) {
            int gn = n0 + tx * 4 + j;
            if (gn >= N) continue;
            float v = acc[i][j];
            if (HAS_BIAS) v += bias[gn];
            if (DO_SILU)  v = silu_f(v);
            C[(size_t)gm * ldc + gn] = v;
        }
    }
}

// ---------------------------- prolog kernels --------------------------------

__global__ void __launch_bounds__(256) k_w1g1(const float* __restrict__ w1,
                                              const float* __restrict__ g1) {
    int l = blockIdx.z;
    gemm_tile<false, false>(w1 + (size_t)l * CIN * HID, HID, g1, HID, nullptr,
                            g_W1G1 + (size_t)l * CIN * HID, HID, CIN, HID, HID);
}

__global__ void __launch_bounds__(256) k_g3w2(const float* __restrict__ g3,
                                              const float* __restrict__ w2) {
    int l = blockIdx.z;
    gemm_tile<false, false>(g3, HID, w2 + (size_t)l * HID * CIN, CIN, nullptr,
                            g_G3W2 + (size_t)l * HID * CIN, CIN, HID, CIN, HID);
}

__global__ void k_b1g1(const float* __restrict__ b1, const float* __restrict__ g1) {
    int k = threadIdx.x;
    float s = 0.0f;
    for (int h = 0; h < HID; h++) s += b1[h] * g1[(size_t)h * HID + k];
    g_b1g1[k] = s;
}

// g_Tb [384 x 128]: cols [0,64)=hi(T[p][i]), [64,128)=lo; pads 0.
__global__ void k_prepT(const float* __restrict__ T) {
    int p = blockIdx.x;
    int c = threadIdx.x;
    int reg = c >> 6, i = c & 63;
    float v = (p < NP && i < NC) ? T[p * NC + i] : 0.0f;
    __half h = __float2half_rn(v);
    __half o = reg ? __float2half_rn(v - __half2float(h)) : h;
    g_Tb[p * 128 + c] = o;
}

// g_FTb [64 x 704]: cols [0,352)=hi(F[p][i]), [352,704)=lo; pads 0.
__global__ void k_prepFT(const float* __restrict__ F) {
    int i = blockIdx.x;
    int reg = blockIdx.y;
    int p = threadIdx.x;
    float v = (i < NC && p < NP) ? F[p * NC + i] : 0.0f;
    __half h = __float2half_rn(v);
    __half o = reg ? __float2half_rn(v - __half2float(h)) : h;
    g_FTb[i * 704 + reg * PBLK + p] = o;
}

// g_g2b [256 x 512] rows n: [hi(g2[k][n]) | lo]
__global__ void k_prepg2(const float* __restrict__ g2) {
    int k = blockIdx.x;
    int n = threadIdx.x;
    float x = g2[(size_t)k * HID + n];
    __half h = __float2half_rn(x);
    __half* row = g_g2b + (size_t)n * 512;
    row[k]       = h;
    row[HID + k] = __float2half_rn(x - __half2float(h));
}

// g_w1g1h [l][n(256)][256]: row n = [hi(W1G1[l][k][n]) k<128 | lo]
__global__ void k_prep_w1g1h() {
    int l = blockIdx.x, n = blockIdx.y, k = threadIdx.x;
    float x = g_W1G1[((size_t)l * CIN + k) * HID + n];
    __half h = __float2half_rn(x);
    __half* row = g_w1g1h + ((size_t)l * HID + n) * 256;
    row[k]       = h;
    row[CIN + k] = __float2half_rn(x - __half2float(h));
}

// g_g3w2h [l][n(128)][512]: row n = [hi(G3W2[l][k][n]) k<256 | lo]
__global__ void k_prep_g3w2h() {
    int l = blockIdx.x, n = blockIdx.y, k = threadIdx.x;
    float x = g_G3W2[((size_t)l * HID + k) * CIN + n];
    __half h = __float2half_rn(x);
    __half* row = g_g3w2h + ((size_t)l * CIN + n) * 512;
    row[k]       = h;
    row[HID + k] = __float2half_rn(x - __half2float(h));
}

// nf -> fp16
__global__ void k_prep_nfh(const float* __restrict__ nf) {
    size_t idx = ((size_t)blockIdx.x * blockDim.x + threadIdx.x) * 2;
    float2 v = *(const float2*)(nf + idx);
    *(uint32_t*)&g_nfh[idx] = pkh2(v.x, v.y);
}

// zero y pad rows (rows [49,64))
__global__ void k_pad_yb() {
    int q = blockIdx.x;
    int node = blockIdx.y;
    int row = NC + q;
    *(uint32_t*)&g_yb[(size_t)node * (64 * HID) + (size_t)row * HID + threadIdx.x * 2] = 0;
}

// zero grid2b pad rows (rows [324,352))
__global__ void k_pad_g2b() {
    int q = blockIdx.x;
    int node = blockIdx.y;
    int row = NP + q;
    *(uint32_t*)&g_grid2b[(size_t)node * (PBLK * HID) + (size_t)row * HID + threadIdx.x * 2] = 0;
}

// ---------------------------- main stage kernels ----------------------------

__global__ void __launch_bounds__(256) k_gate(const float* __restrict__ nf,
                                              const float* __restrict__ ws,
                                              const float* __restrict__ bs) {
    gemm_tile<true, true>(nf, NC * CIN, ws, HID, bs, g_gate, HID,
                          N_NODES, HID, CIN);
}

// ---------------- y = nfh @ W1G1[l] : fp16 MMA, 4-stage, 256 thr ------------
__global__ void __launch_bounds__(256, 1) k_y_mma() {
    extern __shared__ __align__(128) char smem[];
    const uint32_t sbase = smem_u32(smem);
    const int tid = threadIdx.x;
    const int wid = tid >> 5;
    const int lid = tid & 31;
    const int wm  = wid & 1;
    const int wn  = wid >> 1;
    const int i   = blockIdx.y;
    const int l   = deg_of(i);
    const int m0  = blockIdx.x * BM;

    const uint32_t STAGE = BM * 64 + BN * 64;    // 24576
    const uint32_t BOFF  = BM * 64;

    uint32_t a_addr[4][2], b_addr[4][2];
#pragma unroll
    for (int mt = 0; mt < 4; mt++)
#pragma unroll
        for (int ks = 0; ks < 2; ks++) {
            int row = wm * 64 + mt * 16 + (lid & 7) + ((lid >> 3) & 1) * 8;
            int ch  = ks * 2 + (lid >> 4);
            a_addr[mt][ks] = sbase + row * 64 + 16 * (ch ^ ((row >> 1) & 3));
        }
#pragma unroll
    for (int np = 0; np < 4; np++)
#pragma unroll
        for (int ks = 0; ks < 2; ks++) {
            int row = wn * 64 + np * 16 + (lid & 7) + (lid >> 4) * 8;
            int ch  = ks * 2 + ((lid >> 3) & 1);
            b_addr[np][ks] = sbase + BOFF + row * 64 + 16 * (ch ^ ((row >> 1) & 3));
        }

    uint32_t a_rel[2], b_rel[4];
    const __half* a_base[2];
    const __half* b_base[4];
#pragma unroll
    for (int j = 0; j < 2; j++) {
        int id = tid + j * 256, r = id >> 2, c = id & 3;
        a_rel[j] = sbase + r * 64 + 16 * (c ^ ((r >> 1) & 3));
        a_base[j] = g_nfh + ((size_t)(m0 + r) * NC + i) * CIN + c * 8;
    }
#pragma unroll
    for (int j = 0; j < 4; j++) {
        int id = tid + j * 256, r = id >> 2, c = id & 3;
        b_rel[j] = sbase + BOFF + r * 64 + 16 * (c ^ ((r >> 1) & 3));
        b_base[j] = g_w1g1h + ((size_t)l * HID + r) * 256 + c * 8;
    }

    float acc[4][8][4];
#pragma unroll
    for (int mt = 0; mt < 4; mt++)
#pragma unroll
        for (int nt = 0; nt < 8; nt++)
#pragma unroll
            for (int v = 0; v < 4; v++) acc[mt][nt][v] = 0.0f;

#pragma unroll
    for (int s = 0; s < 3; s++) {
        uint32_t so = s * STAGE;
#pragma unroll
        for (int j = 0; j < 2; j++) cp_async16(a_rel[j] + so, a_base[j] + aoffy(s));
#pragma unroll
        for (int j = 0; j < 4; j++) cp_async16(b_rel[j] + so, b_base[j] + s * 32);
        asm volatile("cp.async.commit_group;");
    }

#pragma unroll 1
    for (int kc = 0; kc < NITERY; kc++) {
        asm volatile("cp.async.wait_group 2;");
        __syncthreads();
        int pf = kc + 3;
        if (pf < NITERY) {
            uint32_t so = (pf & 3) * STAGE;
#pragma unroll
            for (int j = 0; j < 2; j++) cp_async16(a_rel[j] + so, a_base[j] + aoffy(pf));
#pragma unroll
            for (int j = 0; j < 4; j++) cp_async16(b_rel[j] + so, b_base[j] + pf * 32);
        }
        asm volatile("cp.async.commit_group;");

        const uint32_t so = (kc & 3) * STAGE;
#pragma unroll
        for (int ks = 0; ks < 2; ks++) {
            uint32_t af[4][4], bf[8][2];
#pragma unroll
            for (int mt = 0; mt < 4; mt++)
                ldsm_x4(af[mt][0], af[mt][1], af[mt][2], af[mt][3],
                        a_addr[mt][ks] + so);
#pragma unroll
            for (int np = 0; np < 4; np++)
                ldsm_x4(bf[2 * np][0], bf[2 * np][1], bf[2 * np + 1][0],
                        bf[2 * np + 1][1], b_addr[np][ks] + so);
#pragma unroll
            for (int mt = 0; mt < 4; mt++)
#pragma unroll
                for (int nt = 0; nt < 8; nt++)
                    mma_f16(acc[mt][nt], af[mt], bf[nt]);
        }
    }

    const int tq = lid >> 2;
    const int tr = lid & 3;
#pragma unroll
    for (int mt = 0; mt < 4; mt++) {
#pragma unroll
        for (int half = 0; half < 2; half++) {
            int node = m0 + wm * 64 + mt * 16 + tq + half * 8;
            __half* row = g_yb + ((size_t)node * 64 + i) * HID;
#pragma unroll
            for (int nt = 0; nt < 8; nt++) {
                int col = wn * 64 + nt * 8 + tr * 2;
                float v0 = acc[mt][nt][half * 2 + 0];
                float v1 = acc[mt][nt][half * 2 + 1];
                if (i == 0) { v0 += g_b1g1[col]; v1 += g_b1g1[col + 1]; }
                *(uint32_t*)&row[col] = pkh2(v0, v1);
            }
        }
    }
}

// -------- grid1 = silu(T @ y[n]) : fp16 MMA, trans-B, 3-stage, 512 thr ------
__global__ void __launch_bounds__(512, 1) k_grid1_mma() {
    extern __shared__ __align__(128) char smem[];
    const uint32_t sbase = smem_u32(smem);
    const int tid = threadIdx.x;
    const int wid = tid >> 5;           // 0..15
    const int lid = tid & 31;
    const int wm  = wid & 1;            // M half (64 rows)
    const int wn  = wid >> 1;           // 0..7, 32 cols each
    const int node = blockIdx.y;
    const int m0 = blockIdx.x * BM;

    const uint32_t STAGE = BM * 64 + BK * 512;   // 24576
    const uint32_t BOFF  = BM * 64;

    uint32_t a_addr[4][2], b_addr[2][2];
#pragma unroll
    for (int mt = 0; mt < 4; mt++)
#pragma unroll
        for (int ks = 0; ks < 2; ks++) {
            int row = wm * 64 + mt * 16 + (lid & 7) + ((lid >> 3) & 1) * 8;
            int ch  = ks * 2 + (lid >> 4);
            a_addr[mt][ks] = sbase + row * 64 + 16 * (ch ^ ((row >> 1) & 3));
        }
#pragma unroll
    for (int np = 0; np < 2; np++)
#pragma unroll
        for (int ks = 0; ks < 2; ks++) {
            int row = ks * 16 + (lid & 7) + 8 * ((lid >> 3) & 1);
            int cn  = wn * 4 + np * 2 + (lid >> 4);
            b_addr[np][ks] = sbase + BOFF + row * 512 + 16 * (cn ^ (row & 7));
        }

    uint32_t a_rel, b_rel[2];
    const __half* a_basep;
    const __half* b_base[2];
    const __half* ybn = g_yb + (size_t)node * (64 * HID);
    {
        int r = tid >> 2, c = tid & 3;          // 512 loads cover 128x4
        a_rel = sbase + r * 64 + 16 * (c ^ ((r >> 1) & 3));
        a_basep = g_Tb + (m0 + r) * 128 + c * 8;
    }
#pragma unroll
    for (int j = 0; j < 2; j++) {
        int id = tid + j * 512, r = id >> 5, c = id & 31;
        b_rel[j] = sbase + BOFF + r * 512 + 16 * (c ^ (r & 7));
        b_base[j] = ybn + r * HID + c * 8;
    }

    float acc[4][4][4];
#pragma unroll
    for (int mt = 0; mt < 4; mt++)
#pragma unroll
        for (int nt = 0; nt < 4; nt++)
#pragma unroll
            for (int v = 0; v < 4; v++) acc[mt][nt][v] = 0.0f;

#pragma unroll
    for (int s = 0; s < 2; s++) {
        uint32_t so = s * STAGE;
        cp_async16(a_rel + so, a_basep + s * 32);
        int ro = brow1(s) * HID;
#pragma unroll
        for (int j = 0; j < 2; j++) cp_async16(b_rel[j] + so, b_base[j] + ro);
        asm volatile("cp.async.commit_group;");
    }

#pragma unroll 1
    for (int kc = 0; kc < NITER1; kc++) {
        asm volatile("cp.async.wait_group 1;");
        __syncthreads();
        int pf = kc + 2;
        if (pf < NITER1) {
            uint32_t so = (pf % 3) * STAGE;
            cp_async16(a_rel + so, a_basep + pf * 32);
            int ro = brow1(pf) * HID;
#pragma unroll
            for (int j = 0; j < 2; j++) cp_async16(b_rel[j] + so, b_base[j] + ro);
        }
        asm volatile("cp.async.commit_group;");

        const uint32_t so = (kc % 3) * STAGE;
#pragma unroll
        for (int ks = 0; ks < 2; ks++) {
            uint32_t af[4][4], bf[4][2];
#pragma unroll
            for (int mt = 0; mt < 4; mt++)
                ldsm_x4(af[mt][0], af[mt][1], af[mt][2], af[mt][3],
                        a_addr[mt][ks] + so);
#pragma unroll
            for (int np = 0; np < 2; np++)
                ldsm_x4_t(bf[2 * np][0], bf[2 * np][1], bf[2 * np + 1][0],
                          bf[2 * np + 1][1], b_addr[np][ks] + so);
#pragma unroll
            for (int mt = 0; mt < 4; mt++)
#pragma unroll
                for (int nt = 0; nt < 4; nt++)
                    mma_f16(acc[mt][nt], af[mt], bf[nt]);
        }
    }

    const int tq = lid >> 2;
    const int tr = lid & 3;
#pragma unroll
    for (int mt = 0; mt < 4; mt++) {
#pragma unroll
        for (int half = 0; half < 2; half++) {
            int p = m0 + wm * 64 + mt * 16 + tq + half * 8;
            if (p >= NP) continue;
            __half* row = g_grid1b + ((size_t)node * NP + p) * HID;
#pragma unroll
            for (int nt = 0; nt < 4; nt++) {
                int col = wn * 32 + nt * 8 + tr * 2;
                *(uint32_t*)&row[col] = pkh2(silu_f(acc[mt][nt][half * 2 + 0]),
                                             silu_f(acc[mt][nt][half * 2 + 1]));
            }
        }
    }
}

// -------- grid2 = silu(grid1 @ g2): fp16 MMA, 4-stage, 512 thr --------------
__global__ void __launch_bounds__(512, 1) k_grid2_mma() {
    extern __shared__ __align__(128) char smem[];
    const uint32_t sbase = smem_u32(smem);
    const int tid = threadIdx.x;
    const int wid = tid >> 5;           // 0..15
    const int lid = tid & 31;
    const int wm  = wid & 1;            // M half
    const int wn  = wid >> 1;           // 0..7, 32 cols each
    const size_t m0 = (size_t)blockIdx.x * BM;

    const uint32_t STAGE = BM * 64 + BN * 64;    // 24576
    const uint32_t BOFF  = BM * 64;

    uint32_t a_addr[4][2], b_addr[2][2];
#pragma unroll
    for (int mt = 0; mt < 4; mt++)
#pragma unroll
        for (int ks = 0; ks < 2; ks++) {
            int row = wm * 64 + mt * 16 + (lid & 7) + ((lid >> 3) & 1) * 8;
            int ch  = ks * 2 + (lid >> 4);
            a_addr[mt][ks] = sbase + row * 64 + 16 * (ch ^ ((row >> 1) & 3));
        }
#pragma unroll
    for (int np = 0; np < 2; np++)
#pragma unroll
        for (int ks = 0; ks < 2; ks++) {
            int row = wn * 32 + np * 16 + (lid & 7) + (lid >> 4) * 8;
            int ch  = ks * 2 + ((lid >> 3) & 1);
            b_addr[np][ks] = sbase + BOFF + row * 64 + 16 * (ch ^ ((row >> 1) & 3));
        }

    uint32_t a_rel, b_rel[2];
    const __half* a_basep;
    const __half* b_base[2];
    {
        int r = tid >> 2, c = tid & 3;          // 512 loads cover 128x4
        a_rel = sbase + r * 64 + 16 * (c ^ ((r >> 1) & 3));
        a_basep = g_grid1b + (m0 + r) * (size_t)HID + c * 8;
    }
#pragma unroll
    for (int j = 0; j < 2; j++) {
        int id = tid + j * 512, r = id >> 2, c = id & 3;
        b_rel[j] = sbase + BOFF + r * 64 + 16 * (c ^ ((r >> 1) & 3));
        b_base[j] = g_g2b + r * (size_t)512 + c * 8;
    }

    float acc[4][4][4];
#pragma unroll
    for (int mt = 0; mt < 4; mt++)
#pragma unroll
        for (int nt = 0; nt < 4; nt++)
#pragma unroll
            for (int v = 0; v < 4; v++) acc[mt][nt][v] = 0.0f;

#pragma unroll
    for (int s = 0; s < 3; s++) {
        uint32_t so = s * STAGE;
        cp_async16(a_rel + so, a_basep + aoff2(s));
#pragma unroll
        for (int j = 0; j < 2; j++) cp_async16(b_rel[j] + so, b_base[j] + s * 32);
        asm volatile("cp.async.commit_group;");
    }

#pragma unroll 1
    for (int kc = 0; kc < NITER2; kc++) {
        asm volatile("cp.async.wait_group 2;");
        __syncthreads();
        int pf = kc + 3;
        if (pf < NITER2) {
            uint32_t so = (pf & 3) * STAGE;
            cp_async16(a_rel + so, a_basep + aoff2(pf));
#pragma unroll
            for (int j = 0; j < 2; j++) cp_async16(b_rel[j] + so, b_base[j] + pf * 32);
        }
        asm volatile("cp.async.commit_group;");

        const uint32_t so = (kc & 3) * STAGE;
#pragma unroll
        for (int ks = 0; ks < 2; ks++) {
            uint32_t af[4][4], bf[4][2];
#pragma unroll
            for (int mt = 0; mt < 4; mt++)
                ldsm_x4(af[mt][0], af[mt][1], af[mt][2], af[mt][3],
                        a_addr[mt][ks] + so);
#pragma unroll
            for (int np = 0; np < 2; np++)
                ldsm_x4(bf[2 * np][0], bf[2 * np][1], bf[2 * np + 1][0],
                        bf[2 * np + 1][1], b_addr[np][ks] + so);
#pragma unroll
            for (int mt = 0; mt < 4; mt++)
#pragma unroll
                for (int nt = 0; nt < 4; nt++)
                    mma_f16(acc[mt][nt], af[mt], bf[nt]);
        }
    }

    const int tq = lid >> 2;
    const int tr = lid & 3;
#pragma unroll
    for (int mt = 0; mt < 4; mt++) {
#pragma unroll
        for (int half = 0; half < 2; half++) {
            size_t r = m0 + wm * 64 + mt * 16 + tq + half * 8;
            uint32_t n = (uint32_t)(r / NP);
            uint32_t p = (uint32_t)(r - (size_t)n * NP);
            __half* row = g_grid2b + ((size_t)n * PBLK + p) * HID;
#pragma unroll
            for (int nt = 0; nt < 4; nt++) {
                int col = wn * 32 + nt * 8 + tr * 2;
                *(uint32_t*)&row[col] = pkh2(silu_f(acc[mt][nt][half * 2 + 0]),
                                             silu_f(acc[mt][nt][half * 2 + 1]));
            }
        }
    }
}

// -------- z = F^T @ grid2[n] : fp16 MMA, trans-B, 4-stage, 512 thr ----------
__global__ void __launch_bounds__(512, 1) k_z_mma() {
    extern __shared__ __align__(128) char smem[];
    const uint32_t sbase = smem_u32(smem);
    const int tid = threadIdx.x;
    const int wid = tid >> 5;           // 0..15, 16 cols each
    const int lid = tid & 31;
    const int node = blockIdx.x;

    const uint32_t STAGE = 64 * 64 + BK * 512;   // 20480
    const uint32_t BOFF  = 64 * 64;

    uint32_t a_addr[4][2], b_addr[2];
#pragma unroll
    for (int mt = 0; mt < 4; mt++)
#pragma unroll
        for (int ks = 0; ks < 2; ks++) {
            int row = mt * 16 + (lid & 7) + ((lid >> 3) & 1) * 8;
            int ch  = ks * 2 + (lid >> 4);
            a_addr[mt][ks] = sbase + row * 64 + 16 * (ch ^ ((row >> 1) & 3));
        }
#pragma unroll
    for (int ks = 0; ks < 2; ks++) {
        int row = ks * 16 + (lid & 7) + 8 * ((lid >> 3) & 1);
        int cn  = wid * 2 + (lid >> 4);
        b_addr[ks] = sbase + BOFF + row * 512 + 16 * (cn ^ (row & 7));
    }

    uint32_t a_rel = 0, b_rel[2];
    const __half* a_basep = nullptr;
    const __half* b_base[2];
    const __half* g2bn = g_grid2b + (size_t)node * (PBLK * HID);
    if (tid < 256) {                     // A tile 64x4 chunks = 256 loads
        int r = tid >> 2, c = tid & 3;
        a_rel = sbase + r * 64 + 16 * (c ^ ((r >> 1) & 3));
        a_basep = g_FTb + r * 704 + c * 8;
    }
#pragma unroll
    for (int j = 0; j < 2; j++) {
        int id = tid + j * 512, r = id >> 5, c = id & 31;
        b_rel[j] = sbase + BOFF + r * 512 + 16 * (c ^ (r & 7));
        b_base[j] = g2bn + r * HID + c * 8;
    }

    float acc[4][2][4];
#pragma unroll
    for (int mt = 0; mt < 4; mt++)
#pragma unroll
        for (int nt = 0; nt < 2; nt++)
#pragma unroll
            for (int v = 0; v < 4; v++) acc[mt][nt][v] = 0.0f;

#pragma unroll
    for (int s = 0; s < 3; s++) {
        uint32_t so = s * STAGE;
        if (tid < 256) cp_async16(a_rel + so, a_basep + s * 32);
        int ro = browz(s) * HID;
#pragma unroll
        for (int j = 0; j < 2; j++) cp_async16(b_rel[j] + so, b_base[j] + ro);
        asm volatile("cp.async.commit_group;");
    }

#pragma unroll 1
    for (int kc = 0; kc < NITERZ; kc++) {
        asm volatile("cp.async.wait_group 2;");
        __syncthreads();
        int pf = kc + 3;
        if (pf < NITERZ) {
            uint32_t so = (pf & 3) * STAGE;
            if (tid < 256) cp_async16(a_rel + so, a_basep + pf * 32);
            int ro = browz(pf) * HID;
#pragma unroll
            for (int j = 0; j < 2; j++) cp_async16(b_rel[j] + so, b_base[j] + ro);
        }
        asm volatile("cp.async.commit_group;");

        const uint32_t so = (kc & 3) * STAGE;
#pragma unroll
        for (int ks = 0; ks < 2; ks++) {
            uint32_t af[4][4], bf[2][2];
#pragma unroll
            for (int mt = 0; mt < 4; mt++)
                ldsm_x4(af[mt][0], af[mt][1], af[mt][2], af[mt][3],
                        a_addr[mt][ks] + so);
            ldsm_x4_t(bf[0][0], bf[0][1], bf[1][0], bf[1][1], b_addr[ks] + so);
#pragma unroll
            for (int mt = 0; mt < 4; mt++)
#pragma unroll
                for (int nt = 0; nt < 2; nt++)
                    mma_f16(acc[mt][nt], af[mt], bf[nt]);
        }
    }

    // Epilogue: fp16 store z[n][i][h], i < 49.
    const int tq = lid >> 2;
    const int tr = lid & 3;
#pragma unroll
    for (int mt = 0; mt < 4; mt++) {
#pragma unroll
        for (int half = 0; half < 2; half++) {
            int i = mt * 16 + tq + half * 8;
            if (i >= NC) continue;
            __half* row = g_zh + ((size_t)node * NC + i) * HID;
#pragma unroll
            for (int nt = 0; nt < 2; nt++) {
                int col = wid * 16 + nt * 8 + tr * 2;
                *(uint32_t*)&row[col] = pkh2(acc[mt][nt][half * 2 + 0],
                                             acc[mt][nt][half * 2 + 1]);
            }
        }
    }
}

// ---------------- out[:,i,:] = z[:,i,:] @ G3W2[l]: fp16 MMA (i>=1) ----------
__global__ void __launch_bounds__(256, 1) k_out_mma(float* __restrict__ out) {
    extern __shared__ __align__(128) char smem[];
    const uint32_t sbase = smem_u32(smem);
    const int tid = threadIdx.x;
    const int wid = tid >> 5;
    const int lid = tid & 31;
    const int wm  = wid & 1;
    const int wn  = wid >> 1;   // 0..3, 32 cols each
    const int i   = blockIdx.y + 1;
    const int l   = deg_of(i);
    const int m0  = blockIdx.x * BM;

    const uint32_t STAGE = BM * 64 + CIN * 64;   // 16384
    const uint32_t BOFF  = BM * 64;

    uint32_t a_addr[4][2], b_addr[2][2];
#pragma unroll
    for (int mt = 0; mt < 4; mt++)
#pragma unroll
        for (int ks = 0; ks < 2; ks++) {
            int row = wm * 64 + mt * 16 + (lid & 7) + ((lid >> 3) & 1) * 8;
            int ch  = ks * 2 + (lid >> 4);
            a_addr[mt][ks] = sbase + row * 64 + 16 * (ch ^ ((row >> 1) & 3));
        }
#pragma unroll
    for (int np = 0; np < 2; np++)
#pragma unroll
        for (int ks = 0; ks < 2; ks++) {
            int row = wn * 32 + np * 16 + (lid & 7) + (lid >> 4) * 8;
            int ch  = ks * 2 + ((lid >> 3) & 1);
            b_addr[np][ks] = sbase + BOFF + row * 64 + 16 * (ch ^ ((row >> 1) & 3));
        }

    uint32_t a_rel[2], b_rel[2];
    const __half* a_base[2];
    const __half* b_base[2];
#pragma unroll
    for (int j = 0; j < 2; j++) {
        int id = tid + j * 256, r = id >> 2, c = id & 3;
        a_rel[j] = sbase + r * 64 + 16 * (c ^ ((r >> 1) & 3));
        a_base[j] = g_zh + ((size_t)(m0 + r) * NC + i) * HID + c * 8;
        b_rel[j] = sbase + BOFF + r * 64 + 16 * (c ^ ((r >> 1) & 3));
        b_base[j] = g_g3w2h + ((size_t)l * CIN + r) * 512 + c * 8;
    }

    float acc[4][4][4];
#pragma unroll
    for (int mt = 0; mt < 4; mt++)
#pragma unroll
        for (int nt = 0; nt < 4; nt++)
#pragma unroll
            for (int v = 0; v < 4; v++) acc[mt][nt][v] = 0.0f;

#pragma unroll
    for (int s = 0; s < 3; s++) {
        uint32_t so = s * STAGE;
#pragma unroll
        for (int j = 0; j < 2; j++) {
            cp_async16(a_rel[j] + so, a_base[j] + aoffo(s));
            cp_async16(b_rel[j] + so, b_base[j] + s * 32);
        }
        asm volatile("cp.async.commit_group;");
    }

#pragma unroll 1
    for (int kc = 0; kc < NITERO; kc++) {
        asm volatile("cp.async.wait_group 2;");
        __syncthreads();
        int pf = kc + 3;
        if (pf < NITERO) {
            uint32_t so = (pf & 3) * STAGE;
#pragma unroll
            for (int j = 0; j < 2; j++) {
                cp_async16(a_rel[j] + so, a_base[j] + aoffo(pf));
                cp_async16(b_rel[j] + so, b_base[j] + pf * 32);
            }
        }
        asm volatile("cp.async.commit_group;");

        const uint32_t so = (kc & 3) * STAGE;
#pragma unroll
        for (int ks = 0; ks < 2; ks++) {
            uint32_t af[4][4], bf[4][2];
#pragma unroll
            for (int mt = 0; mt < 4; mt++)
                ldsm_x4(af[mt][0], af[mt][1], af[mt][2], af[mt][3],
                        a_addr[mt][ks] + so);
#pragma unroll
            for (int np = 0; np < 2; np++)
                ldsm_x4(bf[2 * np][0], bf[2 * np][1], bf[2 * np + 1][0],
                        bf[2 * np + 1][1], b_addr[np][ks] + so);
#pragma unroll
            for (int mt = 0; mt < 4; mt++)
#pragma unroll
                for (int nt = 0; nt < 4; nt++)
                    mma_f16(acc[mt][nt], af[mt], bf[nt]);
        }
    }

    const int tq = lid >> 2;
    const int tr = lid & 3;
#pragma unroll
    for (int mt = 0; mt < 4; mt++) {
#pragma unroll
        for (int half = 0; half < 2; half++) {
            int node = m0 + wm * 64 + mt * 16 + tq + half * 8;
            float* row = out + ((size_t)node * NC + i) * CIN;
#pragma unroll
            for (int nt = 0; nt < 4; nt++) {
                int col = wn * 32 + nt * 8 + tr * 2;
                float2 v;
                v.x = acc[mt][nt][half * 2 + 0];
                v.y = acc[mt][nt][half * 2 + 1];
                *(float2*)&row[col] = v;
            }
        }
    }
}

// out[:,0,:] = gate @ w2[0] + b2  (SIMT, tiny)
__global__ void __launch_bounds__(256) k_out0(const float* __restrict__ w2,
                                              const float* __restrict__ b2,
                                              float* __restrict__ out) {
    gemm_tile<false, true>(g_gate, HID, w2, CIN, b2,
                           out, NC * CIN, N_NODES, CIN, HID);
}

// ---------------------------------------------------------------------------

extern "C" void kernel_launch(void* const* d_in, const int* in_sizes, int n_in,
                              void* d_out, int out_size) {
    const float* nf = (const float*)d_in[0];
    const float* w1 = (const float*)d_in[1];
    const float* b1 = (const float*)d_in[2];
    const float* w2 = (const float*)d_in[3];
    const float* b2 = (const float*)d_in[4];
    const float* ws = (const float*)d_in[5];
    const float* bs = (const float*)d_in[6];
    const float* g1 = (const float*)d_in[7];
    const float* g2 = (const float*)d_in[8];
    const float* g3 = (const float*)d_in[9];
    const float* Tg = (const float*)d_in[10];
    const float* Fg = (const float*)d_in[11];
    float* out = (float*)d_out;

    const int SMEM1 = 3 * (BM * 64 + BK * 512);   // 73728
    const int SMEM2 = 4 * (BM * 64 + BN * 64);    // 98304
    const int SMEMZ = 4 * (64 * 64 + BK * 512);   // 81920
    const int SMEMY = 4 * (BM * 64 + BN * 64);    // 98304
    const int SMEMO = 4 * (BM * 64 + CIN * 64);   // 65536
    cudaFuncSetAttribute(k_grid1_mma, cudaFuncAttributeMaxDynamicSharedMemorySize, SMEM1);
    cudaFuncSetAttribute(k_grid2_mma, cudaFuncAttributeMaxDynamicSharedMemorySize, SMEM2);
    cudaFuncSetAttribute(k_z_mma,     cudaFuncAttributeMaxDynamicSharedMemorySize, SMEMZ);
    cudaFuncSetAttribute(k_y_mma,     cudaFuncAttributeMaxDynamicSharedMemorySize, SMEMY);
    cudaFuncSetAttribute(k_out_mma,   cudaFuncAttributeMaxDynamicSharedMemorySize, SMEMO);

    // prologs
    k_w1g1<<<dim3(HID / 64, CIN / 64, NL), 256>>>(w1, g1);
    k_g3w2<<<dim3(CIN / 64, HID / 64, NL), 256>>>(g3, w2);
    k_b1g1<<<1, HID>>>(b1, g1);
    k_prepT<<<384, 128>>>(Tg);
    k_prepFT<<<dim3(64, 2), PBLK>>>(Fg);
    k_prepg2<<<HID, HID>>>(g2);
    k_prep_w1g1h<<<dim3(NL, HID), CIN>>>();
    k_prep_g3w2h<<<dim3(NL, CIN), HID>>>();
    k_prep_nfh<<<(int)((size_t)N_NODES * NC * CIN / 512), 256>>>(nf);
    k_pad_yb<<<dim3(15, N_NODES), 128>>>();
    k_pad_g2b<<<dim3(28, N_NODES), 128>>>();

    // scalar gating branch
    k_gate<<<dim3(HID / 64, N_NODES / 64), 256>>>(nf, ws, bs);

    // main pipeline (all MMA)
    k_y_mma<<<dim3(N_NODES / BM, NC), 256, SMEMY>>>();
    k_grid1_mma<<<dim3(3, N_NODES), 512, SMEM1>>>();
    k_grid2_mma<<<(int)(MROWS / BM), 512, SMEM2>>>();
    k_z_mma<<<N_NODES, 512, SMEMZ>>>();
    k_out_mma<<<dim3(N_NODES / BM, NC - 1), 256, SMEMO>>>(out);
    k_out0<<<dim3(CIN / 64, N_NODES / 64), 256>>>(w2, b2, out);
}

// round 9
// speedup vs baseline: 5.0100x; 1.2794x over previous
#include <cuda_runtime.h>
#include <cuda_fp16.h>
#include <cstdint>

// ---------------------------------------------------------------------------
// FeedForwardNetwork (SO(3) equivariant FFN), sm_103a — all-MMA plain-fp16
// Round 9: weight lo-planes dropped (empirically ~1e-4 each in quadrature);
// every GEMM runs at native K. 68 GF total MMA work.
//
//   nfh    = fp16(node_feats)
//   y      = nfh @ fp16(W1G1[l])     (MMA K=128, per-coeff i) -> fp16 planes
//   grid1  = silu(fp16(T) @ y)       (MMA K=64, per node)     -> fp16
//   grid2  = silu(grid1 @ fp16(g2))  (MMA K=256)              -> fp16
//   z      = fp16(F^T) @ grid2       (MMA K=352, per node)    -> fp16
//   out[:,i>=1,:] = z[:,i,:] @ fp16(g3 @ w2[l(i)])  (MMA K=256) -> fp32
//   out[:,0,:]    = silu(nf[:,0,:] @ ws + bs) @ w2[0] + b2      (SIMT, tiny)
// ---------------------------------------------------------------------------

#define N_NODES 1024
#define NC      49
#define CIN     128
#define HID     256
#define RES     18
#define NP      (RES*RES)   // 324
#define NL      7
#define MROWS   ((size_t)N_NODES * NP)   // 331776
#define PBLK    352
#define BM      128
#define BN      256
#define BK      32
#define NITER1  2            // grid1 K chunks (64/32)
#define NITER2  8            // grid2 K chunks (256/32)
#define NITERZ  11           // z K chunks (352/32)
#define NITERY  4            // y K chunks (128/32)
#define NITERO  8            // out K chunks (256/32)

// -------- scratch (static device globals; no runtime allocation) -----------
__device__ float g_W1G1[NL * CIN * HID];
__device__ float g_G3W2[NL * HID * CIN];
__device__ float g_b1g1[HID];
__device__ __half g_Tb[384 * 64];                    // to_grid hi [384x64]
__device__ __half g_FTb[64 * PBLK];                  // from_grid^T hi [64x352]
__device__ __half g_g2b[HID * 256];                  // g2^T hi [256x256]
__device__ __half g_w1g1h[NL * HID * 128];           // W1G1^T hi rows
__device__ __half g_g3w2h[NL * CIN * 256];           // (g3 w2)^T hi rows
__device__ __half g_nfh[(size_t)N_NODES * NC * CIN];       // 12.8 MB
__device__ __half g_yb[(size_t)N_NODES * 64 * HID];        // 34 MB
__device__ __half g_grid1b[MROWS * HID];                   // 170 MB
__device__ __half g_grid2b[(size_t)N_NODES * PBLK * HID];  // 185 MB
__device__ __half g_zh[(size_t)N_NODES * NC * HID];        // 25.7 MB
__device__ float g_gate[(size_t)N_NODES * HID];

__device__ __forceinline__ float silu_f(float x) {
    return x / (1.0f + __expf(-x));
}
__device__ __forceinline__ int deg_of(int i) {
    int l = 0;
    while ((l + 1) * (l + 1) <= i) ++l;
    return l;
}
__device__ __forceinline__ uint32_t smem_u32(const void* p) {
    uint32_t a;
    asm("{ .reg .u64 t; cvta.to.shared.u64 t, %1; cvt.u32.u64 %0, t; }"
        : "=r"(a) : "l"(p));
    return a;
}
__device__ __forceinline__ void cp_async16(uint32_t dst, const void* src) {
    asm volatile("cp.async.cg.shared.global [%0], [%1], 16;" :: "r"(dst), "l"(src));
}
__device__ __forceinline__ void ldsm_x4(uint32_t& r0, uint32_t& r1,
                                        uint32_t& r2, uint32_t& r3, uint32_t addr) {
    asm volatile("ldmatrix.sync.aligned.m8n8.x4.shared.b16 {%0,%1,%2,%3}, [%4];"
                 : "=r"(r0), "=r"(r1), "=r"(r2), "=r"(r3) : "r"(addr));
}
__device__ __forceinline__ void ldsm_x4_t(uint32_t& r0, uint32_t& r1,
                                          uint32_t& r2, uint32_t& r3, uint32_t addr) {
    asm volatile("ldmatrix.sync.aligned.m8n8.x4.trans.shared.b16 {%0,%1,%2,%3}, [%4];"
                 : "=r"(r0), "=r"(r1), "=r"(r2), "=r"(r3) : "r"(addr));
}
__device__ __forceinline__ void mma_f16(float* d, const uint32_t* a, const uint32_t* b) {
    asm volatile(
        "mma.sync.aligned.m16n8k16.row.col.f32.f16.f16.f32 "
        "{%0,%1,%2,%3}, {%4,%5,%6,%7}, {%8,%9}, {%0,%1,%2,%3};"
        : "+f"(d[0]), "+f"(d[1]), "+f"(d[2]), "+f"(d[3])
        : "r"(a[0]), "r"(a[1]), "r"(a[2]), "r"(a[3]), "r"(b[0]), "r"(b[1]));
}
__device__ __forceinline__ uint32_t pkh2(float x, float y) {
    __half hx = __float2half_rn(x), hy = __float2half_rn(y);
    uint16_t bx = *(uint16_t*)&hx, by = *(uint16_t*)&hy;
    return (uint32_t)bx | ((uint32_t)by << 16);
}

// ---------------------------------------------------------------------------
// Generic 64x64x16 SIMT tiled GEMM (small stages only).
// ---------------------------------------------------------------------------
template<bool DO_SILU, bool HAS_BIAS>
__device__ __forceinline__ void gemm_tile(
    const float* __restrict__ A, int lda,
    const float* __restrict__ B, int ldb,
    const float* __restrict__ bias,
    float* __restrict__ C, int ldc,
    int M, int N, int K)
{
    __shared__ float As[16][64];
    __shared__ float Bs[16][64];

    const int tid = threadIdx.x;
    const int tx  = tid & 15;
    const int ty  = tid >> 4;
    const int m0  = blockIdx.y * 64;
    const int n0  = blockIdx.x * 64;

    float acc[4][4];
#pragma unroll
    for (int i = 0; i < 4; i++)
#pragma unroll
        for (int j = 0; j < 4; j++) acc[i][j] = 0.0f;

    for (int k0 = 0; k0 < K; k0 += 16) {
#pragma unroll
        for (int e = tid; e < 64 * 16; e += 256) {
            int m = e >> 4, k = e & 15;
            int gm = m0 + m, gk = k0 + k;
            As[k][m] = (gm < M && gk < K) ? A[(size_t)gm * lda + gk] : 0.0f;
        }
#pragma unroll
        for (int e = tid; e < 16 * 64; e += 256) {
            int k = e >> 6, n = e & 63;
            int gk = k0 + k, gn = n0 + n;
            Bs[k][n] = (gk < K && gn < N) ? B[(size_t)gk * ldb + gn] : 0.0f;
        }
        __syncthreads();

#pragma unroll
        for (int k = 0; k < 16; k++) {
            float4 av = *(const float4*)&As[k][ty * 4];
            float4 bv = *(const float4*)&Bs[k][tx * 4];
            float a4[4] = {av.x, av.y, av.z, av.w};
            float b4[4] = {bv.x, bv.y, bv.z, bv.w};
#pragma unroll
            for (int i = 0; i < 4; i++)
#pragma unroll
                for (int j = 0; j < 4; j++)
                    acc[i][j] += a4[i] * b4[j];
        }
        __syncthreads();
    }

#pragma unroll
    for (int i = 0; i < 4; i++) {
        int gm = m0 + ty * 4 + i;
        if (gm >= M) continue;
#pragma unroll
        for (int j = 0; j < 4; j++) {
            int gn = n0 + tx * 4 + j;
            if (gn >= N) continue;
            float v = acc[i][j];
            if (HAS_BIAS) v += bias[gn];
            if (DO_SILU)  v = silu_f(v);
            C[(size_t)gm * ldc + gn] = v;
        }
    }
}

// ---------------------------- prolog kernels --------------------------------

__global__ void __launch_bounds__(256) k_w1g1(const float* __restrict__ w1,
                                              const float* __restrict__ g1) {
    int l = blockIdx.z;
    gemm_tile<false, false>(w1 + (size_t)l * CIN * HID, HID, g1, HID, nullptr,
                            g_W1G1 + (size_t)l * CIN * HID, HID, CIN, HID, HID);
}

__global__ void __launch_bounds__(256) k_g3w2(const float* __restrict__ g3,
                                              const float* __restrict__ w2) {
    int l = blockIdx.z;
    gemm_tile<false, false>(g3, HID, w2 + (size_t)l * HID * CIN, CIN, nullptr,
                            g_G3W2 + (size_t)l * HID * CIN, CIN, HID, CIN, HID);
}

__global__ void k_b1g1(const float* __restrict__ b1, const float* __restrict__ g1) {
    int k = threadIdx.x;
    float s = 0.0f;
    for (int h = 0; h < HID; h++) s += b1[h] * g1[(size_t)h * HID + k];
    g_b1g1[k] = s;
}

// g_Tb [384 x 64]: hi(T[p][i]); pads 0.
__global__ void k_prepT(const float* __restrict__ T) {
    int p = blockIdx.x;          // 0..383
    int i = threadIdx.x;         // 0..63
    float v = (p < NP && i < NC) ? T[p * NC + i] : 0.0f;
    g_Tb[p * 64 + i] = __float2half_rn(v);
}

// g_FTb [64 x 352]: hi(F[p][i]); pads 0.
__global__ void k_prepFT(const float* __restrict__ F) {
    int i = blockIdx.x;          // 0..63
    int p = threadIdx.x;         // 0..351
    float v = (i < NC && p < NP) ? F[p * NC + i] : 0.0f;
    g_FTb[i * PBLK + p] = __float2half_rn(v);
}

// g_g2b [256 x 256] rows n: hi(g2[k][n])
__global__ void k_prepg2(const float* __restrict__ g2) {
    int k = blockIdx.x;
    int n = threadIdx.x;
    g_g2b[(size_t)n * 256 + k] = __float2half_rn(g2[(size_t)k * HID + n]);
}

// g_w1g1h [l][n(256)][128]: hi(W1G1[l][k][n])
__global__ void k_prep_w1g1h() {
    int l = blockIdx.x, n = blockIdx.y, k = threadIdx.x;
    g_w1g1h[((size_t)l * HID + n) * 128 + k] =
        __float2half_rn(g_W1G1[((size_t)l * CIN + k) * HID + n]);
}

// g_g3w2h [l][n(128)][256]: hi(G3W2[l][k][n])
__global__ void k_prep_g3w2h() {
    int l = blockIdx.x, n = blockIdx.y, k = threadIdx.x;
    g_g3w2h[((size_t)l * CIN + n) * 256 + k] =
        __float2half_rn(g_G3W2[((size_t)l * HID + k) * CIN + n]);
}

// nf -> fp16
__global__ void k_prep_nfh(const float* __restrict__ nf) {
    size_t idx = ((size_t)blockIdx.x * blockDim.x + threadIdx.x) * 2;
    float2 v = *(const float2*)(nf + idx);
    *(uint32_t*)&g_nfh[idx] = pkh2(v.x, v.y);
}

// zero y pad rows (rows [49,64))
__global__ void k_pad_yb() {
    int q = blockIdx.x;
    int node = blockIdx.y;
    int row = NC + q;
    *(uint32_t*)&g_yb[(size_t)node * (64 * HID) + (size_t)row * HID + threadIdx.x * 2] = 0;
}

// zero grid2b pad rows (rows [324,352))
__global__ void k_pad_g2b() {
    int q = blockIdx.x;
    int node = blockIdx.y;
    int row = NP + q;
    *(uint32_t*)&g_grid2b[(size_t)node * (PBLK * HID) + (size_t)row * HID + threadIdx.x * 2] = 0;
}

// ---------------------------- main stage kernels ----------------------------

__global__ void __launch_bounds__(256) k_gate(const float* __restrict__ nf,
                                              const float* __restrict__ ws,
                                              const float* __restrict__ bs) {
    gemm_tile<true, true>(nf, NC * CIN, ws, HID, bs, g_gate, HID,
                          N_NODES, HID, CIN);
}

// ---------------- y = nfh @ W1G1[l] : fp16 MMA, K=128, 256 thr --------------
__global__ void __launch_bounds__(256, 1) k_y_mma() {
    extern __shared__ __align__(128) char smem[];
    const uint32_t sbase = smem_u32(smem);
    const int tid = threadIdx.x;
    const int wid = tid >> 5;
    const int lid = tid & 31;
    const int wm  = wid & 1;
    const int wn  = wid >> 1;
    const int i   = blockIdx.y;
    const int l   = deg_of(i);
    const int m0  = blockIdx.x * BM;

    const uint32_t STAGE = BM * 64 + BN * 64;    // 24576
    const uint32_t BOFF  = BM * 64;

    uint32_t a_addr[4][2], b_addr[4][2];
#pragma unroll
    for (int mt = 0; mt < 4; mt++)
#pragma unroll
        for (int ks = 0; ks < 2; ks++) {
            int row = wm * 64 + mt * 16 + (lid & 7) + ((lid >> 3) & 1) * 8;
            int ch  = ks * 2 + (lid >> 4);
            a_addr[mt][ks] = sbase + row * 64 + 16 * (ch ^ ((row >> 1) & 3));
        }
#pragma unroll
    for (int np = 0; np < 4; np++)
#pragma unroll
        for (int ks = 0; ks < 2; ks++) {
            int row = wn * 64 + np * 16 + (lid & 7) + (lid >> 4) * 8;
            int ch  = ks * 2 + ((lid >> 3) & 1);
            b_addr[np][ks] = sbase + BOFF + row * 64 + 16 * (ch ^ ((row >> 1) & 3));
        }

    uint32_t a_rel[2], b_rel[4];
    const __half* a_base[2];
    const __half* b_base[4];
#pragma unroll
    for (int j = 0; j < 2; j++) {
        int id = tid + j * 256, r = id >> 2, c = id & 3;
        a_rel[j] = sbase + r * 64 + 16 * (c ^ ((r >> 1) & 3));
        a_base[j] = g_nfh + ((size_t)(m0 + r) * NC + i) * CIN + c * 8;
    }
#pragma unroll
    for (int j = 0; j < 4; j++) {
        int id = tid + j * 256, r = id >> 2, c = id & 3;
        b_rel[j] = sbase + BOFF + r * 64 + 16 * (c ^ ((r >> 1) & 3));
        b_base[j] = g_w1g1h + ((size_t)l * HID + r) * 128 + c * 8;
    }

    float acc[4][8][4];
#pragma unroll
    for (int mt = 0; mt < 4; mt++)
#pragma unroll
        for (int nt = 0; nt < 8; nt++)
#pragma unroll
            for (int v = 0; v < 4; v++) acc[mt][nt][v] = 0.0f;

#pragma unroll
    for (int s = 0; s < 3; s++) {
        uint32_t so = s * STAGE;
        if (s < NITERY) {
#pragma unroll
            for (int j = 0; j < 2; j++) cp_async16(a_rel[j] + so, a_base[j] + s * 32);
#pragma unroll
            for (int j = 0; j < 4; j++) cp_async16(b_rel[j] + so, b_base[j] + s * 32);
        }
        asm volatile("cp.async.commit_group;");
    }

#pragma unroll 1
    for (int kc = 0; kc < NITERY; kc++) {
        asm volatile("cp.async.wait_group 2;");
        __syncthreads();
        int pf = kc + 3;
        if (pf < NITERY) {
            uint32_t so = (pf & 3) * STAGE;
#pragma unroll
            for (int j = 0; j < 2; j++) cp_async16(a_rel[j] + so, a_base[j] + pf * 32);
#pragma unroll
            for (int j = 0; j < 4; j++) cp_async16(b_rel[j] + so, b_base[j] + pf * 32);
        }
        asm volatile("cp.async.commit_group;");

        const uint32_t so = (kc & 3) * STAGE;
#pragma unroll
        for (int ks = 0; ks < 2; ks++) {
            uint32_t af[4][4], bf[8][2];
#pragma unroll
            for (int mt = 0; mt < 4; mt++)
                ldsm_x4(af[mt][0], af[mt][1], af[mt][2], af[mt][3],
                        a_addr[mt][ks] + so);
#pragma unroll
            for (int np = 0; np < 4; np++)
                ldsm_x4(bf[2 * np][0], bf[2 * np][1], bf[2 * np + 1][0],
                        bf[2 * np + 1][1], b_addr[np][ks] + so);
#pragma unroll
            for (int mt = 0; mt < 4; mt++)
#pragma unroll
                for (int nt = 0; nt < 8; nt++)
                    mma_f16(acc[mt][nt], af[mt], bf[nt]);
        }
    }

    const int tq = lid >> 2;
    const int tr = lid & 3;
#pragma unroll
    for (int mt = 0; mt < 4; mt++) {
#pragma unroll
        for (int half = 0; half < 2; half++) {
            int node = m0 + wm * 64 + mt * 16 + tq + half * 8;
            __half* row = g_yb + ((size_t)node * 64 + i) * HID;
#pragma unroll
            for (int nt = 0; nt < 8; nt++) {
                int col = wn * 64 + nt * 8 + tr * 2;
                float v0 = acc[mt][nt][half * 2 + 0];
                float v1 = acc[mt][nt][half * 2 + 1];
                if (i == 0) { v0 += g_b1g1[col]; v1 += g_b1g1[col + 1]; }
                *(uint32_t*)&row[col] = pkh2(v0, v1);
            }
        }
    }
}

// -------- grid1 = silu(T @ y[n]) : fp16 MMA, K=64, trans-B, 512 thr ---------
__global__ void __launch_bounds__(512, 1) k_grid1_mma() {
    extern __shared__ __align__(128) char smem[];
    const uint32_t sbase = smem_u32(smem);
    const int tid = threadIdx.x;
    const int wid = tid >> 5;           // 0..15
    const int lid = tid & 31;
    const int wm  = wid & 1;
    const int wn  = wid >> 1;           // 0..7, 32 cols each
    const int node = blockIdx.y;
    const int m0 = blockIdx.x * BM;

    const uint32_t STAGE = BM * 64 + BK * 512;   // 24576
    const uint32_t BOFF  = BM * 64;

    uint32_t a_addr[4][2], b_addr[2][2];
#pragma unroll
    for (int mt = 0; mt < 4; mt++)
#pragma unroll
        for (int ks = 0; ks < 2; ks++) {
            int row = wm * 64 + mt * 16 + (lid & 7) + ((lid >> 3) & 1) * 8;
            int ch  = ks * 2 + (lid >> 4);
            a_addr[mt][ks] = sbase + row * 64 + 16 * (ch ^ ((row >> 1) & 3));
        }
#pragma unroll
    for (int np = 0; np < 2; np++)
#pragma unroll
        for (int ks = 0; ks < 2; ks++) {
            int row = ks * 16 + (lid & 7) + 8 * ((lid >> 3) & 1);
            int cn  = wn * 4 + np * 2 + (lid >> 4);
            b_addr[np][ks] = sbase + BOFF + row * 512 + 16 * (cn ^ (row & 7));
        }

    uint32_t a_rel, b_rel[2];
    const __half* a_basep;
    const __half* b_base[2];
    const __half* ybn = g_yb + (size_t)node * (64 * HID);
    {
        int r = tid >> 2, c = tid & 3;
        a_rel = sbase + r * 64 + 16 * (c ^ ((r >> 1) & 3));
        a_basep = g_Tb + (m0 + r) * 64 + c * 8;
    }
#pragma unroll
    for (int j = 0; j < 2; j++) {
        int id = tid + j * 512, r = id >> 5, c = id & 31;
        b_rel[j] = sbase + BOFF + r * 512 + 16 * (c ^ (r & 7));
        b_base[j] = ybn + r * HID + c * 8;
    }

    float acc[4][4][4];
#pragma unroll
    for (int mt = 0; mt < 4; mt++)
#pragma unroll
        for (int nt = 0; nt < 4; nt++)
#pragma unroll
            for (int v = 0; v < 4; v++) acc[mt][nt][v] = 0.0f;

#pragma unroll
    for (int s = 0; s < 2; s++) {
        uint32_t so = s * STAGE;
        cp_async16(a_rel + so, a_basep + s * 32);
#pragma unroll
        for (int j = 0; j < 2; j++) cp_async16(b_rel[j] + so, b_base[j] + s * 32 * HID);
        asm volatile("cp.async.commit_group;");
    }

#pragma unroll 1
    for (int kc = 0; kc < NITER1; kc++) {
        asm volatile("cp.async.wait_group 1;");
        __syncthreads();
        asm volatile("cp.async.commit_group;");

        const uint32_t so = (kc % 3) * STAGE;
#pragma unroll
        for (int ks = 0; ks < 2; ks++) {
            uint32_t af[4][4], bf[4][2];
#pragma unroll
            for (int mt = 0; mt < 4; mt++)
                ldsm_x4(af[mt][0], af[mt][1], af[mt][2], af[mt][3],
                        a_addr[mt][ks] + so);
#pragma unroll
            for (int np = 0; np < 2; np++)
                ldsm_x4_t(bf[2 * np][0], bf[2 * np][1], bf[2 * np + 1][0],
                          bf[2 * np + 1][1], b_addr[np][ks] + so);
#pragma unroll
            for (int mt = 0; mt < 4; mt++)
#pragma unroll
                for (int nt = 0; nt < 4; nt++)
                    mma_f16(acc[mt][nt], af[mt], bf[nt]);
        }
    }

    const int tq = lid >> 2;
    const int tr = lid & 3;
#pragma unroll
    for (int mt = 0; mt < 4; mt++) {
#pragma unroll
        for (int half = 0; half < 2; half++) {
            int p = m0 + wm * 64 + mt * 16 + tq + half * 8;
            if (p >= NP) continue;
            __half* row = g_grid1b + ((size_t)node * NP + p) * HID;
#pragma unroll
            for (int nt = 0; nt < 4; nt++) {
                int col = wn * 32 + nt * 8 + tr * 2;
                *(uint32_t*)&row[col] = pkh2(silu_f(acc[mt][nt][half * 2 + 0]),
                                             silu_f(acc[mt][nt][half * 2 + 1]));
            }
        }
    }
}

// -------- grid2 = silu(grid1 @ g2): fp16 MMA, K=256, 512 thr ----------------
__global__ void __launch_bounds__(512, 1) k_grid2_mma() {
    extern __shared__ __align__(128) char smem[];
    const uint32_t sbase = smem_u32(smem);
    const int tid = threadIdx.x;
    const int wid = tid >> 5;
    const int lid = tid & 31;
    const int wm  = wid & 1;
    const int wn  = wid >> 1;
    const size_t m0 = (size_t)blockIdx.x * BM;

    const uint32_t STAGE = BM * 64 + BN * 64;    // 24576
    const uint32_t BOFF  = BM * 64;

    uint32_t a_addr[4][2], b_addr[2][2];
#pragma unroll
    for (int mt = 0; mt < 4; mt++)
#pragma unroll
        for (int ks = 0; ks < 2; ks++) {
            int row = wm * 64 + mt * 16 + (lid & 7) + ((lid >> 3) & 1) * 8;
            int ch  = ks * 2 + (lid >> 4);
            a_addr[mt][ks] = sbase + row * 64 + 16 * (ch ^ ((row >> 1) & 3));
        }
#pragma unroll
    for (int np = 0; np < 2; np++)
#pragma unroll
        for (int ks = 0; ks < 2; ks++) {
            int row = wn * 32 + np * 16 + (lid & 7) + (lid >> 4) * 8;
            int ch  = ks * 2 + ((lid >> 3) & 1);
            b_addr[np][ks] = sbase + BOFF + row * 64 + 16 * (ch ^ ((row >> 1) & 3));
        }

    uint32_t a_rel, b_rel[2];
    const __half* a_basep;
    const __half* b_base[2];
    {
        int r = tid >> 2, c = tid & 3;
        a_rel = sbase + r * 64 + 16 * (c ^ ((r >> 1) & 3));
        a_basep = g_grid1b + (m0 + r) * (size_t)HID + c * 8;
    }
#pragma unroll
    for (int j = 0; j < 2; j++) {
        int id = tid + j * 512, r = id >> 2, c = id & 3;
        b_rel[j] = sbase + BOFF + r * 64 + 16 * (c ^ ((r >> 1) & 3));
        b_base[j] = g_g2b + r * (size_t)256 + c * 8;
    }

    float acc[4][4][4];
#pragma unroll
    for (int mt = 0; mt < 4; mt++)
#pragma unroll
        for (int nt = 0; nt < 4; nt++)
#pragma unroll
            for (int v = 0; v < 4; v++) acc[mt][nt][v] = 0.0f;

#pragma unroll
    for (int s = 0; s < 3; s++) {
        uint32_t so = s * STAGE;
        cp_async16(a_rel + so, a_basep + s * 32);
#pragma unroll
        for (int j = 0; j < 2; j++) cp_async16(b_rel[j] + so, b_base[j] + s * 32);
        asm volatile("cp.async.commit_group;");
    }

#pragma unroll 1
    for (int kc = 0; kc < NITER2; kc++) {
        asm volatile("cp.async.wait_group 2;");
        __syncthreads();
        int pf = kc + 3;
        if (pf < NITER2) {
            uint32_t so = (pf & 3) * STAGE;
            cp_async16(a_rel + so, a_basep + pf * 32);
#pragma unroll
            for (int j = 0; j < 2; j++) cp_async16(b_rel[j] + so, b_base[j] + pf * 32);
        }
        asm volatile("cp.async.commit_group;");

        const uint32_t so = (kc & 3) * STAGE;
#pragma unroll
        for (int ks = 0; ks < 2; ks++) {
            uint32_t af[4][4], bf[4][2];
#pragma unroll
            for (int mt = 0; mt < 4; mt++)
                ldsm_x4(af[mt][0], af[mt][1], af[mt][2], af[mt][3],
                        a_addr[mt][ks] + so);
#pragma unroll
            for (int np = 0; np < 2; np++)
                ldsm_x4(bf[2 * np][0], bf[2 * np][1], bf[2 * np + 1][0],
                        bf[2 * np + 1][1], b_addr[np][ks] + so);
#pragma unroll
            for (int mt = 0; mt < 4; mt++)
#pragma unroll
                for (int nt = 0; nt < 4; nt++)
                    mma_f16(acc[mt][nt], af[mt], bf[nt]);
        }
    }

    const int tq = lid >> 2;
    const int tr = lid & 3;
#pragma unroll
    for (int mt = 0; mt < 4; mt++) {
#pragma unroll
        for (int half = 0; half < 2; half++) {
            size_t r = m0 + wm * 64 + mt * 16 + tq + half * 8;
            uint32_t n = (uint32_t)(r / NP);
            uint32_t p = (uint32_t)(r - (size_t)n * NP);
            __half* row = g_grid2b + ((size_t)n * PBLK + p) * HID;
#pragma unroll
            for (int nt = 0; nt < 4; nt++) {
                int col = wn * 32 + nt * 8 + tr * 2;
                *(uint32_t*)&row[col] = pkh2(silu_f(acc[mt][nt][half * 2 + 0]),
                                             silu_f(acc[mt][nt][half * 2 + 1]));
            }
        }
    }
}

// -------- z = F^T @ grid2[n] : fp16 MMA, K=352, trans-B, 512 thr ------------
__global__ void __launch_bounds__(512, 1) k_z_mma() {
    extern __shared__ __align__(128) char smem[];
    const uint32_t sbase = smem_u32(smem);
    const int tid = threadIdx.x;
    const int wid = tid >> 5;           // 0..15, 16 cols each
    const int lid = tid & 31;
    const int node = blockIdx.x;

    const uint32_t STAGE = 64 * 64 + BK * 512;   // 20480
    const uint32_t BOFF  = 64 * 64;

    uint32_t a_addr[4][2], b_addr[2];
#pragma unroll
    for (int mt = 0; mt < 4; mt++)
#pragma unroll
        for (int ks = 0; ks < 2; ks++) {
            int row = mt * 16 + (lid & 7) + ((lid >> 3) & 1) * 8;
            int ch  = ks * 2 + (lid >> 4);
            a_addr[mt][ks] = sbase + row * 64 + 16 * (ch ^ ((row >> 1) & 3));
        }
#pragma unroll
    for (int ks = 0; ks < 2; ks++) {
        int row = ks * 16 + (lid & 7) + 8 * ((lid >> 3) & 1);
        int cn  = wid * 2 + (lid >> 4);
        b_addr[ks] = sbase + BOFF + row * 512 + 16 * (cn ^ (row & 7));
    }

    uint32_t a_rel = 0, b_rel[2];
    const __half* a_basep = nullptr;
    const __half* b_base[2];
    const __half* g2bn = g_grid2b + (size_t)node * (PBLK * HID);
    if (tid < 256) {
        int r = tid >> 2, c = tid & 3;
        a_rel = sbase + r * 64 + 16 * (c ^ ((r >> 1) & 3));
        a_basep = g_FTb + r * PBLK + c * 8;
    }
#pragma unroll
    for (int j = 0; j < 2; j++) {
        int id = tid + j * 512, r = id >> 5, c = id & 31;
        b_rel[j] = sbase + BOFF + r * 512 + 16 * (c ^ (r & 7));
        b_base[j] = g2bn + r * HID + c * 8;
    }

    float acc[4][2][4];
#pragma unroll
    for (int mt = 0; mt < 4; mt++)
#pragma unroll
        for (int nt = 0; nt < 2; nt++)
#pragma unroll
            for (int v = 0; v < 4; v++) acc[mt][nt][v] = 0.0f;

#pragma unroll
    for (int s = 0; s < 3; s++) {
        uint32_t so = s * STAGE;
        if (tid < 256) cp_async16(a_rel + so, a_basep + s * 32);
#pragma unroll
        for (int j = 0; j < 2; j++) cp_async16(b_rel[j] + so, b_base[j] + s * 32 * HID);
        asm volatile("cp.async.commit_group;");
    }

#pragma unroll 1
    for (int kc = 0; kc < NITERZ; kc++) {
        asm volatile("cp.async.wait_group 2;");
        __syncthreads();
        int pf = kc + 3;
        if (pf < NITERZ) {
            uint32_t so = (pf & 3) * STAGE;
            if (tid < 256) cp_async16(a_rel + so, a_basep + pf * 32);
#pragma unroll
            for (int j = 0; j < 2; j++) cp_async16(b_rel[j] + so, b_base[j] + pf * 32 * HID);
        }
        asm volatile("cp.async.commit_group;");

        const uint32_t so = (kc & 3) * STAGE;
#pragma unroll
        for (int ks = 0; ks < 2; ks++) {
            uint32_t af[4][4], bf[2][2];
#pragma unroll
            for (int mt = 0; mt < 4; mt++)
                ldsm_x4(af[mt][0], af[mt][1], af[mt][2], af[mt][3],
                        a_addr[mt][ks] + so);
            ldsm_x4_t(bf[0][0], bf[0][1], bf[1][0], bf[1][1], b_addr[ks] + so);
#pragma unroll
            for (int mt = 0; mt < 4; mt++)
#pragma unroll
                for (int nt = 0; nt < 2; nt++)
                    mma_f16(acc[mt][nt], af[mt], bf[nt]);
        }
    }

    // Epilogue: fp16 store z[n][i][h], i < 49.
    const int tq = lid >> 2;
    const int tr = lid & 3;
#pragma unroll
    for (int mt = 0; mt < 4; mt++) {
#pragma unroll
        for (int half = 0; half < 2; half++) {
            int i = mt * 16 + tq + half * 8;
            if (i >= NC) continue;
            __half* row = g_zh + ((size_t)node * NC + i) * HID;
#pragma unroll
            for (int nt = 0; nt < 2; nt++) {
                int col = wid * 16 + nt * 8 + tr * 2;
                *(uint32_t*)&row[col] = pkh2(acc[mt][nt][half * 2 + 0],
                                             acc[mt][nt][half * 2 + 1]);
            }
        }
    }
}

// ---------------- out[:,i,:] = z[:,i,:] @ G3W2[l]: fp16 MMA (i>=1) ----------
__global__ void __launch_bounds__(256, 1) k_out_mma(float* __restrict__ out) {
    extern __shared__ __align__(128) char smem[];
    const uint32_t sbase = smem_u32(smem);
    const int tid = threadIdx.x;
    const int wid = tid >> 5;
    const int lid = tid & 31;
    const int wm  = wid & 1;
    const int wn  = wid >> 1;   // 0..3, 32 cols each
    const int i   = blockIdx.y + 1;
    const int l   = deg_of(i);
    const int m0  = blockIdx.x * BM;

    const uint32_t STAGE = BM * 64 + CIN * 64;   // 16384
    const uint32_t BOFF  = BM * 64;

    uint32_t a_addr[4][2], b_addr[2][2];
#pragma unroll
    for (int mt = 0; mt < 4; mt++)
#pragma unroll
        for (int ks = 0; ks < 2; ks++) {
            int row = wm * 64 + mt * 16 + (lid & 7) + ((lid >> 3) & 1) * 8;
            int ch  = ks * 2 + (lid >> 4);
            a_addr[mt][ks] = sbase + row * 64 + 16 * (ch ^ ((row >> 1) & 3));
        }
#pragma unroll
    for (int np = 0; np < 2; np++)
#pragma unroll
        for (int ks = 0; ks < 2; ks++) {
            int row = wn * 32 + np * 16 + (lid & 7) + (lid >> 4) * 8;
            int ch  = ks * 2 + ((lid >> 3) & 1);
            b_addr[np][ks] = sbase + BOFF + row * 64 + 16 * (ch ^ ((row >> 1) & 3));
        }

    uint32_t a_rel[2], b_rel[2];
    const __half* a_base[2];
    const __half* b_base[2];
#pragma unroll
    for (int j = 0; j < 2; j++) {
        int id = tid + j * 256, r = id >> 2, c = id & 3;
        a_rel[j] = sbase + r * 64 + 16 * (c ^ ((r >> 1) & 3));
        a_base[j] = g_zh + ((size_t)(m0 + r) * NC + i) * HID + c * 8;
        b_rel[j] = sbase + BOFF + r * 64 + 16 * (c ^ ((r >> 1) & 3));
        b_base[j] = g_g3w2h + ((size_t)l * CIN + r) * 256 + c * 8;
    }

    float acc[4][4][4];
#pragma unroll
    for (int mt = 0; mt < 4; mt++)
#pragma unroll
        for (int nt = 0; nt < 4; nt++)
#pragma unroll
            for (int v = 0; v < 4; v++) acc[mt][nt][v] = 0.0f;

#pragma unroll
    for (int s = 0; s < 3; s++) {
        uint32_t so = s * STAGE;
#pragma unroll
        for (int j = 0; j < 2; j++) {
            cp_async16(a_rel[j] + so, a_base[j] + s * 32);
            cp_async16(b_rel[j] + so, b_base[j] + s * 32);
        }
        asm volatile("cp.async.commit_group;");
    }

#pragma unroll 1
    for (int kc = 0; kc < NITERO; kc++) {
        asm volatile("cp.async.wait_group 2;");
        __syncthreads();
        int pf = kc + 3;
        if (pf < NITERO) {
            uint32_t so = (pf & 3) * STAGE;
#pragma unroll
            for (int j = 0; j < 2; j++) {
                cp_async16(a_rel[j] + so, a_base[j] + pf * 32);
                cp_async16(b_rel[j] + so, b_base[j] + pf * 32);
            }
        }
        asm volatile("cp.async.commit_group;");

        const uint32_t so = (kc & 3) * STAGE;
#pragma unroll
        for (int ks = 0; ks < 2; ks++) {
            uint32_t af[4][4], bf[4][2];
#pragma unroll
            for (int mt = 0; mt < 4; mt++)
                ldsm_x4(af[mt][0], af[mt][1], af[mt][2], af[mt][3],
                        a_addr[mt][ks] + so);
#pragma unroll
            for (int np = 0; np < 2; np++)
                ldsm_x4(bf[2 * np][0], bf[2 * np][1], bf[2 * np + 1][0],
                        bf[2 * np + 1][1], b_addr[np][ks] + so);
#pragma unroll
            for (int mt = 0; mt < 4; mt++)
#pragma unroll
                for (int nt = 0; nt < 4; nt++)
                    mma_f16(acc[mt][nt], af[mt], bf[nt]);
        }
    }

    const int tq = lid >> 2;
    const int tr = lid & 3;
#pragma unroll
    for (int mt = 0; mt < 4; mt++) {
#pragma unroll
        for (int half = 0; half < 2; half++) {
            int node = m0 + wm * 64 + mt * 16 + tq + half * 8;
            float* row = out + ((size_t)node * NC + i) * CIN;
#pragma unroll
            for (int nt = 0; nt < 4; nt++) {
                int col = wn * 32 + nt * 8 + tr * 2;
                float2 v;
                v.x = acc[mt][nt][half * 2 + 0];
                v.y = acc[mt][nt][half * 2 + 1];
                *(float2*)&row[col] = v;
            }
        }
    }
}

// out[:,0,:] = gate @ w2[0] + b2  (SIMT, tiny)
__global__ void __launch_bounds__(256) k_out0(const float* __restrict__ w2,
                                              const float* __restrict__ b2,
                                              float* __restrict__ out) {
    gemm_tile<false, true>(g_gate, HID, w2, CIN, b2,
                           out, NC * CIN, N_NODES, CIN, HID);
}

// ---------------------------------------------------------------------------

extern "C" void kernel_launch(void* const* d_in, const int* in_sizes, int n_in,
                              void* d_out, int out_size) {
    const float* nf = (const float*)d_in[0];
    const float* w1 = (const float*)d_in[1];
    const float* b1 = (const float*)d_in[2];
    const float* w2 = (const float*)d_in[3];
    const float* b2 = (const float*)d_in[4];
    const float* ws = (const float*)d_in[5];
    const float* bs = (const float*)d_in[6];
    const float* g1 = (const float*)d_in[7];
    const float* g2 = (const float*)d_in[8];
    const float* g3 = (const float*)d_in[9];
    const float* Tg = (const float*)d_in[10];
    const float* Fg = (const float*)d_in[11];
    float* out = (float*)d_out;

    const int SMEM1 = 3 * (BM * 64 + BK * 512);   // 73728
    const int SMEM2 = 4 * (BM * 64 + BN * 64);    // 98304
    const int SMEMZ = 4 * (64 * 64 + BK * 512);   // 81920
    const int SMEMY = 4 * (BM * 64 + BN * 64);    // 98304
    const int SMEMO = 4 * (BM * 64 + CIN * 64);   // 65536
    cudaFuncSetAttribute(k_grid1_mma, cudaFuncAttributeMaxDynamicSharedMemorySize, SMEM1);
    cudaFuncSetAttribute(k_grid2_mma, cudaFuncAttributeMaxDynamicSharedMemorySize, SMEM2);
    cudaFuncSetAttribute(k_z_mma,     cudaFuncAttributeMaxDynamicSharedMemorySize, SMEMZ);
    cudaFuncSetAttribute(k_y_mma,     cudaFuncAttributeMaxDynamicSharedMemorySize, SMEMY);
    cudaFuncSetAttribute(k_out_mma,   cudaFuncAttributeMaxDynamicSharedMemorySize, SMEMO);

    // prologs
    k_w1g1<<<dim3(HID / 64, CIN / 64, NL), 256>>>(w1, g1);
    k_g3w2<<<dim3(CIN / 64, HID / 64, NL), 256>>>(g3, w2);
    k_b1g1<<<1, HID>>>(b1, g1);
    k_prepT<<<384, 64>>>(Tg);
    k_prepFT<<<64, PBLK>>>(Fg);
    k_prepg2<<<256, 256>>>(g2);
    k_prep_w1g1h<<<dim3(NL, HID), CIN>>>();
    k_prep_g3w2h<<<dim3(NL, CIN), HID>>>();
    k_prep_nfh<<<(int)((size_t)N_NODES * NC * CIN / 512), 256>>>(nf);
    k_pad_yb<<<dim3(15, N_NODES), 128>>>();
    k_pad_g2b<<<dim3(28, N_NODES), 128>>>();

    // scalar gating branch
    k_gate<<<dim3(HID / 64, N_NODES / 64), 256>>>(nf, ws, bs);

    // main pipeline (all MMA)
    k_y_mma<<<dim3(N_NODES / BM, NC), 256, SMEMY>>>();
    k_grid1_mma<<<dim3(3, N_NODES), 512, SMEM1>>>();
    k_grid2_mma<<<(int)(MROWS / BM), 512, SMEM2>>>();
    k_z_mma<<<N_NODES, 512, SMEMZ>>>();
    k_out_mma<<<dim3(N_NODES / BM, NC - 1), 256, SMEMO>>>(out);
    k_out0<<<dim3(CIN / 64, N_NODES / 64), 256>>>(w2, b2, out);
}